// round 2
// baseline (speedup 1.0000x reference)
#include <cuda_runtime.h>
#include <math.h>

#define BATCH 4
#define CDIM 128
#define INNER 512
#define NQ 4096
#define NK 512
#define NHEADS 8
#define DHEAD 64

// ---------------- scratch (static device globals; allocation-free) ----------
__device__ float g_qdw[BATCH * CDIM * NQ];     // 8 MB   depthwise-q + BN
__device__ float g_kvdw[BATCH * CDIM * NK];    // 1 MB   depthwise-kv + BN
__device__ float g_q[BATCH * INNER * NQ];      // 32 MB  q after pointwise
__device__ float g_kv[BATCH * 2 * INNER * NK]; // 8 MB   kv after pointwise
__device__ float g_att[BATCH * INNER * NQ];    // 32 MB  attention output

// ---------------------------------------------------------------------------
// Kernel 1: both depthwise 3x3x3 convs (stride1 and stride2) + batchnorm,
// sharing one padded 18^3 input slab in shared memory.
// grid (C, B), 256 threads.
// ---------------------------------------------------------------------------
__global__ __launch_bounds__(256) void dw_bn_kernel(
    const float* __restrict__ x,
    const float* __restrict__ wq,
    const float* __restrict__ qg, const float* __restrict__ qb,
    const float* __restrict__ qm, const float* __restrict__ qv,
    const float* __restrict__ wkv,
    const float* __restrict__ kg, const float* __restrict__ kb,
    const float* __restrict__ km, const float* __restrict__ kvvar)
{
    __shared__ float s[18 * 18 * 18];
    __shared__ float swq[27], swkv[27];
    const int c = blockIdx.x, b = blockIdx.y;
    const int tid = threadIdx.x;

    const float* xp = x + ((size_t)(b * CDIM + c)) * NQ;
    for (int idx = tid; idx < 5832; idx += 256) {
        int z = idx / 324; int r = idx - z * 324;
        int y = r / 18;    int xx = r - y * 18;
        z -= 1; y -= 1; xx -= 1;
        float v = 0.f;
        if ((unsigned)z < 16u && (unsigned)y < 16u && (unsigned)xx < 16u)
            v = xp[(z * 16 + y) * 16 + xx];
        s[idx] = v;
    }
    if (tid < 27) { swq[tid] = wq[c * 27 + tid]; swkv[tid] = wkv[c * 27 + tid]; }

    const float qscale = qg[c] * rsqrtf(qv[c] + 1e-5f);
    const float qshift = qb[c] - qm[c] * qscale;
    const float kscale = kg[c] * rsqrtf(kvvar[c] + 1e-5f);
    const float kshift = kb[c] - km[c] * kscale;
    __syncthreads();

    // q path: 16^3 outputs, stride 1, pad 1
    float* qo = g_qdw + ((size_t)(b * CDIM + c)) * NQ;
    for (int o = tid; o < 4096; o += 256) {
        const int z = o >> 8, y = (o >> 4) & 15, xx = o & 15;
        float sum = 0.f;
        #pragma unroll
        for (int dz = 0; dz < 3; dz++)
            #pragma unroll
            for (int dy = 0; dy < 3; dy++)
                #pragma unroll
                for (int dx = 0; dx < 3; dx++)
                    sum += swq[dz * 9 + dy * 3 + dx] *
                           s[(z + dz) * 324 + (y + dy) * 18 + (xx + dx)];
        qo[o] = sum * qscale + qshift;
    }

    // kv path: 8^3 outputs, stride 2, pad 1
    float* ko = g_kvdw + ((size_t)(b * CDIM + c)) * NK;
    for (int o = tid; o < 512; o += 256) {
        const int z = o >> 6, y = (o >> 3) & 7, xx = o & 7;
        float sum = 0.f;
        #pragma unroll
        for (int dz = 0; dz < 3; dz++)
            #pragma unroll
            for (int dy = 0; dy < 3; dy++)
                #pragma unroll
                for (int dx = 0; dx < 3; dx++)
                    sum += swkv[dz * 9 + dy * 3 + dx] *
                           s[(2 * z + dz) * 324 + (2 * y + dy) * 18 + (2 * xx + dx)];
        ko[o] = sum * kscale + kshift;
    }
}

// ---------------------------------------------------------------------------
// Kernel 2: batched pointwise GEMM. C[b] = A (MxK) * B[b] (KxN) (+bias).
// 64x64 tile, BK=16, 256 threads, 4x4 micro-tiles, float4 everywhere.
// Requires M%64==0, N%64==0, K%16==0 (true for all three uses).
// ---------------------------------------------------------------------------
template <bool HAS_BIAS>
__global__ __launch_bounds__(256) void gemm_kernel(
    const float* __restrict__ A, const float* __restrict__ Bm,
    float* __restrict__ Cm, int M, int N, int K,
    const float* __restrict__ bias)
{
    __shared__ float AsT[16][68];
    __shared__ float Bs[16][68];

    const int bz = blockIdx.z;
    const float* Bp = Bm + (size_t)bz * K * N;
    float* Cp = Cm + (size_t)bz * M * N;
    const int n0 = blockIdx.x * 64, m0 = blockIdx.y * 64;
    const int tid = threadIdx.x, tx = tid & 15, ty = tid >> 4;

    const int am = tid >> 2, akq = tid & 3;   // A loader: 64 rows x 4 float4
    const int bk = tid >> 4, bf = tid & 15;   // B loader: 16 rows x 16 float4

    float acc[4][4] = {};
    for (int k0 = 0; k0 < K; k0 += 16) {
        __syncthreads();
        float4 av = *(const float4*)(A + (size_t)(m0 + am) * K + k0 + akq * 4);
        AsT[akq * 4 + 0][am] = av.x;
        AsT[akq * 4 + 1][am] = av.y;
        AsT[akq * 4 + 2][am] = av.z;
        AsT[akq * 4 + 3][am] = av.w;
        *(float4*)(&Bs[bk][bf * 4]) =
            *(const float4*)(Bp + (size_t)(k0 + bk) * N + n0 + bf * 4);
        __syncthreads();
        #pragma unroll
        for (int k = 0; k < 16; k++) {
            float4 a4 = *(const float4*)(&AsT[k][ty * 4]);
            float4 b4 = *(const float4*)(&Bs[k][tx * 4]);
            float a[4] = {a4.x, a4.y, a4.z, a4.w};
            float bb[4] = {b4.x, b4.y, b4.z, b4.w};
            #pragma unroll
            for (int i = 0; i < 4; i++)
                #pragma unroll
                for (int j = 0; j < 4; j++)
                    acc[i][j] += a[i] * bb[j];
        }
    }
    #pragma unroll
    for (int i = 0; i < 4; i++) {
        const int row = m0 + ty * 4 + i;
        float bb = HAS_BIAS ? bias[row] : 0.f;
        float4 v = make_float4(acc[i][0] + bb, acc[i][1] + bb,
                               acc[i][2] + bb, acc[i][3] + bb);
        *(float4*)(Cp + (size_t)row * N + n0 + tx * 4) = v;
    }
}

// ---------------------------------------------------------------------------
// Kernel 3: fused attention. One CTA = one (b, h, 64-row q tile).
// Full score tile (64 x 512) kept TRANSPOSED in smem as sSt[j][i]; two-pass
// softmax; PV GEMM reads both operands as conflict-free float4.
// Dynamic smem: sQ 64x68 | sK/sVt 64x68 | sSt 512x68 | linv 64  = 174336 B.
// ---------------------------------------------------------------------------
__global__ __launch_bounds__(256) void attn_kernel(
    const float* __restrict__ gq, const float* __restrict__ gkv,
    float* __restrict__ gout)
{
    extern __shared__ float sm[];
    float* sQ   = sm;                 // [64][68]  (reused as sO in epilogue)
    float* sK   = sQ + 64 * 68;       // [64][68]  (reused as sVt)
    float* sSt  = sK + 64 * 68;       // [512][68] scores transposed [j][i]
    float* sLin = sSt + 512 * 68;     // [64]

    const int i0 = blockIdx.x * 64;
    const int h  = blockIdx.y;
    const int b  = blockIdx.z;
    const int tid = threadIdx.x, tx = tid & 15, ty = tid >> 4;

    const float* qbase = gq  + ((size_t)b * INNER + h * DHEAD) * NQ + i0;
    const float* kbase = gkv + ((size_t)b * 2 * INNER + h * DHEAD) * NK;
    const float* vbase = kbase + (size_t)INNER * NK;

    // load Q tile [d][i], pre-scaled by 1/sqrt(64)
    {
        const int d = tid >> 2, p = tid & 3;
        #pragma unroll
        for (int s4 = 0; s4 < 4; s4++) {
            const int col = p * 16 + s4 * 4;
            float4 v = *(const float4*)(qbase + (size_t)d * NQ + col);
            v.x *= 0.125f; v.y *= 0.125f; v.z *= 0.125f; v.w *= 0.125f;
            *(float4*)(sQ + d * 68 + col) = v;
        }
    }

    // ---- GEMM1: S = (scaled Q)^T K, stored transposed into sSt[j][i] ----
    for (int jc = 0; jc < NK; jc += 64) {
        __syncthreads();
        {
            const int d = tid >> 2, p = tid & 3;
            #pragma unroll
            for (int s4 = 0; s4 < 4; s4++) {
                const int col = p * 16 + s4 * 4;
                *(float4*)(sK + d * 68 + col) =
                    *(const float4*)(kbase + (size_t)d * NK + jc + col);
            }
        }
        __syncthreads();
        float acc[4][4] = {};
        #pragma unroll 8
        for (int d = 0; d < 64; d++) {
            float4 a4 = *(const float4*)(sQ + d * 68 + ty * 4);
            float4 b4 = *(const float4*)(sK + d * 68 + tx * 4);
            float a[4] = {a4.x, a4.y, a4.z, a4.w};
            float bb[4] = {b4.x, b4.y, b4.z, b4.w};
            #pragma unroll
            for (int i = 0; i < 4; i++)
                #pragma unroll
                for (int j = 0; j < 4; j++)
                    acc[i][j] += a[i] * bb[j];
        }
        #pragma unroll
        for (int j = 0; j < 4; j++)
            #pragma unroll
            for (int i = 0; i < 4; i++)
                sSt[(jc + tx * 4 + j) * 68 + ty * 4 + i] = acc[i][j];
    }
    __syncthreads();

    // ---- softmax over j (4 threads per row i) ----
    {
        const int sl = tid & 3, ii = tid >> 2;
        float m = -1e30f;
        for (int j = sl; j < NK; j += 4)
            m = fmaxf(m, sSt[j * 68 + ii]);
        m = fmaxf(m, __shfl_xor_sync(0xffffffffu, m, 1));
        m = fmaxf(m, __shfl_xor_sync(0xffffffffu, m, 2));
        float l = 0.f;
        for (int j = sl; j < NK; j += 4) {
            float p = __expf(sSt[j * 68 + ii] - m);
            sSt[j * 68 + ii] = p;
            l += p;
        }
        l += __shfl_xor_sync(0xffffffffu, l, 1);
        l += __shfl_xor_sync(0xffffffffu, l, 2);
        if (sl == 0) sLin[ii] = 1.f / l;
    }
    __syncthreads();

    // ---- GEMM2: O = P * V^T, with V transposed into smem per chunk ----
    float acc2[4][4] = {};   // [i][d]
    float* sVt = sK;
    for (int jc = 0; jc < NK; jc += 64) {
        __syncthreads();
        {
            const int d = tid >> 2, p = tid & 3;
            #pragma unroll
            for (int s4 = 0; s4 < 4; s4++) {
                const int jj = p * 16 + s4 * 4;
                float4 v = *(const float4*)(vbase + (size_t)d * NK + jc + jj);
                sVt[(jj + 0) * 68 + d] = v.x;
                sVt[(jj + 1) * 68 + d] = v.y;
                sVt[(jj + 2) * 68 + d] = v.z;
                sVt[(jj + 3) * 68 + d] = v.w;
            }
        }
        __syncthreads();
        #pragma unroll 8
        for (int j = 0; j < 64; j++) {
            float4 a4 = *(const float4*)(sSt + (jc + j) * 68 + ty * 4);
            float4 b4 = *(const float4*)(sVt + j * 68 + tx * 4);
            float a[4] = {a4.x, a4.y, a4.z, a4.w};
            float bb[4] = {b4.x, b4.y, b4.z, b4.w};
            #pragma unroll
            for (int i = 0; i < 4; i++)
                #pragma unroll
                for (int d = 0; d < 4; d++)
                    acc2[i][d] += a[i] * bb[d];
        }
    }

    // ---- epilogue: scale by 1/l, stage through smem, coalesced store ----
    float linv[4];
    #pragma unroll
    for (int i = 0; i < 4; i++) linv[i] = sLin[ty * 4 + i];
    __syncthreads();
    float* sO = sQ;
    #pragma unroll
    for (int d = 0; d < 4; d++)
        #pragma unroll
        for (int i = 0; i < 4; i++)
            sO[(tx * 4 + d) * 68 + ty * 4 + i] = acc2[i][d] * linv[i];
    __syncthreads();
    {
        const int d = tid >> 2, p = tid & 3;
        float* obase = gout + ((size_t)b * INNER + h * DHEAD + d) * NQ + i0;
        #pragma unroll
        for (int s4 = 0; s4 < 4; s4++) {
            const int col = p * 16 + s4 * 4;
            *(float4*)(obase + col) = *(const float4*)(sO + d * 68 + col);
        }
    }
}

// ---------------------------------------------------------------------------
extern "C" void kernel_launch(void* const* d_in, const int* in_sizes, int n_in,
                              void* d_out, int out_size)
{
    const float* x      = (const float*)d_in[0];
    const float* wq_dw  = (const float*)d_in[1];
    const float* bn_q_g = (const float*)d_in[2];
    const float* bn_q_b = (const float*)d_in[3];
    const float* bn_q_m = (const float*)d_in[4];
    const float* bn_q_v = (const float*)d_in[5];
    const float* wq_pw  = (const float*)d_in[6];
    const float* wkv_dw = (const float*)d_in[7];
    const float* bn_k_g = (const float*)d_in[8];
    const float* bn_k_b = (const float*)d_in[9];
    const float* bn_k_m = (const float*)d_in[10];
    const float* bn_k_v = (const float*)d_in[11];
    const float* wkv_pw = (const float*)d_in[12];
    const float* w_out  = (const float*)d_in[13];
    const float* b_out  = (const float*)d_in[14];
    float* out = (float*)d_out;

    float *p_qdw, *p_kvdw, *p_q, *p_kv, *p_att;
    cudaGetSymbolAddress((void**)&p_qdw,  g_qdw);
    cudaGetSymbolAddress((void**)&p_kvdw, g_kvdw);
    cudaGetSymbolAddress((void**)&p_q,    g_q);
    cudaGetSymbolAddress((void**)&p_kv,   g_kv);
    cudaGetSymbolAddress((void**)&p_att,  g_att);

    const int ATT_SMEM = (64 * 68 + 64 * 68 + 512 * 68 + 64) * 4; // 174336
    cudaFuncSetAttribute(attn_kernel,
                         cudaFuncAttributeMaxDynamicSharedMemorySize, ATT_SMEM);

    // 1. depthwise convs + BN (fused)
    dw_bn_kernel<<<dim3(CDIM, BATCH), 256>>>(
        x, wq_dw, bn_q_g, bn_q_b, bn_q_m, bn_q_v,
        wkv_dw, bn_k_g, bn_k_b, bn_k_m, bn_k_v);

    // 2. pointwise q: (512 x 128) * (128 x 4096) per batch
    gemm_kernel<false><<<dim3(NQ / 64, INNER / 64, BATCH), 256>>>(
        wq_pw, p_qdw, p_q, INNER, NQ, CDIM, nullptr);

    // 3. pointwise kv: (1024 x 128) * (128 x 512) per batch
    gemm_kernel<false><<<dim3(NK / 64, (2 * INNER) / 64, BATCH), 256>>>(
        wkv_pw, p_kvdw, p_kv, 2 * INNER, NK, CDIM, nullptr);

    // 4. fused attention
    attn_kernel<<<dim3(NQ / 64, NHEADS, BATCH), 256, ATT_SMEM>>>(
        p_q, p_kv, p_att);

    // 5. output projection with bias: (128 x 512) * (512 x 4096) per batch
    gemm_kernel<true><<<dim3(NQ / 64, CDIM / 64, BATCH), 256>>>(
        w_out, p_att, out, CDIM, NQ, INNER, b_out);
}

// round 6
// speedup vs baseline: 1.7679x; 1.7679x over previous
#include <cuda_runtime.h>
#include <cuda_bf16.h>
#include <math.h>
#include <stdint.h>

#define BATCH 4
#define CDIM 128
#define INNER 512
#define NQ 4096
#define NK 512
#define NHEADS 8
#define DHEAD 64

// ---------------- scratch (static device globals; allocation-free) ----------
__device__ float g_qdw[BATCH * CDIM * NQ];     // 8 MB   depthwise-q + BN
__device__ float g_kvdw[BATCH * CDIM * NK];    // 1 MB   depthwise-kv + BN
__device__ float g_q[BATCH * INNER * NQ];      // 32 MB  q after pointwise
__device__ float g_kv[BATCH * 2 * INNER * NK]; // 8 MB   kv after pointwise
__device__ float g_att[BATCH * INNER * NQ];    // 32 MB  attention output

// ---------------------------------------------------------------------------
// Kernel 1: both depthwise 3x3x3 convs (stride1 and stride2) + batchnorm.
// ---------------------------------------------------------------------------
__global__ __launch_bounds__(256) void dw_bn_kernel(
    const float* __restrict__ x,
    const float* __restrict__ wq,
    const float* __restrict__ qg, const float* __restrict__ qb,
    const float* __restrict__ qm, const float* __restrict__ qv,
    const float* __restrict__ wkv,
    const float* __restrict__ kg, const float* __restrict__ kb,
    const float* __restrict__ km, const float* __restrict__ kvvar)
{
    __shared__ float s[18 * 18 * 18];
    __shared__ float swq[27], swkv[27];
    const int c = blockIdx.x, b = blockIdx.y;
    const int tid = threadIdx.x;

    const float* xp = x + ((size_t)(b * CDIM + c)) * NQ;
    for (int idx = tid; idx < 5832; idx += 256) {
        int z = idx / 324; int r = idx - z * 324;
        int y = r / 18;    int xx = r - y * 18;
        z -= 1; y -= 1; xx -= 1;
        float v = 0.f;
        if ((unsigned)z < 16u && (unsigned)y < 16u && (unsigned)xx < 16u)
            v = xp[(z * 16 + y) * 16 + xx];
        s[idx] = v;
    }
    if (tid < 27) { swq[tid] = wq[c * 27 + tid]; swkv[tid] = wkv[c * 27 + tid]; }

    const float qscale = qg[c] * rsqrtf(qv[c] + 1e-5f);
    const float qshift = qb[c] - qm[c] * qscale;
    const float kscale = kg[c] * rsqrtf(kvvar[c] + 1e-5f);
    const float kshift = kb[c] - km[c] * kscale;
    __syncthreads();

    float* qo = g_qdw + ((size_t)(b * CDIM + c)) * NQ;
    for (int o = tid; o < 4096; o += 256) {
        const int z = o >> 8, y = (o >> 4) & 15, xx = o & 15;
        float sum = 0.f;
        #pragma unroll
        for (int dz = 0; dz < 3; dz++)
            #pragma unroll
            for (int dy = 0; dy < 3; dy++)
                #pragma unroll
                for (int dx = 0; dx < 3; dx++)
                    sum += swq[dz * 9 + dy * 3 + dx] *
                           s[(z + dz) * 324 + (y + dy) * 18 + (xx + dx)];
        qo[o] = sum * qscale + qshift;
    }

    float* ko = g_kvdw + ((size_t)(b * CDIM + c)) * NK;
    for (int o = tid; o < 512; o += 256) {
        const int z = o >> 6, y = (o >> 3) & 7, xx = o & 7;
        float sum = 0.f;
        #pragma unroll
        for (int dz = 0; dz < 3; dz++)
            #pragma unroll
            for (int dy = 0; dy < 3; dy++)
                #pragma unroll
                for (int dx = 0; dx < 3; dx++)
                    sum += swkv[dz * 9 + dy * 3 + dx] *
                           s[(2 * z + dz) * 324 + (2 * y + dy) * 18 + (2 * xx + dx)];
        ko[o] = sum * kscale + kshift;
    }
}

// ---------------------------------------------------------------------------
// Kernel 2: batched pointwise GEMM (fp32).
// ---------------------------------------------------------------------------
template <bool HAS_BIAS>
__global__ __launch_bounds__(256) void gemm_kernel(
    const float* __restrict__ A, const float* __restrict__ Bm,
    float* __restrict__ Cm, int M, int N, int K,
    const float* __restrict__ bias)
{
    __shared__ float AsT[16][68];
    __shared__ float Bs[16][68];

    const int bz = blockIdx.z;
    const float* Bp = Bm + (size_t)bz * K * N;
    float* Cp = Cm + (size_t)bz * M * N;
    const int n0 = blockIdx.x * 64, m0 = blockIdx.y * 64;
    const int tid = threadIdx.x, tx = tid & 15, ty = tid >> 4;

    const int am = tid >> 2, akq = tid & 3;
    const int bk = tid >> 4, bf = tid & 15;

    float acc[4][4] = {};
    for (int k0 = 0; k0 < K; k0 += 16) {
        __syncthreads();
        float4 av = *(const float4*)(A + (size_t)(m0 + am) * K + k0 + akq * 4);
        AsT[akq * 4 + 0][am] = av.x;
        AsT[akq * 4 + 1][am] = av.y;
        AsT[akq * 4 + 2][am] = av.z;
        AsT[akq * 4 + 3][am] = av.w;
        *(float4*)(&Bs[bk][bf * 4]) =
            *(const float4*)(Bp + (size_t)(k0 + bk) * N + n0 + bf * 4);
        __syncthreads();
        #pragma unroll
        for (int k = 0; k < 16; k++) {
            float4 a4 = *(const float4*)(&AsT[k][ty * 4]);
            float4 b4 = *(const float4*)(&Bs[k][tx * 4]);
            float a[4] = {a4.x, a4.y, a4.z, a4.w};
            float bb[4] = {b4.x, b4.y, b4.z, b4.w};
            #pragma unroll
            for (int i = 0; i < 4; i++)
                #pragma unroll
                for (int j = 0; j < 4; j++)
                    acc[i][j] += a[i] * bb[j];
        }
    }
    #pragma unroll
    for (int i = 0; i < 4; i++) {
        const int row = m0 + ty * 4 + i;
        float bb = HAS_BIAS ? bias[row] : 0.f;
        float4 v = make_float4(acc[i][0] + bb, acc[i][1] + bb,
                               acc[i][2] + bb, acc[i][3] + bb);
        *(float4*)(Cp + (size_t)row * N + n0 + tx * 4) = v;
    }
}

// ===========================================================================
// tcgen05 helpers
// ===========================================================================
__device__ __forceinline__ uint32_t s2u(const void* p) {
    uint32_t a;
    asm("{ .reg .u64 t; cvta.to.shared.u64 t, %1; cvt.u32.u64 %0, t; }"
        : "=r"(a) : "l"(p));
    return a;
}
__device__ __forceinline__ uint32_t elect1() {
    uint32_t pred;
    asm volatile("{\n\t.reg .pred p;\n\telect.sync _|p, 0xFFFFFFFF;\n\t"
                 "selp.b32 %0, 1, 0, p;\n\t}" : "=r"(pred));
    return pred;
}
__device__ __forceinline__ void mbar_init(uint32_t mbar, uint32_t cnt) {
    asm volatile("mbarrier.init.shared.b64 [%0], %1;" :: "r"(mbar), "r"(cnt) : "memory");
}
__device__ __forceinline__ void mbar_inval(uint32_t mbar) {
    asm volatile("mbarrier.inval.shared.b64 [%0];" :: "r"(mbar) : "memory");
}
__device__ __forceinline__ void mbar_wait(uint32_t mbar, uint32_t parity) {
    asm volatile(
        "{\n\t.reg .pred P1;\n\t"
        "WL%=:\n\t"
        "mbarrier.try_wait.parity.acquire.cta.shared::cta.b64 P1, [%0], %1, 0x989680;\n\t"
        "@P1 bra.uni WD%=;\n\t"
        "bra.uni WL%=;\n\t"
        "WD%=:\n\t}"
        :: "r"(mbar), "r"(parity) : "memory");
}
__device__ __forceinline__ void tmem_alloc(uint32_t smem_dst, uint32_t ncols) {
    asm volatile("tcgen05.alloc.cta_group::1.sync.aligned.shared::cta.b32 [%0], %1;"
                 :: "r"(smem_dst), "r"(ncols) : "memory");
}
__device__ __forceinline__ void tmem_dealloc(uint32_t tmem, uint32_t ncols) {
    asm volatile("tcgen05.relinquish_alloc_permit.cta_group::1.sync.aligned;");
    asm volatile("tcgen05.dealloc.cta_group::1.sync.aligned.b32 %0, %1;"
                 :: "r"(tmem), "r"(ncols));
}
__device__ __forceinline__ void mma_f16_ss(uint32_t d, uint64_t a, uint64_t b,
                                           uint32_t idesc, uint32_t en) {
    asm volatile(
        "{\n\t.reg .pred p;\n\tsetp.ne.u32 p, %5, 0;\n\t"
        "tcgen05.mma.cta_group::1.kind::f16 [%0], %1, %2, %3, {%4, %4, %4, %4}, p;\n\t}"
        :: "r"(d), "l"(a), "l"(b), "r"(idesc), "r"(0u), "r"(en) : "memory");
}
__device__ __forceinline__ void tc_commit(uint32_t mbar) {
    asm volatile(
        "tcgen05.commit.cta_group::1.mbarrier::arrive::one.shared::cluster.b64 [%0];"
        :: "r"(mbar) : "memory");
}
#define TC_FENCE_AFTER()  asm volatile("tcgen05.fence::after_thread_sync;" ::: "memory")
#define TC_FENCE_BEFORE() asm volatile("tcgen05.fence::before_thread_sync;" ::: "memory")
#define TC_WAIT_LD()      asm volatile("tcgen05.wait::ld.sync.aligned;" ::: "memory")
#define FENCE_ASYNC()     asm volatile("fence.proxy.async.shared::cta;" ::: "memory")

#define TC_LD_X32(r, addr) \
    asm volatile( \
        "tcgen05.ld.sync.aligned.32x32b.x32.b32 " \
        "{%0, %1, %2, %3, %4, %5, %6, %7, " \
        " %8, %9, %10, %11, %12, %13, %14, %15, " \
        " %16, %17, %18, %19, %20, %21, %22, %23, " \
        " %24, %25, %26, %27, %28, %29, %30, %31}, [%32];" \
        : "=r"((r)[0]),  "=r"((r)[1]),  "=r"((r)[2]),  "=r"((r)[3]), \
          "=r"((r)[4]),  "=r"((r)[5]),  "=r"((r)[6]),  "=r"((r)[7]), \
          "=r"((r)[8]),  "=r"((r)[9]),  "=r"((r)[10]), "=r"((r)[11]), \
          "=r"((r)[12]), "=r"((r)[13]), "=r"((r)[14]), "=r"((r)[15]), \
          "=r"((r)[16]), "=r"((r)[17]), "=r"((r)[18]), "=r"((r)[19]), \
          "=r"((r)[20]), "=r"((r)[21]), "=r"((r)[22]), "=r"((r)[23]), \
          "=r"((r)[24]), "=r"((r)[25]), "=r"((r)[26]), "=r"((r)[27]), \
          "=r"((r)[28]), "=r"((r)[29]), "=r"((r)[30]), "=r"((r)[31]) \
        : "r"(addr))

// SW128 smem descriptor base (layout=2, version=1, SBO=64, LBO=1)
#define DESC_BASE ((2ULL << 61) | (1ULL << 46) | (64ULL << 32) | (1ULL << 16))
#define MK_DESC(a) (DESC_BASE | ((uint64_t)((a) >> 4) & 0x3FFFULL))

// smem regions (relative to 1024-aligned base)
//  MISC 2KB | A 64KB (K_hi / P_hi / sO) | B 64KB (K_lo / P_lo)
//  C 32KB (Q_hi+Q_lo / V_hi) | D 32KB (V_lo)
#define SM_MISC 0
#define SM_A    2048
#define SM_B    (SM_A + 65536)
#define SM_C    (SM_B + 65536)
#define SM_D    (SM_C + 32768)
#define SM_REQ  (SM_D + 32768 + 1024)

__device__ __forceinline__ uint32_t sw128(uint32_t o) { return o ^ ((o >> 3) & 0x70); }
__device__ __forceinline__ uint32_t qk_off(int r, int c) {   // rows x 64 bf16 (128B rows)
    return sw128((uint32_t)r * 128u + (uint32_t)c * 2u);
}
__device__ __forceinline__ uint32_t p_off(int i, int j) {    // 128 x 256, 16 atom-rows
    uint32_t o = ((uint32_t)(i >> 3) + (uint32_t)(j >> 6) * 16u) * 1024u +
                 (uint32_t)(i & 7) * 128u + (uint32_t)(j & 63) * 2u;
    return sw128(o);
}
__device__ __forceinline__ uint32_t v_off(int d, int j) {    // 64 x 256, 8 atom-rows
    uint32_t o = ((uint32_t)(d >> 3) + (uint32_t)(j >> 6) * 8u) * 1024u +
                 (uint32_t)(d & 7) * 128u + (uint32_t)(j & 63) * 2u;
    return sw128(o);
}

// idesc: dtype F32, atype/btype BF16, M=128 (8<<24), N via bits 17..22
#define IDESC_N(n) ((1u << 4) | (1u << 7) | (1u << 10) | (((n) / 8) << 17) | (8u << 24))

__device__ __forceinline__ void split_store(char* dst_hi, char* dst_lo,
                                            uint32_t off, float f) {
    __nv_bfloat16 hi = __float2bfloat16(f);
    __nv_bfloat16 lo = __float2bfloat16(f - __bfloat162float(hi));
    *(__nv_bfloat16*)(dst_hi + off) = hi;
    *(__nv_bfloat16*)(dst_lo + off) = lo;
}

// ===========================================================================
// Kernel 3a: tcgen05 bf16 fused attention with hi/lo error compensation.
// One CTA = (b, h, 128 q rows). grid (32, 8, 4), 256 threads.
// ===========================================================================
__global__ __launch_bounds__(256, 1)
void attn_tc_kernel(const float* __restrict__ gq,
                    const float* __restrict__ gkv,
                    float* __restrict__ gout)
{
#if defined(__CUDA_ARCH_FEAT_SM103_ALL)
    extern __shared__ char sm_raw[];
    char* base = (char*)(((uintptr_t)sm_raw + 1023) & ~(uintptr_t)1023);
    const uint32_t sb = s2u(base);

    const int tid = threadIdx.x, w = tid >> 5, lane = tid & 31;
    const int i0 = blockIdx.x * 128;
    const int h  = blockIdx.y;
    const int b  = blockIdx.z;

    const uint32_t misc = sb + SM_MISC;
    const uint32_t mbar = misc + 8;
    float* pa   = (float*)(base + SM_MISC + 16);
    float* pb   = (float*)(base + SM_MISC + 528);
    float* linv = (float*)(base + SM_MISC + 1040);

    if (w == 0) tmem_alloc(misc, 512);
    if (tid == 0) mbar_init(mbar, 1);
    __syncthreads();
    uint32_t tmem;
    asm volatile("ld.shared.b32 %0, [%1];" : "=r"(tmem) : "r"(misc));

    const float* qbase = gq  + ((size_t)b * INNER + h * DHEAD) * NQ + i0;
    const float* kbase = gkv + ((size_t)b * 2 * INNER + h * DHEAD) * NK;
    const float* vbase = kbase + (size_t)INNER * NK;

    // ---- load Q hi/lo (transpose [d][i]->[i][d], scale 1/8, SW128) ----
    for (int e = tid; e < 2048; e += 256) {
        const int d = e >> 5, i4 = (e & 31) * 4;
        float4 v = *(const float4*)(qbase + (size_t)d * NQ + i4);
        split_store(base + SM_C, base + SM_C + 16384, qk_off(i4 + 0, d), v.x * 0.125f);
        split_store(base + SM_C, base + SM_C + 16384, qk_off(i4 + 1, d), v.y * 0.125f);
        split_store(base + SM_C, base + SM_C + 16384, qk_off(i4 + 2, d), v.z * 0.125f);
        split_store(base + SM_C, base + SM_C + 16384, qk_off(i4 + 3, d), v.w * 0.125f);
    }
    // ---- load K hi/lo (transpose [d][j]->[j][d], SW128) ----
    for (int e = tid; e < 8192; e += 256) {
        const int d = e >> 7, j4 = (e & 127) * 4;
        float4 v = *(const float4*)(kbase + (size_t)d * NK + j4);
        split_store(base + SM_A, base + SM_B, qk_off(j4 + 0, d), v.x);
        split_store(base + SM_A, base + SM_B, qk_off(j4 + 1, d), v.y);
        split_store(base + SM_A, base + SM_B, qk_off(j4 + 2, d), v.z);
        split_store(base + SM_A, base + SM_B, qk_off(j4 + 3, d), v.w);
    }
    FENCE_ASYNC();
    __syncthreads();

    // ---- MMA1: dots = (Qh+Ql)(Kh+Kl)^T, 3 terms, two N=256 chunks ----
    if (w == 0) {
        const uint64_t qh = MK_DESC(sb + SM_C);
        const uint64_t ql = MK_DESC(sb + SM_C + 16384);
        const uint64_t kh = MK_DESC(sb + SM_A);
        const uint64_t kl = MK_DESC(sb + SM_B);
        const uint32_t id1 = IDESC_N(256);
        if (elect1()) {
            #pragma unroll
            for (int c = 0; c < 2; c++) {
                const uint32_t dst = tmem + c * 256;
                const uint64_t koff = (uint64_t)c * 2048;
                #pragma unroll
                for (int s = 0; s < 4; s++)
                    mma_f16_ss(dst, qh + s * 2, kh + koff + s * 2, id1, s > 0);
                #pragma unroll
                for (int s = 0; s < 4; s++)
                    mma_f16_ss(dst, ql + s * 2, kh + koff + s * 2, id1, 1);
                #pragma unroll
                for (int s = 0; s < 4; s++)
                    mma_f16_ss(dst, qh + s * 2, kl + koff + s * 2, id1, 1);
            }
            tc_commit(mbar);
        }
    }
    mbar_wait(mbar, 0);
    TC_FENCE_AFTER();

    // ================= two PV phases (j halves of 256) ====================
    float rsum = 0.f;
    const int sub = w & 3;
    const int row = sub * 32 + lane;
    const int colbase = (w < 4) ? 0 : 128;       // local j cols per warp-group
    const int rot = (lane >> 3) & 3;

    #pragma unroll 1
    for (int ph = 0; ph < 2; ph++) {
        // phase B must wait for MMA2-A to release P/V buffers
        if (ph == 1) { mbar_wait(mbar, 1); TC_FENCE_AFTER(); }

        // ---- load V half hi/lo: V[d][ph*256 + j], blocked-atom ----
        for (int e = tid; e < 2048; e += 256) {
            const int d = e >> 5, j8 = (e & 31) * 8;
            const float* vsrc = vbase + (size_t)d * NK + ph * 256 + j8;
            float4 v0 = *(const float4*)(vsrc);
            float4 v1 = *(const float4*)(vsrc + 4);
            float f[8] = {v0.x, v0.y, v0.z, v0.w, v1.x, v1.y, v1.z, v1.w};
            uint4 hi4, lo4;
            #pragma unroll
            for (int t = 0; t < 4; t++) {
                __nv_bfloat16 h0 = __float2bfloat16(f[2 * t]);
                __nv_bfloat16 h1 = __float2bfloat16(f[2 * t + 1]);
                __nv_bfloat162 hp; hp.x = h0; hp.y = h1;
                __nv_bfloat162 lp;
                lp.x = __float2bfloat16(f[2 * t] - __bfloat162float(h0));
                lp.y = __float2bfloat16(f[2 * t + 1] - __bfloat162float(h1));
                ((uint32_t*)&hi4)[t] = *(uint32_t*)&hp;
                ((uint32_t*)&lo4)[t] = *(uint32_t*)&lp;
            }
            *(uint4*)(base + SM_C + v_off(d, j8)) = hi4;
            *(uint4*)(base + SM_D + v_off(d, j8)) = lo4;
        }

        // ---- LDTM dots + exp + row-sum + split-store P hi/lo ----
        for (int c8 = 0; c8 < 4; c8++) {
            uint32_t r[32];
            TC_LD_X32(r, tmem + ph * 256 + colbase + c8 * 32);
            TC_WAIT_LD();
            float vexp[32];
            #pragma unroll
            for (int t = 0; t < 32; t++) {
                float ve = __expf(__uint_as_float(r[t]));
                vexp[t] = ve;
                rsum += ve;
            }
            uint32_t pkh[16], pkl[16];
            #pragma unroll
            for (int t = 0; t < 16; t++) {
                __nv_bfloat16 h0 = __float2bfloat16(vexp[2 * t]);
                __nv_bfloat16 h1 = __float2bfloat16(vexp[2 * t + 1]);
                __nv_bfloat162 hp; hp.x = h0; hp.y = h1;
                __nv_bfloat162 lp;
                lp.x = __float2bfloat16(vexp[2 * t] - __bfloat162float(h0));
                lp.y = __float2bfloat16(vexp[2 * t + 1] - __bfloat162float(h1));
                pkh[t] = *(uint32_t*)&hp;
                pkl[t] = *(uint32_t*)&lp;
            }
            const int jb = colbase + c8 * 32;   // local j in [0,256)
            #pragma unroll
            for (int q0 = 0; q0 < 4; q0++) {
                const int q = (q0 + rot) & 3;
                const uint32_t off = p_off(row, jb + q * 8);
                *(uint4*)(base + SM_A + off) =
                    make_uint4(pkh[q * 4], pkh[q * 4 + 1], pkh[q * 4 + 2], pkh[q * 4 + 3]);
                *(uint4*)(base + SM_B + off) =
                    make_uint4(pkl[q * 4], pkl[q * 4 + 1], pkl[q * 4 + 2], pkl[q * 4 + 3]);
            }
        }
        TC_FENCE_BEFORE();
        FENCE_ASYNC();
        __syncthreads();

        // ---- MMA2 phase: O += Ph*Vh + Pl*Vh + Ph*Vl (16 K-steps each) ----
        if (w == 0) {
            TC_FENCE_AFTER();
            const uint64_t phd = MK_DESC(sb + SM_A);
            const uint64_t pld = MK_DESC(sb + SM_B);
            const uint64_t vhd = MK_DESC(sb + SM_C);
            const uint64_t vld = MK_DESC(sb + SM_D);
            const uint32_t id2 = IDESC_N(64);
            if (elect1()) {
                #pragma unroll
                for (int t = 0; t < 3; t++) {
                    const uint64_t pd = (t == 1) ? pld : phd;
                    const uint64_t vd = (t == 2) ? vld : vhd;
                    #pragma unroll
                    for (int s = 0; s < 16; s++) {
                        uint64_t ad = pd + (uint64_t)(s >> 2) * 1024 + (s & 3) * 2;
                        uint64_t bd = vd + (uint64_t)(s >> 2) * 512  + (s & 3) * 2;
                        mma_f16_ss(tmem, ad, bd, id2,
                                   !(ph == 0 && t == 0 && s == 0));
                    }
                }
                tc_commit(mbar);
            }
        }
    }
    // final MMA2-B wait (3rd commit -> parity 0)
    mbar_wait(mbar, 0);
    TC_FENCE_AFTER();

    // ---- row sums -> linv ----
    if (w < 4) pa[row] = rsum; else pb[row] = rsum;
    __syncthreads();
    if (tid < 128) linv[tid] = 1.f / (pa[tid] + pb[tid]);
    __syncthreads();

    // ---- epilogue: scale by 1/l, stage sO[d][i], coalesced store ----
    float* sO = (float*)(base + SM_A);               // [64][132] floats
    {
        const int colb = (w < 4) ? 0 : 32;
        uint32_t r[32];
        TC_LD_X32(r, tmem + colb);
        TC_WAIT_LD();
        TC_FENCE_BEFORE();
        const float li = linv[row];
        #pragma unroll
        for (int t = 0; t < 32; t++)
            sO[(colb + t) * 132 + row] = __uint_as_float(r[t]) * li;
    }
    __syncthreads();
    for (int e = tid; e < 2048; e += 256) {
        const int d = e >> 5, i4 = (e & 31) * 4;
        float4 v = *(const float4*)(sO + d * 132 + i4);
        *(float4*)(gout + ((size_t)b * INNER + h * DHEAD + d) * NQ + i0 + i4) = v;
    }

    __syncthreads();
    if (tid == 0) mbar_inval(mbar);
    __syncthreads();
    if (w == 0) tmem_dealloc(tmem, 512);
#endif  // __CUDA_ARCH_FEAT_SM103_ALL
}

// ===========================================================================
// Kernel 3b: fp32 fallback attention — stub on sm_103a targets.
// ===========================================================================
#define ATT_SMEM ((64 * 68 + 64 * 68 + 512 * 68 + 64) * 4)

__global__ __launch_bounds__(256) void attn_fp32_kernel(
    const float* __restrict__ gq, const float* __restrict__ gkv,
    float* __restrict__ gout)
{
#if !defined(__CUDA_ARCH_FEAT_SM103_ALL)
    extern __shared__ float sm[];
    float* sQ   = sm;
    float* sK   = sQ + 64 * 68;
    float* sSt  = sK + 64 * 68;
    float* sLin = sSt + 512 * 68;

    const int i0 = blockIdx.x * 64;
    const int h  = blockIdx.y;
    const int b  = blockIdx.z;
    const int tid = threadIdx.x, tx = tid & 15, ty = tid >> 4;

    const float* qbase = gq  + ((size_t)b * INNER + h * DHEAD) * NQ + i0;
    const float* kbase = gkv + ((size_t)b * 2 * INNER + h * DHEAD) * NK;
    const float* vbase = kbase + (size_t)INNER * NK;

    {
        const int d = tid >> 2, p = tid & 3;
        #pragma unroll
        for (int s4 = 0; s4 < 4; s4++) {
            const int col = p * 16 + s4 * 4;
            float4 v = *(const float4*)(qbase + (size_t)d * NQ + col);
            v.x *= 0.125f; v.y *= 0.125f; v.z *= 0.125f; v.w *= 0.125f;
            *(float4*)(sQ + d * 68 + col) = v;
        }
    }

    for (int jc = 0; jc < NK; jc += 64) {
        __syncthreads();
        {
            const int d = tid >> 2, p = tid & 3;
            #pragma unroll
            for (int s4 = 0; s4 < 4; s4++) {
                const int col = p * 16 + s4 * 4;
                *(float4*)(sK + d * 68 + col) =
                    *(const float4*)(kbase + (size_t)d * NK + jc + col);
            }
        }
        __syncthreads();
        float acc[4][4] = {};
        #pragma unroll 8
        for (int d = 0; d < 64; d++) {
            float4 a4 = *(const float4*)(sQ + d * 68 + ty * 4);
            float4 b4 = *(const float4*)(sK + d * 68 + tx * 4);
            float a[4] = {a4.x, a4.y, a4.z, a4.w};
            float bb[4] = {b4.x, b4.y, b4.z, b4.w};
            #pragma unroll
            for (int i = 0; i < 4; i++)
                #pragma unroll
                for (int j = 0; j < 4; j++)
                    acc[i][j] += a[i] * bb[j];
        }
        #pragma unroll
        for (int j = 0; j < 4; j++)
            #pragma unroll
            for (int i = 0; i < 4; i++)
                sSt[(jc + tx * 4 + j) * 68 + ty * 4 + i] = acc[i][j];
    }
    __syncthreads();

    {
        const int sl = tid & 3, ii = tid >> 2;
        float m = -1e30f;
        for (int j = sl; j < NK; j += 4)
            m = fmaxf(m, sSt[j * 68 + ii]);
        m = fmaxf(m, __shfl_xor_sync(0xffffffffu, m, 1));
        m = fmaxf(m, __shfl_xor_sync(0xffffffffu, m, 2));
        float l = 0.f;
        for (int j = sl; j < NK; j += 4) {
            float p = __expf(sSt[j * 68 + ii] - m);
            sSt[j * 68 + ii] = p;
            l += p;
        }
        l += __shfl_xor_sync(0xffffffffu, l, 1);
        l += __shfl_xor_sync(0xffffffffu, l, 2);
        if (sl == 0) sLin[ii] = 1.f / l;
    }
    __syncthreads();

    float acc2[4][4] = {};
    float* sVt = sK;
    for (int jc = 0; jc < NK; jc += 64) {
        __syncthreads();
        {
            const int d = tid >> 2, p = tid & 3;
            #pragma unroll
            for (int s4 = 0; s4 < 4; s4++) {
                const int jj = p * 16 + s4 * 4;
                float4 v = *(const float4*)(vbase + (size_t)d * NK + jc + jj);
                sVt[(jj + 0) * 68 + d] = v.x;
                sVt[(jj + 1) * 68 + d] = v.y;
                sVt[(jj + 2) * 68 + d] = v.z;
                sVt[(jj + 3) * 68 + d] = v.w;
            }
        }
        __syncthreads();
        #pragma unroll 8
        for (int j = 0; j < 64; j++) {
            float4 a4 = *(const float4*)(sSt + (jc + j) * 68 + ty * 4);
            float4 b4 = *(const float4*)(sVt + j * 68 + tx * 4);
            float a[4] = {a4.x, a4.y, a4.z, a4.w};
            float bb[4] = {b4.x, b4.y, b4.z, b4.w};
            #pragma unroll
            for (int i = 0; i < 4; i++)
                #pragma unroll
                for (int d = 0; d < 4; d++)
                    acc2[i][d] += a[i] * bb[d];
        }
    }

    float linv4[4];
    #pragma unroll
    for (int i = 0; i < 4; i++) linv4[i] = sLin[ty * 4 + i];
    __syncthreads();
    float* sO = sQ;
    #pragma unroll
    for (int d = 0; d < 4; d++)
        #pragma unroll
        for (int i = 0; i < 4; i++)
            sO[(tx * 4 + d) * 68 + ty * 4 + i] = acc2[i][d] * linv4[i];
    __syncthreads();
    {
        const int d = tid >> 2, p = tid & 3;
        float* obase = gout + ((size_t)b * INNER + h * DHEAD + d) * NQ + i0;
        #pragma unroll
        for (int s4 = 0; s4 < 4; s4++) {
            const int col = p * 16 + s4 * 4;
            *(float4*)(obase + col) = *(const float4*)(sO + d * 68 + col);
        }
    }
#endif  // !__CUDA_ARCH_FEAT_SM103_ALL
}

// ---------------------------------------------------------------------------
extern "C" void kernel_launch(void* const* d_in, const int* in_sizes, int n_in,
                              void* d_out, int out_size)
{
    const float* x      = (const float*)d_in[0];
    const float* wq_dw  = (const float*)d_in[1];
    const float* bn_q_g = (const float*)d_in[2];
    const float* bn_q_b = (const float*)d_in[3];
    const float* bn_q_m = (const float*)d_in[4];
    const float* bn_q_v = (const float*)d_in[5];
    const float* wq_pw  = (const float*)d_in[6];
    const float* wkv_dw = (const float*)d_in[7];
    const float* bn_k_g = (const float*)d_in[8];
    const float* bn_k_b = (const float*)d_in[9];
    const float* bn_k_m = (const float*)d_in[10];
    const float* bn_k_v = (const float*)d_in[11];
    const float* wkv_pw = (const float*)d_in[12];
    const float* w_out  = (const float*)d_in[13];
    const float* b_out  = (const float*)d_in[14];
    float* out = (float*)d_out;

    float *p_qdw, *p_kvdw, *p_q, *p_kv, *p_att;
    cudaGetSymbolAddress((void**)&p_qdw,  g_qdw);
    cudaGetSymbolAddress((void**)&p_kvdw, g_kvdw);
    cudaGetSymbolAddress((void**)&p_q,    g_q);
    cudaGetSymbolAddress((void**)&p_kv,   g_kv);
    cudaGetSymbolAddress((void**)&p_att,  g_att);

    cudaFuncSetAttribute(attn_tc_kernel,
                         cudaFuncAttributeMaxDynamicSharedMemorySize, SM_REQ);
    cudaFuncSetAttribute(attn_fp32_kernel,
                         cudaFuncAttributeMaxDynamicSharedMemorySize, ATT_SMEM);

    // 1. depthwise convs + BN (fused)
    dw_bn_kernel<<<dim3(CDIM, BATCH), 256>>>(
        x, wq_dw, bn_q_g, bn_q_b, bn_q_m, bn_q_v,
        wkv_dw, bn_k_g, bn_k_b, bn_k_m, bn_k_v);

    // 2. pointwise q: (512 x 128) * (128 x 4096) per batch
    gemm_kernel<false><<<dim3(NQ / 64, INNER / 64, BATCH), 256>>>(
        wq_pw, p_qdw, p_q, INNER, NQ, CDIM, nullptr);

    // 3. pointwise kv: (1024 x 128) * (128 x 512) per batch
    gemm_kernel<false><<<dim3(NK / 64, (2 * INNER) / 64, BATCH), 256>>>(
        wkv_pw, p_kvdw, p_kv, 2 * INNER, NK, CDIM, nullptr);

    // 4. fused attention: tcgen05 on sm_103a, fp32 otherwise.
    attn_tc_kernel<<<dim3(NQ / 128, NHEADS, BATCH), 256, SM_REQ>>>(
        p_q, p_kv, p_att);
    attn_fp32_kernel<<<dim3(NQ / 64, NHEADS, BATCH), 256, ATT_SMEM>>>(
        p_q, p_kv, p_att);

    // 5. output projection with bias: (128 x 512) * (512 x 4096) per batch
    gemm_kernel<true><<<dim3(NQ / 64, CDIM / 64, BATCH), 256>>>(
        w_out, p_att, out, CDIM, NQ, INNER, b_out);
}

// round 8
// speedup vs baseline: 3.0948x; 1.7506x over previous
#include <cuda_runtime.h>
#include <cuda_bf16.h>
#include <cuda_fp16.h>
#include <math.h>
#include <stdint.h>

#define BATCH 4
#define CDIM 128
#define INNER 512
#define NQ 4096
#define NK 512
#define NHEADS 8
#define DHEAD 64

// ---------------- scratch (static device globals; allocation-free) ----------
__device__ float g_qdw[BATCH * CDIM * NQ];     // 8 MB   depthwise-q + BN
__device__ float g_kvdw[BATCH * CDIM * NK];    // 1 MB   depthwise-kv + BN
__device__ float g_q[BATCH * INNER * NQ];      // 32 MB  q after pointwise
__device__ float g_kv[BATCH * 2 * INNER * NK]; // 8 MB   kv after pointwise
__device__ float g_att[BATCH * INNER * NQ];    // 32 MB  attention output

// ---------------------------------------------------------------------------
// Kernel 1: both depthwise 3x3x3 convs (stride1 and stride2) + batchnorm.
// ---------------------------------------------------------------------------
__global__ __launch_bounds__(256) void dw_bn_kernel(
    const float* __restrict__ x,
    const float* __restrict__ wq,
    const float* __restrict__ qg, const float* __restrict__ qb,
    const float* __restrict__ qm, const float* __restrict__ qv,
    const float* __restrict__ wkv,
    const float* __restrict__ kg, const float* __restrict__ kb,
    const float* __restrict__ km, const float* __restrict__ kvvar)
{
    __shared__ float s[18 * 18 * 18];
    __shared__ float swq[27], swkv[27];
    const int c = blockIdx.x, b = blockIdx.y;
    const int tid = threadIdx.x;

    const float* xp = x + ((size_t)(b * CDIM + c)) * NQ;
    for (int idx = tid; idx < 5832; idx += 256) {
        int z = idx / 324; int r = idx - z * 324;
        int y = r / 18;    int xx = r - y * 18;
        z -= 1; y -= 1; xx -= 1;
        float v = 0.f;
        if ((unsigned)z < 16u && (unsigned)y < 16u && (unsigned)xx < 16u)
            v = xp[(z * 16 + y) * 16 + xx];
        s[idx] = v;
    }
    if (tid < 27) { swq[tid] = wq[c * 27 + tid]; swkv[tid] = wkv[c * 27 + tid]; }

    const float qscale = qg[c] * rsqrtf(qv[c] + 1e-5f);
    const float qshift = qb[c] - qm[c] * qscale;
    const float kscale = kg[c] * rsqrtf(kvvar[c] + 1e-5f);
    const float kshift = kb[c] - km[c] * kscale;
    __syncthreads();

    float* qo = g_qdw + ((size_t)(b * CDIM + c)) * NQ;
    for (int o = tid; o < 4096; o += 256) {
        const int z = o >> 8, y = (o >> 4) & 15, xx = o & 15;
        float sum = 0.f;
        #pragma unroll
        for (int dz = 0; dz < 3; dz++)
            #pragma unroll
            for (int dy = 0; dy < 3; dy++)
                #pragma unroll
                for (int dx = 0; dx < 3; dx++)
                    sum += swq[dz * 9 + dy * 3 + dx] *
                           s[(z + dz) * 324 + (y + dy) * 18 + (xx + dx)];
        qo[o] = sum * qscale + qshift;
    }

    float* ko = g_kvdw + ((size_t)(b * CDIM + c)) * NK;
    for (int o = tid; o < 512; o += 256) {
        const int z = o >> 6, y = (o >> 3) & 7, xx = o & 7;
        float sum = 0.f;
        #pragma unroll
        for (int dz = 0; dz < 3; dz++)
            #pragma unroll
            for (int dy = 0; dy < 3; dy++)
                #pragma unroll
                for (int dx = 0; dx < 3; dx++)
                    sum += swkv[dz * 9 + dy * 3 + dx] *
                           s[(2 * z + dz) * 324 + (2 * y + dy) * 18 + (2 * xx + dx)];
        ko[o] = sum * kscale + kshift;
    }
}

// ---------------------------------------------------------------------------
// Kernel 2: batched pointwise GEMM (fp32).
// ---------------------------------------------------------------------------
template <bool HAS_BIAS>
__global__ __launch_bounds__(256) void gemm_kernel(
    const float* __restrict__ A, const float* __restrict__ Bm,
    float* __restrict__ Cm, int M, int N, int K,
    const float* __restrict__ bias)
{
    __shared__ float AsT[16][68];
    __shared__ float Bs[16][68];

    const int bz = blockIdx.z;
    const float* Bp = Bm + (size_t)bz * K * N;
    float* Cp = Cm + (size_t)bz * M * N;
    const int n0 = blockIdx.x * 64, m0 = blockIdx.y * 64;
    const int tid = threadIdx.x, tx = tid & 15, ty = tid >> 4;

    const int am = tid >> 2, akq = tid & 3;
    const int bk = tid >> 4, bf = tid & 15;

    float acc[4][4] = {};
    for (int k0 = 0; k0 < K; k0 += 16) {
        __syncthreads();
        float4 av = *(const float4*)(A + (size_t)(m0 + am) * K + k0 + akq * 4);
        AsT[akq * 4 + 0][am] = av.x;
        AsT[akq * 4 + 1][am] = av.y;
        AsT[akq * 4 + 2][am] = av.z;
        AsT[akq * 4 + 3][am] = av.w;
        *(float4*)(&Bs[bk][bf * 4]) =
            *(const float4*)(Bp + (size_t)(k0 + bk) * N + n0 + bf * 4);
        __syncthreads();
        #pragma unroll
        for (int k = 0; k < 16; k++) {
            float4 a4 = *(const float4*)(&AsT[k][ty * 4]);
            float4 b4 = *(const float4*)(&Bs[k][tx * 4]);
            float a[4] = {a4.x, a4.y, a4.z, a4.w};
            float bb[4] = {b4.x, b4.y, b4.z, b4.w};
            #pragma unroll
            for (int i = 0; i < 4; i++)
                #pragma unroll
                for (int j = 0; j < 4; j++)
                    acc[i][j] += a[i] * bb[j];
        }
    }
    #pragma unroll
    for (int i = 0; i < 4; i++) {
        const int row = m0 + ty * 4 + i;
        float bb = HAS_BIAS ? bias[row] : 0.f;
        float4 v = make_float4(acc[i][0] + bb, acc[i][1] + bb,
                               acc[i][2] + bb, acc[i][3] + bb);
        *(float4*)(Cp + (size_t)row * N + n0 + tx * 4) = v;
    }
}

// ===========================================================================
// tcgen05 helpers
// ===========================================================================
__device__ __forceinline__ uint32_t s2u(const void* p) {
    uint32_t a;
    asm("{ .reg .u64 t; cvta.to.shared.u64 t, %1; cvt.u32.u64 %0, t; }"
        : "=r"(a) : "l"(p));
    return a;
}
__device__ __forceinline__ uint32_t elect1() {
    uint32_t pred;
    asm volatile("{\n\t.reg .pred p;\n\telect.sync _|p, 0xFFFFFFFF;\n\t"
                 "selp.b32 %0, 1, 0, p;\n\t}" : "=r"(pred));
    return pred;
}
__device__ __forceinline__ void mbar_init(uint32_t mbar, uint32_t cnt) {
    asm volatile("mbarrier.init.shared.b64 [%0], %1;" :: "r"(mbar), "r"(cnt) : "memory");
}
__device__ __forceinline__ void mbar_inval(uint32_t mbar) {
    asm volatile("mbarrier.inval.shared.b64 [%0];" :: "r"(mbar) : "memory");
}
__device__ __forceinline__ void mbar_wait(uint32_t mbar, uint32_t parity) {
    asm volatile(
        "{\n\t.reg .pred P1;\n\t"
        "WL%=:\n\t"
        "mbarrier.try_wait.parity.acquire.cta.shared::cta.b64 P1, [%0], %1, 0x989680;\n\t"
        "@P1 bra.uni WD%=;\n\t"
        "bra.uni WL%=;\n\t"
        "WD%=:\n\t}"
        :: "r"(mbar), "r"(parity) : "memory");
}
__device__ __forceinline__ void tmem_alloc(uint32_t smem_dst, uint32_t ncols) {
    asm volatile("tcgen05.alloc.cta_group::1.sync.aligned.shared::cta.b32 [%0], %1;"
                 :: "r"(smem_dst), "r"(ncols) : "memory");
}
__device__ __forceinline__ void tmem_dealloc(uint32_t tmem, uint32_t ncols) {
    asm volatile("tcgen05.relinquish_alloc_permit.cta_group::1.sync.aligned;");
    asm volatile("tcgen05.dealloc.cta_group::1.sync.aligned.b32 %0, %1;"
                 :: "r"(tmem), "r"(ncols));
}
__device__ __forceinline__ void mma_f16_ss(uint32_t d, uint64_t a, uint64_t b,
                                           uint32_t idesc, uint32_t en) {
    asm volatile(
        "{\n\t.reg .pred p;\n\tsetp.ne.u32 p, %5, 0;\n\t"
        "tcgen05.mma.cta_group::1.kind::f16 [%0], %1, %2, %3, {%4, %4, %4, %4}, p;\n\t}"
        :: "r"(d), "l"(a), "l"(b), "r"(idesc), "r"(0u), "r"(en) : "memory");
}
__device__ __forceinline__ void tc_commit(uint32_t mbar) {
    asm volatile(
        "tcgen05.commit.cta_group::1.mbarrier::arrive::one.shared::cluster.b64 [%0];"
        :: "r"(mbar) : "memory");
}
#define TC_FENCE_AFTER()  asm volatile("tcgen05.fence::after_thread_sync;" ::: "memory")
#define TC_FENCE_BEFORE() asm volatile("tcgen05.fence::before_thread_sync;" ::: "memory")
#define TC_WAIT_LD()      asm volatile("tcgen05.wait::ld.sync.aligned;" ::: "memory")
#define FENCE_ASYNC()     asm volatile("fence.proxy.async.shared::cta;" ::: "memory")

#define TC_LD_X32(r, addr) \
    asm volatile( \
        "tcgen05.ld.sync.aligned.32x32b.x32.b32 " \
        "{%0, %1, %2, %3, %4, %5, %6, %7, " \
        " %8, %9, %10, %11, %12, %13, %14, %15, " \
        " %16, %17, %18, %19, %20, %21, %22, %23, " \
        " %24, %25, %26, %27, %28, %29, %30, %31}, [%32];" \
        : "=r"((r)[0]),  "=r"((r)[1]),  "=r"((r)[2]),  "=r"((r)[3]), \
          "=r"((r)[4]),  "=r"((r)[5]),  "=r"((r)[6]),  "=r"((r)[7]), \
          "=r"((r)[8]),  "=r"((r)[9]),  "=r"((r)[10]), "=r"((r)[11]), \
          "=r"((r)[12]), "=r"((r)[13]), "=r"((r)[14]), "=r"((r)[15]), \
          "=r"((r)[16]), "=r"((r)[17]), "=r"((r)[18]), "=r"((r)[19]), \
          "=r"((r)[20]), "=r"((r)[21]), "=r"((r)[22]), "=r"((r)[23]), \
          "=r"((r)[24]), "=r"((r)[25]), "=r"((r)[26]), "=r"((r)[27]), \
          "=r"((r)[28]), "=r"((r)[29]), "=r"((r)[30]), "=r"((r)[31]) \
        : "r"(addr))

// SW128 smem descriptor base (layout=2, version=1, SBO=64, LBO=1)
#define DESC_BASE ((2ULL << 61) | (1ULL << 46) | (64ULL << 32) | (1ULL << 16))
#define MK_DESC(a) (DESC_BASE | ((uint64_t)((a) >> 4) & 0x3FFFULL))

// smem regions (relative to 1024-aligned base):
//  MISC 4KB
//  A 64KB: K chunk0 [hi rows 0-255 | lo rows 0-255]  ->  P fp16 cols 0-255 -> sO
//  B 64KB: K chunk1 [hi rows 256-511 | lo rows 256-511] -> P fp16 cols 256-511
//  C 32KB: Q hi (16K) + Q lo (16K)  ->  V0 fp16 (j 0-255)
//  D 32KB: V1 fp16 (j 256-511)
#define SM_MISC 0
#define SM_A    4096
#define SM_B    (SM_A + 65536)
#define SM_C    (SM_B + 65536)
#define SM_D    (SM_C + 32768)
#define SM_REQ  (SM_D + 32768 + 1024)

__device__ __forceinline__ uint32_t sw128(uint32_t o) { return o ^ ((o >> 3) & 0x70); }
__device__ __forceinline__ uint32_t qk_off(int r, int c) {   // rows x 64 elems (128B rows)
    return sw128((uint32_t)r * 128u + (uint32_t)c * 2u);
}
__device__ __forceinline__ uint32_t p_off(int i, int j) {    // 128 x 256 fp16, 16 atom-rows
    uint32_t o = ((uint32_t)(i >> 3) + (uint32_t)(j >> 6) * 16u) * 1024u +
                 (uint32_t)(i & 7) * 128u + (uint32_t)(j & 63) * 2u;
    return sw128(o);
}
__device__ __forceinline__ uint32_t v_off(int d, int j) {    // 64 x 256 fp16, 8 atom-rows
    uint32_t o = ((uint32_t)(d >> 3) + (uint32_t)(j >> 6) * 8u) * 1024u +
                 (uint32_t)(d & 7) * 128u + (uint32_t)(j & 63) * 2u;
    return sw128(o);
}

// idesc: dtype F32 (1<<4); atype/btype: BF16=1, F16=0; M=128 (8<<24); N bits 17..22
#define IDESC_BF16_N(n) ((1u << 4) | (1u << 7) | (1u << 10) | (((n) / 8) << 17) | (8u << 24))
#define IDESC_F16_N64   ((1u << 4) | (8u << 17) | (8u << 24))

// ===========================================================================
// Kernel 3a: tcgen05 fused attention. QK^T in bf16 hi/lo (3 terms), PV in
// plain fp16 (1 term, single pass). One CTA = (b, h, 128 q rows).
// grid (32, 8, 4), 512 threads.
// ===========================================================================
__global__ __launch_bounds__(512, 1)
void attn_tc_kernel(const float* __restrict__ gq,
                    const float* __restrict__ gkv,
                    float* __restrict__ gout)
{
#if defined(__CUDA_ARCH_FEAT_SM103_ALL)
    extern __shared__ char sm_raw[];
    char* base = (char*)(((uintptr_t)sm_raw + 1023) & ~(uintptr_t)1023);
    const uint32_t sb = s2u(base);

    const int tid = threadIdx.x, w = tid >> 5, lane = tid & 31;
    const int sub = w & 3, grp = w >> 2;         // TMEM subpartition / col quarter
    const int row = sub * 32 + lane;             // q row this thread owns in TMEM
    const int i0 = blockIdx.x * 128;
    const int h  = blockIdx.y;
    const int b  = blockIdx.z;

    const uint32_t misc  = sb + SM_MISC;
    const uint32_t mbar0 = misc + 8;
    const uint32_t mbar1 = misc + 16;
    const uint32_t mbar2 = misc + 24;
    float* sRow = (float*)(base + SM_MISC + 1024);   // [4][128] partial row sums
    float* linv = (float*)(base + SM_MISC + 3072);   // [128]

    if (w == 0) tmem_alloc(misc, 512);
    if (tid == 0) { mbar_init(mbar0, 1); mbar_init(mbar1, 1); mbar_init(mbar2, 1); }
    __syncthreads();
    uint32_t tmem;
    asm volatile("ld.shared.b32 %0, [%1];" : "=r"(tmem) : "r"(misc));

    const float* qbase = gq  + ((size_t)b * INNER + h * DHEAD) * NQ + i0;
    const float* kbase = gkv + ((size_t)b * 2 * INNER + h * DHEAD) * NK;
    const float* vbase = kbase + (size_t)INNER * NK;

    // ---- load Q hi/lo: transpose [d][i]->[i][d], scale 1/8, packed STS.128 ----
    for (int g = tid; g < 1024; g += 512) {
        const int i = g & 127, d0 = (g >> 7) * 8;
        float f[8];
        #pragma unroll
        for (int k = 0; k < 8; k++)
            f[k] = qbase[(size_t)(d0 + k) * NQ + i] * 0.125f;
        uint4 hi, lo;
        #pragma unroll
        for (int t = 0; t < 4; t++) {
            __nv_bfloat16 h0 = __float2bfloat16(f[2 * t]);
            __nv_bfloat16 h1 = __float2bfloat16(f[2 * t + 1]);
            __nv_bfloat162 hp; hp.x = h0; hp.y = h1;
            __nv_bfloat162 lp;
            lp.x = __float2bfloat16(f[2 * t] - __bfloat162float(h0));
            lp.y = __float2bfloat16(f[2 * t + 1] - __bfloat162float(h1));
            ((uint32_t*)&hi)[t] = *(uint32_t*)&hp;
            ((uint32_t*)&lo)[t] = *(uint32_t*)&lp;
        }
        const uint32_t off = qk_off(i, d0);
        *(uint4*)(base + SM_C + off) = hi;
        *(uint4*)(base + SM_C + 16384 + off) = lo;
    }
    // ---- load K hi/lo: transpose [d][j]->[j][d]; chunk0 rows->A, chunk1->B ----
    for (int g = tid; g < 4096; g += 512) {
        const int j = g & 511, d0 = (g >> 9) * 8;
        float f[8];
        #pragma unroll
        for (int k = 0; k < 8; k++)
            f[k] = kbase[(size_t)(d0 + k) * NK + j];
        uint4 hi, lo;
        #pragma unroll
        for (int t = 0; t < 4; t++) {
            __nv_bfloat16 h0 = __float2bfloat16(f[2 * t]);
            __nv_bfloat16 h1 = __float2bfloat16(f[2 * t + 1]);
            __nv_bfloat162 hp; hp.x = h0; hp.y = h1;
            __nv_bfloat162 lp;
            lp.x = __float2bfloat16(f[2 * t] - __bfloat162float(h0));
            lp.y = __float2bfloat16(f[2 * t + 1] - __bfloat162float(h1));
            ((uint32_t*)&hi)[t] = *(uint32_t*)&hp;
            ((uint32_t*)&lo)[t] = *(uint32_t*)&lp;
        }
        char* reg = base + ((j < 256) ? SM_A : SM_B);
        const uint32_t off = qk_off(j & 255, d0);
        *(uint4*)(reg + off) = hi;
        *(uint4*)(reg + 32768 + off) = lo;
    }
    FENCE_ASYNC();
    __syncthreads();

    // ---- MMA1: dots = (Qh+Ql)(Kh+Kl)^T; chunk0 -> mbar0, chunk1 -> mbar1 ----
    if (w == 0) {
        const uint64_t qh = MK_DESC(sb + SM_C);
        const uint64_t ql = MK_DESC(sb + SM_C + 16384);
        const uint32_t id1 = IDESC_BF16_N(256);
        if (elect1()) {
            #pragma unroll
            for (int c = 0; c < 2; c++) {
                const uint32_t dst = tmem + c * 256;
                const uint64_t kh = MK_DESC(sb + (c ? SM_B : SM_A));
                const uint64_t kl = kh + 2048;        // +32768 B
                #pragma unroll
                for (int s = 0; s < 4; s++)
                    mma_f16_ss(dst, qh + s * 2, kh + s * 2, id1, s > 0);
                #pragma unroll
                for (int s = 0; s < 4; s++)
                    mma_f16_ss(dst, ql + s * 2, kh + s * 2, id1, 1);
                #pragma unroll
                for (int s = 0; s < 4; s++)
                    mma_f16_ss(dst, qh + s * 2, kl + s * 2, id1, 1);
                tc_commit(c ? mbar1 : mbar0);
            }
        }
    }

    // ---- load V1 (j 256-511) -> D in fp16 (overlaps MMA1) ----
    for (int g = tid; g < 2048; g += 512) {
        const int d = g >> 5, j8 = (g & 31) * 8;
        const float* vs = vbase + (size_t)d * NK + 256 + j8;
        float4 v0 = *(const float4*)(vs);
        float4 v1 = *(const float4*)(vs + 4);
        uint4 pk;
        ((__half2*)&pk)[0] = __floats2half2_rn(v0.x, v0.y);
        ((__half2*)&pk)[1] = __floats2half2_rn(v0.z, v0.w);
        ((__half2*)&pk)[2] = __floats2half2_rn(v1.x, v1.y);
        ((__half2*)&pk)[3] = __floats2half2_rn(v1.z, v1.w);
        *(uint4*)(base + SM_D + v_off(d, j8)) = pk;
    }

    // ---- LDTM dots + exp + row-sum + store P (fp16). Warp quarter = 128 cols.
    //      grps 0,1 (cols 0-255, region A) only need chunk0 (mbar0).        ----
    mbar_wait(grp < 2 ? mbar0 : mbar1, 0);
    TC_FENCE_AFTER();
    {
        float rsum = 0.f;
        char* preg = base + (grp < 2 ? SM_A : SM_B);
        const int jbase = (grp & 1) * 128;     // local col within 256-col region
        for (int c8 = 0; c8 < 4; c8++) {
            uint32_t r[32];
            TC_LD_X32(r, tmem + grp * 128 + c8 * 32);
            TC_WAIT_LD();
            uint32_t pk[16];
            #pragma unroll
            for (int t = 0; t < 16; t++) {
                float e0 = __expf(__uint_as_float(r[2 * t]));
                float e1 = __expf(__uint_as_float(r[2 * t + 1]));
                rsum += e0 + e1;
                __half2 h2 = __floats2half2_rn(e0, e1);
                pk[t] = *(uint32_t*)&h2;
            }
            const int jl = jbase + c8 * 32;
            #pragma unroll
            for (int q = 0; q < 4; q++)
                *(uint4*)(preg + p_off(row, jl + q * 8)) =
                    make_uint4(pk[q * 4], pk[q * 4 + 1], pk[q * 4 + 2], pk[q * 4 + 3]);
        }
        sRow[grp * 128 + row] = rsum;
        TC_FENCE_BEFORE();
    }

    // ---- load V0 (j 0-255) -> C; Q is dead once chunk1 MMAs finished ----
    mbar_wait(mbar1, 0);     // immediate for grps 2,3
    for (int g = tid; g < 2048; g += 512) {
        const int d = g >> 5, j8 = (g & 31) * 8;
        const float* vs = vbase + (size_t)d * NK + j8;
        float4 v0 = *(const float4*)(vs);
        float4 v1 = *(const float4*)(vs + 4);
        uint4 pk;
        ((__half2*)&pk)[0] = __floats2half2_rn(v0.x, v0.y);
        ((__half2*)&pk)[1] = __floats2half2_rn(v0.z, v0.w);
        ((__half2*)&pk)[2] = __floats2half2_rn(v1.x, v1.y);
        ((__half2*)&pk)[3] = __floats2half2_rn(v1.z, v1.w);
        *(uint4*)(base + SM_C + v_off(d, j8)) = pk;
    }
    __syncthreads();
    if (tid < 128)
        linv[tid] = 1.f / (sRow[tid] + sRow[128 + tid] +
                           sRow[256 + tid] + sRow[384 + tid]);
    FENCE_ASYNC();
    __syncthreads();

    // ---- MMA2: O = P @ V^T, fp16, single pass, K=512 (32 steps) ----
    if (w == 0) {
        TC_FENCE_AFTER();
        if (elect1()) {
            #pragma unroll
            for (int s = 0; s < 32; s++) {
                const uint64_t pd = MK_DESC(sb + ((s < 16) ? SM_A : SM_B));
                const uint64_t vd = MK_DESC(sb + ((s < 16) ? SM_C : SM_D));
                const int sl = s & 15;
                uint64_t ad = pd + (uint64_t)(sl >> 2) * 1024 + (sl & 3) * 2;
                uint64_t bd = vd + (uint64_t)(sl >> 2) * 512  + (sl & 3) * 2;
                mma_f16_ss(tmem, ad, bd, IDESC_F16_N64, s > 0);
            }
            tc_commit(mbar2);
        }
    }
    mbar_wait(mbar2, 0);
    TC_FENCE_AFTER();

    // ---- epilogue: scale by 1/l, stage sO[d][i] in A, coalesced store ----
    float* sO = (float*)(base + SM_A);       // [64][132] floats
    if (grp < 2) {
        const int colb = grp * 32;
        uint32_t r[32];
        TC_LD_X32(r, tmem + colb);
        TC_WAIT_LD();
        TC_FENCE_BEFORE();
        const float li = linv[row];
        #pragma unroll
        for (int t = 0; t < 32; t++)
            sO[(colb + t) * 132 + row] = __uint_as_float(r[t]) * li;
    }
    __syncthreads();
    for (int e = tid; e < 2048; e += 512) {
        const int d = e >> 5, i4 = (e & 31) * 4;
        float4 v = *(const float4*)(sO + d * 132 + i4);
        *(float4*)(gout + ((size_t)b * INNER + h * DHEAD + d) * NQ + i0 + i4) = v;
    }

    __syncthreads();
    if (tid == 0) { mbar_inval(mbar0); mbar_inval(mbar1); mbar_inval(mbar2); }
    __syncthreads();
    if (w == 0) tmem_dealloc(tmem, 512);
#endif  // __CUDA_ARCH_FEAT_SM103_ALL
}

// ===========================================================================
// Kernel 3b: fp32 fallback attention — stub on sm_103a targets.
// ===========================================================================
#define ATT_SMEM ((64 * 68 + 64 * 68 + 512 * 68 + 64) * 4)

__global__ __launch_bounds__(256) void attn_fp32_kernel(
    const float* __restrict__ gq, const float* __restrict__ gkv,
    float* __restrict__ gout)
{
#if !defined(__CUDA_ARCH_FEAT_SM103_ALL)
    extern __shared__ float sm[];
    float* sQ   = sm;
    float* sK   = sQ + 64 * 68;
    float* sSt  = sK + 64 * 68;
    float* sLin = sSt + 512 * 68;

    const int i0 = blockIdx.x * 64;
    const int h  = blockIdx.y;
    const int b  = blockIdx.z;
    const int tid = threadIdx.x, tx = tid & 15, ty = tid >> 4;

    const float* qbase = gq  + ((size_t)b * INNER + h * DHEAD) * NQ + i0;
    const float* kbase = gkv + ((size_t)b * 2 * INNER + h * DHEAD) * NK;
    const float* vbase = kbase + (size_t)INNER * NK;

    {
        const int d = tid >> 2, p = tid & 3;
        #pragma unroll
        for (int s4 = 0; s4 < 4; s4++) {
            const int col = p * 16 + s4 * 4;
            float4 v = *(const float4*)(qbase + (size_t)d * NQ + col);
            v.x *= 0.125f; v.y *= 0.125f; v.z *= 0.125f; v.w *= 0.125f;
            *(float4*)(sQ + d * 68 + col) = v;
        }
    }

    for (int jc = 0; jc < NK; jc += 64) {
        __syncthreads();
        {
            const int d = tid >> 2, p = tid & 3;
            #pragma unroll
            for (int s4 = 0; s4 < 4; s4++) {
                const int col = p * 16 + s4 * 4;
                *(float4*)(sK + d * 68 + col) =
                    *(const float4*)(kbase + (size_t)d * NK + jc + col);
            }
        }
        __syncthreads();
        float acc[4][4] = {};
        #pragma unroll 8
        for (int d = 0; d < 64; d++) {
            float4 a4 = *(const float4*)(sQ + d * 68 + ty * 4);
            float4 b4 = *(const float4*)(sK + d * 68 + tx * 4);
            float a[4] = {a4.x, a4.y, a4.z, a4.w};
            float bb[4] = {b4.x, b4.y, b4.z, b4.w};
            #pragma unroll
            for (int i = 0; i < 4; i++)
                #pragma unroll
                for (int j = 0; j < 4; j++)
                    acc[i][j] += a[i] * bb[j];
        }
        #pragma unroll
        for (int j = 0; j < 4; j++)
            #pragma unroll
            for (int i = 0; i < 4; i++)
                sSt[(jc + tx * 4 + j) * 68 + ty * 4 + i] = acc[i][j];
    }
    __syncthreads();

    {
        const int sl = tid & 3, ii = tid >> 2;
        float m = -1e30f;
        for (int j = sl; j < NK; j += 4)
            m = fmaxf(m, sSt[j * 68 + ii]);
        m = fmaxf(m, __shfl_xor_sync(0xffffffffu, m, 1));
        m = fmaxf(m, __shfl_xor_sync(0xffffffffu, m, 2));
        float l = 0.f;
        for (int j = sl; j < NK; j += 4) {
            float p = __expf(sSt[j * 68 + ii] - m);
            sSt[j * 68 + ii] = p;
            l += p;
        }
        l += __shfl_xor_sync(0xffffffffu, l, 1);
        l += __shfl_xor_sync(0xffffffffu, l, 2);
        if (sl == 0) sLin[ii] = 1.f / l;
    }
    __syncthreads();

    float acc2[4][4] = {};
    float* sVt = sK;
    for (int jc = 0; jc < NK; jc += 64) {
        __syncthreads();
        {
            const int d = tid >> 2, p = tid & 3;
            #pragma unroll
            for (int s4 = 0; s4 < 4; s4++) {
                const int jj = p * 16 + s4 * 4;
                float4 v = *(const float4*)(vbase + (size_t)d * NK + jc + jj);
                sVt[(jj + 0) * 68 + d] = v.x;
                sVt[(jj + 1) * 68 + d] = v.y;
                sVt[(jj + 2) * 68 + d] = v.z;
                sVt[(jj + 3) * 68 + d] = v.w;
            }
        }
        __syncthreads();
        #pragma unroll 8
        for (int j = 0; j < 64; j++) {
            float4 a4 = *(const float4*)(sSt + (jc + j) * 68 + ty * 4);
            float4 b4 = *(const float4*)(sVt + j * 68 + tx * 4);
            float a[4] = {a4.x, a4.y, a4.z, a4.w};
            float bb[4] = {b4.x, b4.y, b4.z, b4.w};
            #pragma unroll
            for (int i = 0; i < 4; i++)
                #pragma unroll
                for (int d = 0; d < 4; d++)
                    acc2[i][d] += a[i] * bb[d];
        }
    }

    float linv4[4];
    #pragma unroll
    for (int i = 0; i < 4; i++) linv4[i] = sLin[ty * 4 + i];
    __syncthreads();
    float* sO = sQ;
    #pragma unroll
    for (int d = 0; d < 4; d++)
        #pragma unroll
        for (int i = 0; i < 4; i++)
            sO[(tx * 4 + d) * 68 + ty * 4 + i] = acc2[i][d] * linv4[i];
    __syncthreads();
    {
        const int d = tid >> 2, p = tid & 3;
        float* obase = gout + ((size_t)b * INNER + h * DHEAD + d) * NQ + i0;
        #pragma unroll
        for (int s4 = 0; s4 < 4; s4++) {
            const int col = p * 16 + s4 * 4;
            *(float4*)(obase + col) = *(const float4*)(sO + d * 68 + col);
        }
    }
#endif  // !__CUDA_ARCH_FEAT_SM103_ALL
}

// ---------------------------------------------------------------------------
extern "C" void kernel_launch(void* const* d_in, const int* in_sizes, int n_in,
                              void* d_out, int out_size)
{
    const float* x      = (const float*)d_in[0];
    const float* wq_dw  = (const float*)d_in[1];
    const float* bn_q_g = (const float*)d_in[2];
    const float* bn_q_b = (const float*)d_in[3];
    const float* bn_q_m = (const float*)d_in[4];
    const float* bn_q_v = (const float*)d_in[5];
    const float* wq_pw  = (const float*)d_in[6];
    const float* wkv_dw = (const float*)d_in[7];
    const float* bn_k_g = (const float*)d_in[8];
    const float* bn_k_b = (const float*)d_in[9];
    const float* bn_k_m = (const float*)d_in[10];
    const float* bn_k_v = (const float*)d_in[11];
    const float* wkv_pw = (const float*)d_in[12];
    const float* w_out  = (const float*)d_in[13];
    const float* b_out  = (const float*)d_in[14];
    float* out = (float*)d_out;

    float *p_qdw, *p_kvdw, *p_q, *p_kv, *p_att;
    cudaGetSymbolAddress((void**)&p_qdw,  g_qdw);
    cudaGetSymbolAddress((void**)&p_kvdw, g_kvdw);
    cudaGetSymbolAddress((void**)&p_q,    g_q);
    cudaGetSymbolAddress((void**)&p_kv,   g_kv);
    cudaGetSymbolAddress((void**)&p_att,  g_att);

    cudaFuncSetAttribute(attn_tc_kernel,
                         cudaFuncAttributeMaxDynamicSharedMemorySize, SM_REQ);
    cudaFuncSetAttribute(attn_fp32_kernel,
                         cudaFuncAttributeMaxDynamicSharedMemorySize, ATT_SMEM);

    // 1. depthwise convs + BN (fused)
    dw_bn_kernel<<<dim3(CDIM, BATCH), 256>>>(
        x, wq_dw, bn_q_g, bn_q_b, bn_q_m, bn_q_v,
        wkv_dw, bn_k_g, bn_k_b, bn_k_m, bn_k_v);

    // 2. pointwise q: (512 x 128) * (128 x 4096) per batch
    gemm_kernel<false><<<dim3(NQ / 64, INNER / 64, BATCH), 256>>>(
        wq_pw, p_qdw, p_q, INNER, NQ, CDIM, nullptr);

    // 3. pointwise kv: (1024 x 128) * (128 x 512) per batch
    gemm_kernel<false><<<dim3(NK / 64, (2 * INNER) / 64, BATCH), 256>>>(
        wkv_pw, p_kvdw, p_kv, 2 * INNER, NK, CDIM, nullptr);

    // 4. fused attention: tcgen05 on sm_103a, fp32 otherwise.
    attn_tc_kernel<<<dim3(NQ / 128, NHEADS, BATCH), 512, SM_REQ>>>(
        p_q, p_kv, p_att);
    attn_fp32_kernel<<<dim3(NQ / 64, NHEADS, BATCH), 256, ATT_SMEM>>>(
        p_q, p_kv, p_att);

    // 5. output projection with bias: (128 x 512) * (512 x 4096) per batch
    gemm_kernel<true><<<dim3(NQ / 64, CDIM / 64, BATCH), 256>>>(
        w_out, p_att, out, CDIM, NQ, INNER, b_out);
}

// round 9
// speedup vs baseline: 4.4898x; 1.4508x over previous
#include <cuda_runtime.h>
#include <cuda_bf16.h>
#include <cuda_fp16.h>
#include <math.h>
#include <stdint.h>

#define BATCH 4
#define CDIM 128
#define INNER 512
#define NQ 4096
#define NK 512
#define NHEADS 8
#define DHEAD 64

// ---------------- scratch (static device globals; allocation-free) ----------
__device__ float g_qdw[BATCH * CDIM * NQ];     // 8 MB   depthwise-q + BN
__device__ float g_kvdw[BATCH * CDIM * NK];    // 1 MB   depthwise-kv + BN
__device__ float g_q[BATCH * INNER * NQ];      // 32 MB  q after pointwise
__device__ float g_kv[BATCH * 2 * INNER * NK]; // 8 MB   kv after pointwise
__device__ float g_att[BATCH * INNER * NQ];    // 32 MB  attention output

// ---------------------------------------------------------------------------
// Kernel 1: both depthwise 3x3x3 convs (stride1 and stride2) + batchnorm.
// ---------------------------------------------------------------------------
__global__ __launch_bounds__(256) void dw_bn_kernel(
    const float* __restrict__ x,
    const float* __restrict__ wq,
    const float* __restrict__ qg, const float* __restrict__ qb,
    const float* __restrict__ qm, const float* __restrict__ qv,
    const float* __restrict__ wkv,
    const float* __restrict__ kg, const float* __restrict__ kb,
    const float* __restrict__ km, const float* __restrict__ kvvar)
{
    __shared__ float s[18 * 18 * 18];
    __shared__ float swq[27], swkv[27];
    const int c = blockIdx.x, b = blockIdx.y;
    const int tid = threadIdx.x;

    const float* xp = x + ((size_t)(b * CDIM + c)) * NQ;
    for (int idx = tid; idx < 5832; idx += 256) {
        int z = idx / 324; int r = idx - z * 324;
        int y = r / 18;    int xx = r - y * 18;
        z -= 1; y -= 1; xx -= 1;
        float v = 0.f;
        if ((unsigned)z < 16u && (unsigned)y < 16u && (unsigned)xx < 16u)
            v = xp[(z * 16 + y) * 16 + xx];
        s[idx] = v;
    }
    if (tid < 27) { swq[tid] = wq[c * 27 + tid]; swkv[tid] = wkv[c * 27 + tid]; }

    const float qscale = qg[c] * rsqrtf(qv[c] + 1e-5f);
    const float qshift = qb[c] - qm[c] * qscale;
    const float kscale = kg[c] * rsqrtf(kvvar[c] + 1e-5f);
    const float kshift = kb[c] - km[c] * kscale;
    __syncthreads();

    float* qo = g_qdw + ((size_t)(b * CDIM + c)) * NQ;
    for (int o = tid; o < 4096; o += 256) {
        const int z = o >> 8, y = (o >> 4) & 15, xx = o & 15;
        float sum = 0.f;
        #pragma unroll
        for (int dz = 0; dz < 3; dz++)
            #pragma unroll
            for (int dy = 0; dy < 3; dy++)
                #pragma unroll
                for (int dx = 0; dx < 3; dx++)
                    sum += swq[dz * 9 + dy * 3 + dx] *
                           s[(z + dz) * 324 + (y + dy) * 18 + (xx + dx)];
        qo[o] = sum * qscale + qshift;
    }

    float* ko = g_kvdw + ((size_t)(b * CDIM + c)) * NK;
    for (int o = tid; o < 512; o += 256) {
        const int z = o >> 6, y = (o >> 3) & 7, xx = o & 7;
        float sum = 0.f;
        #pragma unroll
        for (int dz = 0; dz < 3; dz++)
            #pragma unroll
            for (int dy = 0; dy < 3; dy++)
                #pragma unroll
                for (int dx = 0; dx < 3; dx++)
                    sum += swkv[dz * 9 + dy * 3 + dx] *
                           s[(2 * z + dz) * 324 + (2 * y + dy) * 18 + (2 * xx + dx)];
        ko[o] = sum * kscale + kshift;
    }
}

// ===========================================================================
// tcgen05 helpers
// ===========================================================================
__device__ __forceinline__ uint32_t s2u(const void* p) {
    uint32_t a;
    asm("{ .reg .u64 t; cvta.to.shared.u64 t, %1; cvt.u32.u64 %0, t; }"
        : "=r"(a) : "l"(p));
    return a;
}
__device__ __forceinline__ uint32_t elect1() {
    uint32_t pred;
    asm volatile("{\n\t.reg .pred p;\n\telect.sync _|p, 0xFFFFFFFF;\n\t"
                 "selp.b32 %0, 1, 0, p;\n\t}" : "=r"(pred));
    return pred;
}
__device__ __forceinline__ void mbar_init(uint32_t mbar, uint32_t cnt) {
    asm volatile("mbarrier.init.shared.b64 [%0], %1;" :: "r"(mbar), "r"(cnt) : "memory");
}
__device__ __forceinline__ void mbar_inval(uint32_t mbar) {
    asm volatile("mbarrier.inval.shared.b64 [%0];" :: "r"(mbar) : "memory");
}
__device__ __forceinline__ void mbar_wait(uint32_t mbar, uint32_t parity) {
    asm volatile(
        "{\n\t.reg .pred P1;\n\t"
        "WL%=:\n\t"
        "mbarrier.try_wait.parity.acquire.cta.shared::cta.b64 P1, [%0], %1, 0x989680;\n\t"
        "@P1 bra.uni WD%=;\n\t"
        "bra.uni WL%=;\n\t"
        "WD%=:\n\t}"
        :: "r"(mbar), "r"(parity) : "memory");
}
__device__ __forceinline__ void tmem_alloc(uint32_t smem_dst, uint32_t ncols) {
    asm volatile("tcgen05.alloc.cta_group::1.sync.aligned.shared::cta.b32 [%0], %1;"
                 :: "r"(smem_dst), "r"(ncols) : "memory");
}
__device__ __forceinline__ void tmem_dealloc(uint32_t tmem, uint32_t ncols) {
    asm volatile("tcgen05.relinquish_alloc_permit.cta_group::1.sync.aligned;");
    asm volatile("tcgen05.dealloc.cta_group::1.sync.aligned.b32 %0, %1;"
                 :: "r"(tmem), "r"(ncols));
}
__device__ __forceinline__ void mma_f16_ss(uint32_t d, uint64_t a, uint64_t b,
                                           uint32_t idesc, uint32_t en) {
    asm volatile(
        "{\n\t.reg .pred p;\n\tsetp.ne.u32 p, %5, 0;\n\t"
        "tcgen05.mma.cta_group::1.kind::f16 [%0], %1, %2, %3, {%4, %4, %4, %4}, p;\n\t}"
        :: "r"(d), "l"(a), "l"(b), "r"(idesc), "r"(0u), "r"(en) : "memory");
}
__device__ __forceinline__ void tc_commit(uint32_t mbar) {
    asm volatile(
        "tcgen05.commit.cta_group::1.mbarrier::arrive::one.shared::cluster.b64 [%0];"
        :: "r"(mbar) : "memory");
}
#define TC_FENCE_AFTER()  asm volatile("tcgen05.fence::after_thread_sync;" ::: "memory")
#define TC_FENCE_BEFORE() asm volatile("tcgen05.fence::before_thread_sync;" ::: "memory")
#define TC_WAIT_LD()      asm volatile("tcgen05.wait::ld.sync.aligned;" ::: "memory")
#define FENCE_ASYNC()     asm volatile("fence.proxy.async.shared::cta;" ::: "memory")

#define TC_LD_X32(r, addr) \
    asm volatile( \
        "tcgen05.ld.sync.aligned.32x32b.x32.b32 " \
        "{%0, %1, %2, %3, %4, %5, %6, %7, " \
        " %8, %9, %10, %11, %12, %13, %14, %15, " \
        " %16, %17, %18, %19, %20, %21, %22, %23, " \
        " %24, %25, %26, %27, %28, %29, %30, %31}, [%32];" \
        : "=r"((r)[0]),  "=r"((r)[1]),  "=r"((r)[2]),  "=r"((r)[3]), \
          "=r"((r)[4]),  "=r"((r)[5]),  "=r"((r)[6]),  "=r"((r)[7]), \
          "=r"((r)[8]),  "=r"((r)[9]),  "=r"((r)[10]), "=r"((r)[11]), \
          "=r"((r)[12]), "=r"((r)[13]), "=r"((r)[14]), "=r"((r)[15]), \
          "=r"((r)[16]), "=r"((r)[17]), "=r"((r)[18]), "=r"((r)[19]), \
          "=r"((r)[20]), "=r"((r)[21]), "=r"((r)[22]), "=r"((r)[23]), \
          "=r"((r)[24]), "=r"((r)[25]), "=r"((r)[26]), "=r"((r)[27]), \
          "=r"((r)[28]), "=r"((r)[29]), "=r"((r)[30]), "=r"((r)[31]) \
        : "r"(addr))

// SW128 smem descriptor base (layout=2, version=1, SBO=64, LBO=1)
#define DESC_BASE ((2ULL << 61) | (1ULL << 46) | (64ULL << 32) | (1ULL << 16))
#define MK_DESC(a) (DESC_BASE | ((uint64_t)((a) >> 4) & 0x3FFFULL))

__device__ __forceinline__ uint32_t sw128(uint32_t o) { return o ^ ((o >> 3) & 0x70); }
// 128 rows x 64 elems (128B rows), SW128
__device__ __forceinline__ uint32_t qk_off(int r, int c) {
    return sw128((uint32_t)r * 128u + (uint32_t)c * 2u);
}
// 128 x 256 fp16/bf16, 16 atom-rows per atom-col
__device__ __forceinline__ uint32_t p_off(int i, int j) {
    uint32_t o = ((uint32_t)(i >> 3) + (uint32_t)(j >> 6) * 16u) * 1024u +
                 (uint32_t)(i & 7) * 128u + (uint32_t)(j & 63) * 2u;
    return sw128(o);
}
// 64 x 256 fp16, 8 atom-rows per atom-col
__device__ __forceinline__ uint32_t v_off(int d, int j) {
    uint32_t o = ((uint32_t)(d >> 3) + (uint32_t)(j >> 6) * 8u) * 1024u +
                 (uint32_t)(d & 7) * 128u + (uint32_t)(j & 63) * 2u;
    return sw128(o);
}

// idesc: dtype F32 (1<<4); atype/btype: BF16=1, F16=0; M=128 (8<<24); N bits 17..22
#define IDESC_BF16_N(n) ((1u << 4) | (1u << 7) | (1u << 10) | (((n) / 8) << 17) | (8u << 24))
#define IDESC_F16_N64   ((1u << 4) | (8u << 17) | (8u << 24))

// ===========================================================================
// Kernel 2: tcgen05 GEMM with bf16 hi/lo compensation on both operands.
// C[b][m0+128][n0+128] = A[M,K] (row-major, K-major) @ B[b][K,N] (N contig).
// K looped in 128-chunks accumulating in TMEM. grid (N/128, M/128, BATCH),
// 512 threads.
// ===========================================================================
#define GM_MISC 0
#define GM_AH   1024
#define GM_AL   (GM_AH + 32768)
#define GM_BH   (GM_AL + 32768)
#define GM_BL   (GM_BH + 32768)
#define GM_REQ  (GM_BL + 32768 + 1024)

__global__ __launch_bounds__(512, 1)
void gemm_tc_kernel(const float* __restrict__ A, const float* __restrict__ Bm,
                    float* __restrict__ Cm, int M, int N, int K,
                    const float* __restrict__ bias)
{
#if defined(__CUDA_ARCH_FEAT_SM103_ALL)
    extern __shared__ char sm_raw[];
    char* base = (char*)(((uintptr_t)sm_raw + 1023) & ~(uintptr_t)1023);
    const uint32_t sb = s2u(base);

    const int tid = threadIdx.x, w = tid >> 5, lane = tid & 31;
    const int sub = w & 3, grp = w >> 2;
    const int row = sub * 32 + lane;
    const int n0 = blockIdx.x * 128, m0 = blockIdx.y * 128, bz = blockIdx.z;

    const uint32_t misc = sb + GM_MISC;
    const uint32_t mbar = misc + 8;
    if (w == 0) tmem_alloc(misc, 128);
    if (tid == 0) mbar_init(mbar, 1);
    __syncthreads();
    uint32_t tmem;
    asm volatile("ld.shared.b32 %0, [%1];" : "=r"(tmem) : "r"(misc));

    const float* Bp = Bm + (size_t)bz * K * N;
    float* Cp = Cm + (size_t)bz * M * N;
    const int nchunks = K >> 7;

    for (int kc = 0; kc < nchunks; kc++) {
        const int k0 = kc << 7;
        // ---- load A tile [128 m][128 k] -> hi/lo, blocked-atom ----
        for (int g = tid; g < 2048; g += 512) {
            const int m = g >> 4, kg = (g & 15) * 8;
            const float* as = A + (size_t)(m0 + m) * K + k0 + kg;
            float4 a0 = *(const float4*)(as);
            float4 a1 = *(const float4*)(as + 4);
            float f[8] = {a0.x, a0.y, a0.z, a0.w, a1.x, a1.y, a1.z, a1.w};
            uint4 hi, lo;
            #pragma unroll
            for (int t = 0; t < 4; t++) {
                __nv_bfloat16 h0 = __float2bfloat16(f[2 * t]);
                __nv_bfloat16 h1 = __float2bfloat16(f[2 * t + 1]);
                __nv_bfloat162 hp; hp.x = h0; hp.y = h1;
                __nv_bfloat162 lp;
                lp.x = __float2bfloat16(f[2 * t] - __bfloat162float(h0));
                lp.y = __float2bfloat16(f[2 * t + 1] - __bfloat162float(h1));
                ((uint32_t*)&hi)[t] = *(uint32_t*)&hp;
                ((uint32_t*)&lo)[t] = *(uint32_t*)&lp;
            }
            const uint32_t off = p_off(m, kg);
            *(uint4*)(base + GM_AH + off) = hi;
            *(uint4*)(base + GM_AL + off) = lo;
        }
        // ---- load B tile transposed: Bs[n][k] = B[k0+k][n0+n], hi/lo ----
        for (int g = tid; g < 2048; g += 512) {
            const int n = g & 127, kg = (g >> 7) * 8;
            const float* bs = Bp + (size_t)(k0 + kg) * N + n0 + n;
            float f[8];
            #pragma unroll
            for (int j = 0; j < 8; j++) f[j] = bs[(size_t)j * N];
            uint4 hi, lo;
            #pragma unroll
            for (int t = 0; t < 4; t++) {
                __nv_bfloat16 h0 = __float2bfloat16(f[2 * t]);
                __nv_bfloat16 h1 = __float2bfloat16(f[2 * t + 1]);
                __nv_bfloat162 hp; hp.x = h0; hp.y = h1;
                __nv_bfloat162 lp;
                lp.x = __float2bfloat16(f[2 * t] - __bfloat162float(h0));
                lp.y = __float2bfloat16(f[2 * t + 1] - __bfloat162float(h1));
                ((uint32_t*)&hi)[t] = *(uint32_t*)&hp;
                ((uint32_t*)&lo)[t] = *(uint32_t*)&lp;
            }
            const uint32_t off = p_off(n, kg);
            *(uint4*)(base + GM_BH + off) = hi;
            *(uint4*)(base + GM_BL + off) = lo;
        }
        FENCE_ASYNC();
        __syncthreads();

        // ---- 3-term MMA over this K-chunk (8 k-steps each) ----
        if (w == 0) {
            TC_FENCE_AFTER();
            const uint64_t ah = MK_DESC(sb + GM_AH);
            const uint64_t al = MK_DESC(sb + GM_AL);
            const uint64_t bh = MK_DESC(sb + GM_BH);
            const uint64_t bl = MK_DESC(sb + GM_BL);
            const uint32_t id = IDESC_BF16_N(128);
            if (elect1()) {
                #pragma unroll
                for (int t = 0; t < 3; t++) {
                    const uint64_t ad0 = (t == 1) ? al : ah;
                    const uint64_t bd0 = (t == 2) ? bl : bh;
                    #pragma unroll
                    for (int s = 0; s < 8; s++) {
                        uint64_t doff = (uint64_t)(s >> 2) * 1024 + (s & 3) * 2;
                        mma_f16_ss(tmem, ad0 + doff, bd0 + doff, id,
                                   !(kc == 0 && t == 0 && s == 0));
                    }
                }
                tc_commit(mbar);
            }
        }
        mbar_wait(mbar, kc & 1);
    }
    TC_FENCE_AFTER();

    // ---- epilogue: LDTM 32 cols per warp-group, (+bias), direct store ----
    {
        uint32_t r[32];
        TC_LD_X32(r, tmem + grp * 32);
        TC_WAIT_LD();
        TC_FENCE_BEFORE();
        const float bb = bias ? bias[m0 + row] : 0.f;
        float* cp = Cp + (size_t)(m0 + row) * N + n0 + grp * 32;
        float4 v;
        #pragma unroll
        for (int t = 0; t < 32; t += 4) {
            v = make_float4(__uint_as_float(r[t]) + bb,
                            __uint_as_float(r[t + 1]) + bb,
                            __uint_as_float(r[t + 2]) + bb,
                            __uint_as_float(r[t + 3]) + bb);
            *(float4*)(cp + t) = v;
        }
    }

    __syncthreads();
    if (tid == 0) mbar_inval(mbar);
    __syncthreads();
    if (w == 0) tmem_dealloc(tmem, 128);
#endif
}

// smem regions for attention (relative to 1024-aligned base)
#define SM_MISC 0
#define SM_A    4096
#define SM_B    (SM_A + 65536)
#define SM_C    (SM_B + 65536)
#define SM_D    (SM_C + 32768)
#define SM_REQ  (SM_D + 32768 + 1024)

// ===========================================================================
// Kernel 3: tcgen05 fused attention (unchanged from R8).
// QK^T bf16 hi/lo (3 terms), PV plain fp16 single pass.
// One CTA = (b, h, 128 q rows). grid (32, 8, 4), 512 threads.
// ===========================================================================
__global__ __launch_bounds__(512, 1)
void attn_tc_kernel(const float* __restrict__ gq,
                    const float* __restrict__ gkv,
                    float* __restrict__ gout)
{
#if defined(__CUDA_ARCH_FEAT_SM103_ALL)
    extern __shared__ char sm_raw[];
    char* base = (char*)(((uintptr_t)sm_raw + 1023) & ~(uintptr_t)1023);
    const uint32_t sb = s2u(base);

    const int tid = threadIdx.x, w = tid >> 5, lane = tid & 31;
    const int sub = w & 3, grp = w >> 2;
    const int row = sub * 32 + lane;
    const int i0 = blockIdx.x * 128;
    const int h  = blockIdx.y;
    const int b  = blockIdx.z;

    const uint32_t misc  = sb + SM_MISC;
    const uint32_t mbar0 = misc + 8;
    const uint32_t mbar1 = misc + 16;
    const uint32_t mbar2 = misc + 24;
    float* sRow = (float*)(base + SM_MISC + 1024);
    float* linv = (float*)(base + SM_MISC + 3072);

    if (w == 0) tmem_alloc(misc, 512);
    if (tid == 0) { mbar_init(mbar0, 1); mbar_init(mbar1, 1); mbar_init(mbar2, 1); }
    __syncthreads();
    uint32_t tmem;
    asm volatile("ld.shared.b32 %0, [%1];" : "=r"(tmem) : "r"(misc));

    const float* qbase = gq  + ((size_t)b * INNER + h * DHEAD) * NQ + i0;
    const float* kbase = gkv + ((size_t)b * 2 * INNER + h * DHEAD) * NK;
    const float* vbase = kbase + (size_t)INNER * NK;

    for (int g = tid; g < 1024; g += 512) {
        const int i = g & 127, d0 = (g >> 7) * 8;
        float f[8];
        #pragma unroll
        for (int k = 0; k < 8; k++)
            f[k] = qbase[(size_t)(d0 + k) * NQ + i] * 0.125f;
        uint4 hi, lo;
        #pragma unroll
        for (int t = 0; t < 4; t++) {
            __nv_bfloat16 h0 = __float2bfloat16(f[2 * t]);
            __nv_bfloat16 h1 = __float2bfloat16(f[2 * t + 1]);
            __nv_bfloat162 hp; hp.x = h0; hp.y = h1;
            __nv_bfloat162 lp;
            lp.x = __float2bfloat16(f[2 * t] - __bfloat162float(h0));
            lp.y = __float2bfloat16(f[2 * t + 1] - __bfloat162float(h1));
            ((uint32_t*)&hi)[t] = *(uint32_t*)&hp;
            ((uint32_t*)&lo)[t] = *(uint32_t*)&lp;
        }
        const uint32_t off = qk_off(i, d0);
        *(uint4*)(base + SM_C + off) = hi;
        *(uint4*)(base + SM_C + 16384 + off) = lo;
    }
    for (int g = tid; g < 4096; g += 512) {
        const int j = g & 511, d0 = (g >> 9) * 8;
        float f[8];
        #pragma unroll
        for (int k = 0; k < 8; k++)
            f[k] = kbase[(size_t)(d0 + k) * NK + j];
        uint4 hi, lo;
        #pragma unroll
        for (int t = 0; t < 4; t++) {
            __nv_bfloat16 h0 = __float2bfloat16(f[2 * t]);
            __nv_bfloat16 h1 = __float2bfloat16(f[2 * t + 1]);
            __nv_bfloat162 hp; hp.x = h0; hp.y = h1;
            __nv_bfloat162 lp;
            lp.x = __float2bfloat16(f[2 * t] - __bfloat162float(h0));
            lp.y = __float2bfloat16(f[2 * t + 1] - __bfloat162float(h1));
            ((uint32_t*)&hi)[t] = *(uint32_t*)&hp;
            ((uint32_t*)&lo)[t] = *(uint32_t*)&lp;
        }
        char* reg = base + ((j < 256) ? SM_A : SM_B);
        const uint32_t off = qk_off(j & 255, d0);
        *(uint4*)(reg + off) = hi;
        *(uint4*)(reg + 32768 + off) = lo;
    }
    FENCE_ASYNC();
    __syncthreads();

    if (w == 0) {
        const uint64_t qh = MK_DESC(sb + SM_C);
        const uint64_t ql = MK_DESC(sb + SM_C + 16384);
        const uint32_t id1 = IDESC_BF16_N(256);
        if (elect1()) {
            #pragma unroll
            for (int c = 0; c < 2; c++) {
                const uint32_t dst = tmem + c * 256;
                const uint64_t kh = MK_DESC(sb + (c ? SM_B : SM_A));
                const uint64_t kl = kh + 2048;
                #pragma unroll
                for (int s = 0; s < 4; s++)
                    mma_f16_ss(dst, qh + s * 2, kh + s * 2, id1, s > 0);
                #pragma unroll
                for (int s = 0; s < 4; s++)
                    mma_f16_ss(dst, ql + s * 2, kh + s * 2, id1, 1);
                #pragma unroll
                for (int s = 0; s < 4; s++)
                    mma_f16_ss(dst, qh + s * 2, kl + s * 2, id1, 1);
                tc_commit(c ? mbar1 : mbar0);
            }
        }
    }

    for (int g = tid; g < 2048; g += 512) {
        const int d = g >> 5, j8 = (g & 31) * 8;
        const float* vs = vbase + (size_t)d * NK + 256 + j8;
        float4 v0 = *(const float4*)(vs);
        float4 v1 = *(const float4*)(vs + 4);
        uint4 pk;
        ((__half2*)&pk)[0] = __floats2half2_rn(v0.x, v0.y);
        ((__half2*)&pk)[1] = __floats2half2_rn(v0.z, v0.w);
        ((__half2*)&pk)[2] = __floats2half2_rn(v1.x, v1.y);
        ((__half2*)&pk)[3] = __floats2half2_rn(v1.z, v1.w);
        *(uint4*)(base + SM_D + v_off(d, j8)) = pk;
    }

    mbar_wait(grp < 2 ? mbar0 : mbar1, 0);
    TC_FENCE_AFTER();
    {
        float rsum = 0.f;
        char* preg = base + (grp < 2 ? SM_A : SM_B);
        const int jbase = (grp & 1) * 128;
        for (int c8 = 0; c8 < 4; c8++) {
            uint32_t r[32];
            TC_LD_X32(r, tmem + grp * 128 + c8 * 32);
            TC_WAIT_LD();
            uint32_t pk[16];
            #pragma unroll
            for (int t = 0; t < 16; t++) {
                float e0 = __expf(__uint_as_float(r[2 * t]));
                float e1 = __expf(__uint_as_float(r[2 * t + 1]));
                rsum += e0 + e1;
                __half2 h2 = __floats2half2_rn(e0, e1);
                pk[t] = *(uint32_t*)&h2;
            }
            const int jl = jbase + c8 * 32;
            #pragma unroll
            for (int q = 0; q < 4; q++)
                *(uint4*)(preg + p_off(row, jl + q * 8)) =
                    make_uint4(pk[q * 4], pk[q * 4 + 1], pk[q * 4 + 2], pk[q * 4 + 3]);
        }
        sRow[grp * 128 + row] = rsum;
        TC_FENCE_BEFORE();
    }

    mbar_wait(mbar1, 0);
    for (int g = tid; g < 2048; g += 512) {
        const int d = g >> 5, j8 = (g & 31) * 8;
        const float* vs = vbase + (size_t)d * NK + j8;
        float4 v0 = *(const float4*)(vs);
        float4 v1 = *(const float4*)(vs + 4);
        uint4 pk;
        ((__half2*)&pk)[0] = __floats2half2_rn(v0.x, v0.y);
        ((__half2*)&pk)[1] = __floats2half2_rn(v0.z, v0.w);
        ((__half2*)&pk)[2] = __floats2half2_rn(v1.x, v1.y);
        ((__half2*)&pk)[3] = __floats2half2_rn(v1.z, v1.w);
        *(uint4*)(base + SM_C + v_off(d, j8)) = pk;
    }
    __syncthreads();
    if (tid < 128)
        linv[tid] = 1.f / (sRow[tid] + sRow[128 + tid] +
                           sRow[256 + tid] + sRow[384 + tid]);
    FENCE_ASYNC();
    __syncthreads();

    if (w == 0) {
        TC_FENCE_AFTER();
        if (elect1()) {
            #pragma unroll
            for (int s = 0; s < 32; s++) {
                const uint64_t pd = MK_DESC(sb + ((s < 16) ? SM_A : SM_B));
                const uint64_t vd = MK_DESC(sb + ((s < 16) ? SM_C : SM_D));
                const int sl = s & 15;
                uint64_t ad = pd + (uint64_t)(sl >> 2) * 1024 + (sl & 3) * 2;
                uint64_t bd = vd + (uint64_t)(sl >> 2) * 512  + (sl & 3) * 2;
                mma_f16_ss(tmem, ad, bd, IDESC_F16_N64, s > 0);
            }
            tc_commit(mbar2);
        }
    }
    mbar_wait(mbar2, 0);
    TC_FENCE_AFTER();

    float* sO = (float*)(base + SM_A);
    if (grp < 2) {
        const int colb = grp * 32;
        uint32_t r[32];
        TC_LD_X32(r, tmem + colb);
        TC_WAIT_LD();
        TC_FENCE_BEFORE();
        const float li = linv[row];
        #pragma unroll
        for (int t = 0; t < 32; t++)
            sO[(colb + t) * 132 + row] = __uint_as_float(r[t]) * li;
    }
    __syncthreads();
    for (int e = tid; e < 2048; e += 512) {
        const int d = e >> 5, i4 = (e & 31) * 4;
        float4 v = *(const float4*)(sO + d * 132 + i4);
        *(float4*)(gout + ((size_t)b * INNER + h * DHEAD + d) * NQ + i0 + i4) = v;
    }

    __syncthreads();
    if (tid == 0) { mbar_inval(mbar0); mbar_inval(mbar1); mbar_inval(mbar2); }
    __syncthreads();
    if (w == 0) tmem_dealloc(tmem, 512);
#endif  // __CUDA_ARCH_FEAT_SM103_ALL
}

// ---------------------------------------------------------------------------
extern "C" void kernel_launch(void* const* d_in, const int* in_sizes, int n_in,
                              void* d_out, int out_size)
{
    const float* x      = (const float*)d_in[0];
    const float* wq_dw  = (const float*)d_in[1];
    const float* bn_q_g = (const float*)d_in[2];
    const float* bn_q_b = (const float*)d_in[3];
    const float* bn_q_m = (const float*)d_in[4];
    const float* bn_q_v = (const float*)d_in[5];
    const float* wq_pw  = (const float*)d_in[6];
    const float* wkv_dw = (const float*)d_in[7];
    const float* bn_k_g = (const float*)d_in[8];
    const float* bn_k_b = (const float*)d_in[9];
    const float* bn_k_m = (const float*)d_in[10];
    const float* bn_k_v = (const float*)d_in[11];
    const float* wkv_pw = (const float*)d_in[12];
    const float* w_out  = (const float*)d_in[13];
    const float* b_out  = (const float*)d_in[14];
    float* out = (float*)d_out;

    float *p_qdw, *p_kvdw, *p_q, *p_kv, *p_att;
    cudaGetSymbolAddress((void**)&p_qdw,  g_qdw);
    cudaGetSymbolAddress((void**)&p_kvdw, g_kvdw);
    cudaGetSymbolAddress((void**)&p_q,    g_q);
    cudaGetSymbolAddress((void**)&p_kv,   g_kv);
    cudaGetSymbolAddress((void**)&p_att,  g_att);

    cudaFuncSetAttribute(attn_tc_kernel,
                         cudaFuncAttributeMaxDynamicSharedMemorySize, SM_REQ);
    cudaFuncSetAttribute(gemm_tc_kernel,
                         cudaFuncAttributeMaxDynamicSharedMemorySize, GM_REQ);

    // 1. depthwise convs + BN (fused)
    dw_bn_kernel<<<dim3(CDIM, BATCH), 256>>>(
        x, wq_dw, bn_q_g, bn_q_b, bn_q_m, bn_q_v,
        wkv_dw, bn_k_g, bn_k_b, bn_k_m, bn_k_v);

    // 2. pointwise q: (512 x 128) @ (128 x 4096) per batch  [tcgen05]
    gemm_tc_kernel<<<dim3(NQ / 128, INNER / 128, BATCH), 512, GM_REQ>>>(
        wq_pw, p_qdw, p_q, INNER, NQ, CDIM, nullptr);

    // 3. pointwise kv: (1024 x 128) @ (128 x 512) per batch  [tcgen05]
    gemm_tc_kernel<<<dim3(NK / 128, (2 * INNER) / 128, BATCH), 512, GM_REQ>>>(
        wkv_pw, p_kvdw, p_kv, 2 * INNER, NK, CDIM, nullptr);

    // 4. fused attention (tcgen05)
    attn_tc_kernel<<<dim3(NQ / 128, NHEADS, BATCH), 512, SM_REQ>>>(
        p_q, p_kv, p_att);

    // 5. out projection + bias: (128 x 512) @ (512 x 4096) per batch  [tcgen05]
    gemm_tc_kernel<<<dim3(NQ / 128, CDIM / 128, BATCH), 512, GM_REQ>>>(
        w_out, p_att, out, CDIM, NQ, INNER, b_out);
}

// round 10
// speedup vs baseline: 4.7787x; 1.0643x over previous
#include <cuda_runtime.h>
#include <cuda_bf16.h>
#include <cuda_fp16.h>
#include <math.h>
#include <stdint.h>

#define BATCH 4
#define CDIM 128
#define INNER 512
#define NQ 4096
#define NK 512
#define NHEADS 8
#define DHEAD 64

// ---------------- scratch (static device globals; allocation-free) ----------
__device__ float g_qdw[BATCH * CDIM * NQ];     // 8 MB   depthwise-q + BN
__device__ float g_kvdw[BATCH * CDIM * NK];    // 1 MB   depthwise-kv + BN
__device__ float g_q[BATCH * INNER * NQ];      // 32 MB  q after pointwise
__device__ float g_kv[BATCH * 2 * INNER * NK]; // 8 MB   kv after pointwise
__device__ float g_att[BATCH * INNER * NQ];    // 32 MB  attention output

// ---------------------------------------------------------------------------
// Kernel 1: both depthwise 3x3x3 convs (stride1 and stride2) + batchnorm.
// ---------------------------------------------------------------------------
__global__ __launch_bounds__(256) void dw_bn_kernel(
    const float* __restrict__ x,
    const float* __restrict__ wq,
    const float* __restrict__ qg, const float* __restrict__ qb,
    const float* __restrict__ qm, const float* __restrict__ qv,
    const float* __restrict__ wkv,
    const float* __restrict__ kg, const float* __restrict__ kb,
    const float* __restrict__ km, const float* __restrict__ kvvar)
{
    __shared__ float s[18 * 18 * 18];
    __shared__ float swq[27], swkv[27];
    const int c = blockIdx.x, b = blockIdx.y;
    const int tid = threadIdx.x;

    const float* xp = x + ((size_t)(b * CDIM + c)) * NQ;
    for (int idx = tid; idx < 5832; idx += 256) {
        int z = idx / 324; int r = idx - z * 324;
        int y = r / 18;    int xx = r - y * 18;
        z -= 1; y -= 1; xx -= 1;
        float v = 0.f;
        if ((unsigned)z < 16u && (unsigned)y < 16u && (unsigned)xx < 16u)
            v = xp[(z * 16 + y) * 16 + xx];
        s[idx] = v;
    }
    if (tid < 27) { swq[tid] = wq[c * 27 + tid]; swkv[tid] = wkv[c * 27 + tid]; }

    const float qscale = qg[c] * rsqrtf(qv[c] + 1e-5f);
    const float qshift = qb[c] - qm[c] * qscale;
    const float kscale = kg[c] * rsqrtf(kvvar[c] + 1e-5f);
    const float kshift = kb[c] - km[c] * kscale;
    __syncthreads();

    float* qo = g_qdw + ((size_t)(b * CDIM + c)) * NQ;
    for (int o = tid; o < 4096; o += 256) {
        const int z = o >> 8, y = (o >> 4) & 15, xx = o & 15;
        float sum = 0.f;
        #pragma unroll
        for (int dz = 0; dz < 3; dz++)
            #pragma unroll
            for (int dy = 0; dy < 3; dy++)
                #pragma unroll
                for (int dx = 0; dx < 3; dx++)
                    sum += swq[dz * 9 + dy * 3 + dx] *
                           s[(z + dz) * 324 + (y + dy) * 18 + (xx + dx)];
        qo[o] = sum * qscale + qshift;
    }

    float* ko = g_kvdw + ((size_t)(b * CDIM + c)) * NK;
    for (int o = tid; o < 512; o += 256) {
        const int z = o >> 6, y = (o >> 3) & 7, xx = o & 7;
        float sum = 0.f;
        #pragma unroll
        for (int dz = 0; dz < 3; dz++)
            #pragma unroll
            for (int dy = 0; dy < 3; dy++)
                #pragma unroll
                for (int dx = 0; dx < 3; dx++)
                    sum += swkv[dz * 9 + dy * 3 + dx] *
                           s[(2 * z + dz) * 324 + (2 * y + dy) * 18 + (2 * xx + dx)];
        ko[o] = sum * kscale + kshift;
    }
}

// ===========================================================================
// tcgen05 helpers
// ===========================================================================
__device__ __forceinline__ uint32_t s2u(const void* p) {
    uint32_t a;
    asm("{ .reg .u64 t; cvta.to.shared.u64 t, %1; cvt.u32.u64 %0, t; }"
        : "=r"(a) : "l"(p));
    return a;
}
__device__ __forceinline__ uint32_t elect1() {
    uint32_t pred;
    asm volatile("{\n\t.reg .pred p;\n\telect.sync _|p, 0xFFFFFFFF;\n\t"
                 "selp.b32 %0, 1, 0, p;\n\t}" : "=r"(pred));
    return pred;
}
__device__ __forceinline__ void mbar_init(uint32_t mbar, uint32_t cnt) {
    asm volatile("mbarrier.init.shared.b64 [%0], %1;" :: "r"(mbar), "r"(cnt) : "memory");
}
__device__ __forceinline__ void mbar_inval(uint32_t mbar) {
    asm volatile("mbarrier.inval.shared.b64 [%0];" :: "r"(mbar) : "memory");
}
__device__ __forceinline__ void mbar_wait(uint32_t mbar, uint32_t parity) {
    asm volatile(
        "{\n\t.reg .pred P1;\n\t"
        "WL%=:\n\t"
        "mbarrier.try_wait.parity.acquire.cta.shared::cta.b64 P1, [%0], %1, 0x989680;\n\t"
        "@P1 bra.uni WD%=;\n\t"
        "bra.uni WL%=;\n\t"
        "WD%=:\n\t}"
        :: "r"(mbar), "r"(parity) : "memory");
}
__device__ __forceinline__ void tmem_alloc(uint32_t smem_dst, uint32_t ncols) {
    asm volatile("tcgen05.alloc.cta_group::1.sync.aligned.shared::cta.b32 [%0], %1;"
                 :: "r"(smem_dst), "r"(ncols) : "memory");
}
__device__ __forceinline__ void tmem_dealloc(uint32_t tmem, uint32_t ncols) {
    asm volatile("tcgen05.relinquish_alloc_permit.cta_group::1.sync.aligned;");
    asm volatile("tcgen05.dealloc.cta_group::1.sync.aligned.b32 %0, %1;"
                 :: "r"(tmem), "r"(ncols));
}
__device__ __forceinline__ void mma_f16_ss(uint32_t d, uint64_t a, uint64_t b,
                                           uint32_t idesc, uint32_t en) {
    asm volatile(
        "{\n\t.reg .pred p;\n\tsetp.ne.u32 p, %5, 0;\n\t"
        "tcgen05.mma.cta_group::1.kind::f16 [%0], %1, %2, %3, {%4, %4, %4, %4}, p;\n\t}"
        :: "r"(d), "l"(a), "l"(b), "r"(idesc), "r"(0u), "r"(en) : "memory");
}
__device__ __forceinline__ void mma_f16_ts(uint32_t d, uint32_t a_tmem, uint64_t b,
                                           uint32_t idesc, uint32_t en) {
    asm volatile(
        "{\n\t.reg .pred p;\n\tsetp.ne.u32 p, %5, 0;\n\t"
        "tcgen05.mma.cta_group::1.kind::f16 [%0], [%1], %2, %3, {%4, %4, %4, %4}, p;\n\t}"
        :: "r"(d), "r"(a_tmem), "l"(b), "r"(idesc), "r"(0u), "r"(en) : "memory");
}
__device__ __forceinline__ void tc_commit(uint32_t mbar) {
    asm volatile(
        "tcgen05.commit.cta_group::1.mbarrier::arrive::one.shared::cluster.b64 [%0];"
        :: "r"(mbar) : "memory");
}
__device__ __forceinline__ float ex2f(float x) {
    float r;
    asm("ex2.approx.f32 %0, %1;" : "=f"(r) : "f"(x));
    return r;
}
#define TC_FENCE_AFTER()  asm volatile("tcgen05.fence::after_thread_sync;" ::: "memory")
#define TC_FENCE_BEFORE() asm volatile("tcgen05.fence::before_thread_sync;" ::: "memory")
#define TC_WAIT_LD()      asm volatile("tcgen05.wait::ld.sync.aligned;" ::: "memory")
#define TC_WAIT_ST()      asm volatile("tcgen05.wait::st.sync.aligned;" ::: "memory")
#define FENCE_ASYNC()     asm volatile("fence.proxy.async.shared::cta;" ::: "memory")

#define TC_LD_X32(r, addr) \
    asm volatile( \
        "tcgen05.ld.sync.aligned.32x32b.x32.b32 " \
        "{%0, %1, %2, %3, %4, %5, %6, %7, " \
        " %8, %9, %10, %11, %12, %13, %14, %15, " \
        " %16, %17, %18, %19, %20, %21, %22, %23, " \
        " %24, %25, %26, %27, %28, %29, %30, %31}, [%32];" \
        : "=r"((r)[0]),  "=r"((r)[1]),  "=r"((r)[2]),  "=r"((r)[3]), \
          "=r"((r)[4]),  "=r"((r)[5]),  "=r"((r)[6]),  "=r"((r)[7]), \
          "=r"((r)[8]),  "=r"((r)[9]),  "=r"((r)[10]), "=r"((r)[11]), \
          "=r"((r)[12]), "=r"((r)[13]), "=r"((r)[14]), "=r"((r)[15]), \
          "=r"((r)[16]), "=r"((r)[17]), "=r"((r)[18]), "=r"((r)[19]), \
          "=r"((r)[20]), "=r"((r)[21]), "=r"((r)[22]), "=r"((r)[23]), \
          "=r"((r)[24]), "=r"((r)[25]), "=r"((r)[26]), "=r"((r)[27]), \
          "=r"((r)[28]), "=r"((r)[29]), "=r"((r)[30]), "=r"((r)[31]) \
        : "r"(addr))

#define TC_ST_X64(addr, r) \
    asm volatile( \
        "tcgen05.st.sync.aligned.32x32b.x64.b32 [%0], " \
        "{%1, %2, %3, %4, %5, %6, %7, %8, " \
        " %9, %10, %11, %12, %13, %14, %15, %16, " \
        " %17, %18, %19, %20, %21, %22, %23, %24, " \
        " %25, %26, %27, %28, %29, %30, %31, %32, " \
        " %33, %34, %35, %36, %37, %38, %39, %40, " \
        " %41, %42, %43, %44, %45, %46, %47, %48, " \
        " %49, %50, %51, %52, %53, %54, %55, %56, " \
        " %57, %58, %59, %60, %61, %62, %63, %64};" \
        :: "r"(addr), \
           "r"((r)[0]),  "r"((r)[1]),  "r"((r)[2]),  "r"((r)[3]), \
           "r"((r)[4]),  "r"((r)[5]),  "r"((r)[6]),  "r"((r)[7]), \
           "r"((r)[8]),  "r"((r)[9]),  "r"((r)[10]), "r"((r)[11]), \
           "r"((r)[12]), "r"((r)[13]), "r"((r)[14]), "r"((r)[15]), \
           "r"((r)[16]), "r"((r)[17]), "r"((r)[18]), "r"((r)[19]), \
           "r"((r)[20]), "r"((r)[21]), "r"((r)[22]), "r"((r)[23]), \
           "r"((r)[24]), "r"((r)[25]), "r"((r)[26]), "r"((r)[27]), \
           "r"((r)[28]), "r"((r)[29]), "r"((r)[30]), "r"((r)[31]), \
           "r"((r)[32]), "r"((r)[33]), "r"((r)[34]), "r"((r)[35]), \
           "r"((r)[36]), "r"((r)[37]), "r"((r)[38]), "r"((r)[39]), \
           "r"((r)[40]), "r"((r)[41]), "r"((r)[42]), "r"((r)[43]), \
           "r"((r)[44]), "r"((r)[45]), "r"((r)[46]), "r"((r)[47]), \
           "r"((r)[48]), "r"((r)[49]), "r"((r)[50]), "r"((r)[51]), \
           "r"((r)[52]), "r"((r)[53]), "r"((r)[54]), "r"((r)[55]), \
           "r"((r)[56]), "r"((r)[57]), "r"((r)[58]), "r"((r)[59]), \
           "r"((r)[60]), "r"((r)[61]), "r"((r)[62]), "r"((r)[63]) \
        : "memory")

// SW128 smem descriptor base (layout=2, version=1, SBO=64, LBO=1)
#define DESC_BASE ((2ULL << 61) | (1ULL << 46) | (64ULL << 32) | (1ULL << 16))
#define MK_DESC(a) (DESC_BASE | ((uint64_t)((a) >> 4) & 0x3FFFULL))

__device__ __forceinline__ uint32_t sw128(uint32_t o) { return o ^ ((o >> 3) & 0x70); }
// rows x 64 elems (128B rows), SW128
__device__ __forceinline__ uint32_t qk_off(int r, int c) {
    return sw128((uint32_t)r * 128u + (uint32_t)c * 2u);
}
// 128 x 128 elems blocked-atom (16 atom-rows per atom-col), 2B elems
__device__ __forceinline__ uint32_t p_off(int i, int j) {
    uint32_t o = ((uint32_t)(i >> 3) + (uint32_t)(j >> 6) * 16u) * 1024u +
                 (uint32_t)(i & 7) * 128u + (uint32_t)(j & 63) * 2u;
    return sw128(o);
}
// 64 x 512 fp16 blocked-atom (8 atom-rows per atom-col)
__device__ __forceinline__ uint32_t v_off(int d, int j) {
    uint32_t o = ((uint32_t)(d >> 3) + (uint32_t)(j >> 6) * 8u) * 1024u +
                 (uint32_t)(d & 7) * 128u + (uint32_t)(j & 63) * 2u;
    return sw128(o);
}

// idesc: dtype F32 (1<<4); atype/btype: BF16=1, F16=0; M=128 (8<<24); N bits 17..22
#define IDESC_BF16_N(n) ((1u << 4) | (1u << 7) | (1u << 10) | (((n) / 8) << 17) | (8u << 24))
#define IDESC_F16_N(n)  ((1u << 4) | (((n) / 8) << 17) | (8u << 24))

// ===========================================================================
// Kernel 2: tcgen05 GEMM, bf16 hi/lo compensation on both operands (as R9).
// grid (N/128, M/128, BATCH), 512 threads.
// ===========================================================================
#define GM_MISC 0
#define GM_AH   1024
#define GM_AL   (GM_AH + 32768)
#define GM_BH   (GM_AL + 32768)
#define GM_BL   (GM_BH + 32768)
#define GM_REQ  (GM_BL + 32768 + 1024)

__global__ __launch_bounds__(512, 1)
void gemm_tc_kernel(const float* __restrict__ A, const float* __restrict__ Bm,
                    float* __restrict__ Cm, int M, int N, int K,
                    const float* __restrict__ bias)
{
#if defined(__CUDA_ARCH_FEAT_SM103_ALL)
    extern __shared__ char sm_raw[];
    char* base = (char*)(((uintptr_t)sm_raw + 1023) & ~(uintptr_t)1023);
    const uint32_t sb = s2u(base);

    const int tid = threadIdx.x, w = tid >> 5, lane = tid & 31;
    const int sub = w & 3, grp = w >> 2;
    const int row = sub * 32 + lane;
    const int n0 = blockIdx.x * 128, m0 = blockIdx.y * 128, bz = blockIdx.z;

    const uint32_t misc = sb + GM_MISC;
    const uint32_t mbar = misc + 8;
    if (w == 0) tmem_alloc(misc, 128);
    if (tid == 0) mbar_init(mbar, 1);
    __syncthreads();
    uint32_t tmem;
    asm volatile("ld.shared.b32 %0, [%1];" : "=r"(tmem) : "r"(misc));

    const float* Bp = Bm + (size_t)bz * K * N;
    float* Cp = Cm + (size_t)bz * M * N;
    const int nchunks = K >> 7;

    for (int kc = 0; kc < nchunks; kc++) {
        const int k0 = kc << 7;
        for (int g = tid; g < 2048; g += 512) {
            const int m = g >> 4, kg = (g & 15) * 8;
            const float* as = A + (size_t)(m0 + m) * K + k0 + kg;
            float4 a0 = *(const float4*)(as);
            float4 a1 = *(const float4*)(as + 4);
            float f[8] = {a0.x, a0.y, a0.z, a0.w, a1.x, a1.y, a1.z, a1.w};
            uint4 hi, lo;
            #pragma unroll
            for (int t = 0; t < 4; t++) {
                __nv_bfloat16 h0 = __float2bfloat16(f[2 * t]);
                __nv_bfloat16 h1 = __float2bfloat16(f[2 * t + 1]);
                __nv_bfloat162 hp; hp.x = h0; hp.y = h1;
                __nv_bfloat162 lp;
                lp.x = __float2bfloat16(f[2 * t] - __bfloat162float(h0));
                lp.y = __float2bfloat16(f[2 * t + 1] - __bfloat162float(h1));
                ((uint32_t*)&hi)[t] = *(uint32_t*)&hp;
                ((uint32_t*)&lo)[t] = *(uint32_t*)&lp;
            }
            const uint32_t off = p_off(m, kg);
            *(uint4*)(base + GM_AH + off) = hi;
            *(uint4*)(base + GM_AL + off) = lo;
        }
        for (int g = tid; g < 2048; g += 512) {
            const int n = g & 127, kg = (g >> 7) * 8;
            const float* bs = Bp + (size_t)(k0 + kg) * N + n0 + n;
            float f[8];
            #pragma unroll
            for (int j = 0; j < 8; j++) f[j] = bs[(size_t)j * N];
            uint4 hi, lo;
            #pragma unroll
            for (int t = 0; t < 4; t++) {
                __nv_bfloat16 h0 = __float2bfloat16(f[2 * t]);
                __nv_bfloat16 h1 = __float2bfloat16(f[2 * t + 1]);
                __nv_bfloat162 hp; hp.x = h0; hp.y = h1;
                __nv_bfloat162 lp;
                lp.x = __float2bfloat16(f[2 * t] - __bfloat162float(h0));
                lp.y = __float2bfloat16(f[2 * t + 1] - __bfloat162float(h1));
                ((uint32_t*)&hi)[t] = *(uint32_t*)&hp;
                ((uint32_t*)&lo)[t] = *(uint32_t*)&lp;
            }
            const uint32_t off = p_off(n, kg);
            *(uint4*)(base + GM_BH + off) = hi;
            *(uint4*)(base + GM_BL + off) = lo;
        }
        FENCE_ASYNC();
        __syncthreads();

        if (w == 0) {
            TC_FENCE_AFTER();
            const uint64_t ah = MK_DESC(sb + GM_AH);
            const uint64_t al = MK_DESC(sb + GM_AL);
            const uint64_t bh = MK_DESC(sb + GM_BH);
            const uint64_t bl = MK_DESC(sb + GM_BL);
            const uint32_t id = IDESC_BF16_N(128);
            if (elect1()) {
                #pragma unroll
                for (int t = 0; t < 3; t++) {
                    const uint64_t ad0 = (t == 1) ? al : ah;
                    const uint64_t bd0 = (t == 2) ? bl : bh;
                    #pragma unroll
                    for (int s = 0; s < 8; s++) {
                        uint64_t doff = (uint64_t)(s >> 2) * 1024 + (s & 3) * 2;
                        mma_f16_ss(tmem, ad0 + doff, bd0 + doff, id,
                                   !(kc == 0 && t == 0 && s == 0));
                    }
                }
                tc_commit(mbar);
            }
        }
        mbar_wait(mbar, kc & 1);
    }
    TC_FENCE_AFTER();

    {
        uint32_t r[32];
        TC_LD_X32(r, tmem + grp * 32);
        TC_WAIT_LD();
        TC_FENCE_BEFORE();
        const float bb = bias ? bias[m0 + row] : 0.f;
        float* cp = Cp + (size_t)(m0 + row) * N + n0 + grp * 32;
        float4 v;
        #pragma unroll
        for (int t = 0; t < 32; t += 4) {
            v = make_float4(__uint_as_float(r[t]) + bb,
                            __uint_as_float(r[t + 1]) + bb,
                            __uint_as_float(r[t + 2]) + bb,
                            __uint_as_float(r[t + 3]) + bb);
            *(float4*)(cp + t) = v;
        }
    }

    __syncthreads();
    if (tid == 0) mbar_inval(mbar);
    __syncthreads();
    if (w == 0) tmem_dealloc(tmem, 128);
#endif
}

// smem regions for attention (relative to 1024-aligned base)
#define SM_MISC 0
#define SM_Q    4096                 // 16 KB: Q fp16 [128 i][64 d]
#define SM_K    (SM_Q + 16384)       // 64 KB: K fp16 [512 j][64 d]   -> sO stage
#define SM_V    (SM_K + 65536)       // 64 KB: V fp16 [64 d][512 j] blocked-atom
#define SM_REQ  (SM_V + 65536 + 1024)

// ===========================================================================
// Kernel 3: tcgen05 fused attention, all-fp16 operands, P staged in TMEM.
// TMEM map: cols 0-511 dots (fp32) -> cols 0-255 P (fp16x2) ; D at 256-319.
// One CTA = (b, h, 128 q rows). grid (32, 8, 4), 512 threads.
// ===========================================================================
__global__ __launch_bounds__(512, 1)
void attn_tc_kernel(const float* __restrict__ gq,
                    const float* __restrict__ gkv,
                    float* __restrict__ gout)
{
#if defined(__CUDA_ARCH_FEAT_SM103_ALL)
    extern __shared__ char sm_raw[];
    char* base = (char*)(((uintptr_t)sm_raw + 1023) & ~(uintptr_t)1023);
    const uint32_t sb = s2u(base);

    const int tid = threadIdx.x, w = tid >> 5, lane = tid & 31;
    const int sub = w & 3, grp = w >> 2;     // subpartition / 128-col quarter
    const int row = sub * 32 + lane;         // q row owned in TMEM
    const int i0 = blockIdx.x * 128;
    const int h  = blockIdx.y;
    const int b  = blockIdx.z;

    const uint32_t misc  = sb + SM_MISC;
    const uint32_t mbar0 = misc + 8;
    const uint32_t mbar1 = misc + 16;
    const uint32_t mbar2 = misc + 24;
    float* sRow = (float*)(base + SM_MISC + 1024);   // [4][128]
    float* linv = (float*)(base + SM_MISC + 3072);   // [128]

    if (w == 0) tmem_alloc(misc, 512);
    if (tid == 0) { mbar_init(mbar0, 1); mbar_init(mbar1, 1); mbar_init(mbar2, 1); }
    __syncthreads();
    uint32_t tmem;
    asm volatile("ld.shared.b32 %0, [%1];" : "=r"(tmem) : "r"(misc));

    const float* qbase = gq  + ((size_t)b * INNER + h * DHEAD) * NQ + i0;
    const float* kbase = gkv + ((size_t)b * 2 * INNER + h * DHEAD) * NK;
    const float* vbase = kbase + (size_t)INNER * NK;

    // softmax base-2 trick: scale = 1/sqrt(64) * log2(e)
    const float QSCALE = 0.125f * 1.44269504088896341f;

    // ---- load Q fp16 (transpose [d][i]->[i][d], scaled) ----
    for (int g = tid; g < 1024; g += 512) {
        const int i = g & 127, d0 = (g >> 7) * 8;
        float f[8];
        #pragma unroll
        for (int k = 0; k < 8; k++)
            f[k] = qbase[(size_t)(d0 + k) * NQ + i] * QSCALE;
        uint4 pk;
        #pragma unroll
        for (int t = 0; t < 4; t++) {
            __half2 h2 = __floats2half2_rn(f[2 * t], f[2 * t + 1]);
            ((uint32_t*)&pk)[t] = *(uint32_t*)&h2;
        }
        *(uint4*)(base + SM_Q + qk_off(i, d0)) = pk;
    }
    // ---- load K fp16 (transpose [d][j]->[j][d]) ----
    for (int g = tid; g < 4096; g += 512) {
        const int j = g & 511, d0 = (g >> 9) * 8;
        float f[8];
        #pragma unroll
        for (int k = 0; k < 8; k++)
            f[k] = kbase[(size_t)(d0 + k) * NK + j];
        uint4 pk;
        #pragma unroll
        for (int t = 0; t < 4; t++) {
            __half2 h2 = __floats2half2_rn(f[2 * t], f[2 * t + 1]);
            ((uint32_t*)&pk)[t] = *(uint32_t*)&h2;
        }
        *(uint4*)(base + SM_K + qk_off(j, d0)) = pk;
    }
    FENCE_ASYNC();
    __syncthreads();

    // ---- MMA1: dots = Q K^T, fp16, two N=256 chunks (4 K-steps each) ----
    if (w == 0) {
        const uint64_t qd = MK_DESC(sb + SM_Q);
        const uint32_t id1 = IDESC_F16_N(256);
        if (elect1()) {
            #pragma unroll
            for (int c = 0; c < 2; c++) {
                const uint32_t dst = tmem + c * 256;
                const uint64_t kd = MK_DESC(sb + SM_K + c * 32768);
                #pragma unroll
                for (int s = 0; s < 4; s++)
                    mma_f16_ss(dst, qd + s * 2, kd + s * 2, id1, s > 0);
                tc_commit(c ? mbar1 : mbar0);
            }
        }
    }

    // ---- load V fp16 [d][j] blocked-atom (overlaps MMA1) ----
    for (int g = tid; g < 4096; g += 512) {
        const int d = g >> 6, j8 = (g & 63) * 8;
        const float* vs = vbase + (size_t)d * NK + j8;
        float4 v0 = *(const float4*)(vs);
        float4 v1 = *(const float4*)(vs + 4);
        uint4 pk;
        ((__half2*)&pk)[0] = __floats2half2_rn(v0.x, v0.y);
        ((__half2*)&pk)[1] = __floats2half2_rn(v0.z, v0.w);
        ((__half2*)&pk)[2] = __floats2half2_rn(v1.x, v1.y);
        ((__half2*)&pk)[3] = __floats2half2_rn(v1.z, v1.w);
        *(uint4*)(base + SM_V + v_off(d, j8)) = pk;
    }
    FENCE_ASYNC();

    // ---- LDTM dots + exp2 + row-sum -> 64 packed fp16x2 regs ----
    mbar_wait(grp < 2 ? mbar0 : mbar1, 0);
    TC_FENCE_AFTER();
    uint32_t pk[64];
    {
        float rsum = 0.f;
        #pragma unroll
        for (int c8 = 0; c8 < 4; c8++) {
            uint32_t r[32];
            TC_LD_X32(r, tmem + grp * 128 + c8 * 32);
            TC_WAIT_LD();
            #pragma unroll
            for (int t = 0; t < 16; t++) {
                float e0 = ex2f(__uint_as_float(r[2 * t]));
                float e1 = ex2f(__uint_as_float(r[2 * t + 1]));
                rsum += e0 + e1;
                __half2 h2 = __floats2half2_rn(e0, e1);
                pk[c8 * 16 + t] = *(uint32_t*)&h2;
            }
        }
        sRow[grp * 128 + row] = rsum;
    }
    __syncthreads();   // ALL dots consumed before any P overwrites them

    // ---- STTM P (fp16x2) into TMEM cols [64*grp, 64*grp+64) ----
    TC_ST_X64(tmem + grp * 64, pk);
    TC_WAIT_ST();
    if (tid < 128)
        linv[tid] = 1.f / (sRow[tid] + sRow[128 + tid] +
                           sRow[256 + tid] + sRow[384 + tid]);
    TC_FENCE_BEFORE();
    __syncthreads();

    // ---- MMA2 (TS): D = P(tmem) @ V^T, K=512 (32 steps), D at cols 256 ----
    if (w == 0) {
        TC_FENCE_AFTER();
        const uint64_t vd = MK_DESC(sb + SM_V);
        const uint32_t id2 = IDESC_F16_N(64);
        if (elect1()) {
            #pragma unroll
            for (int s = 0; s < 32; s++) {
                uint64_t bd = vd + (uint64_t)(s >> 2) * 512 + (s & 3) * 2;
                mma_f16_ts(tmem + 256, tmem + s * 8, bd, id2, s > 0);
            }
            tc_commit(mbar2);
        }
    }
    mbar_wait(mbar2, 0);
    TC_FENCE_AFTER();

    // ---- epilogue: scale by 1/l, stage sO[d][i] in SM_K, coalesced store ----
    float* sO = (float*)(base + SM_K);       // [64][132] floats
    if (grp < 2) {
        const int colb = grp * 32;
        uint32_t r[32];
        TC_LD_X32(r, tmem + 256 + colb);
        TC_WAIT_LD();
        TC_FENCE_BEFORE();
        const float li = linv[row];
        #pragma unroll
        for (int t = 0; t < 32; t++)
            sO[(colb + t) * 132 + row] = __uint_as_float(r[t]) * li;
    }
    __syncthreads();
    for (int e = tid; e < 2048; e += 512) {
        const int d = e >> 5, i4 = (e & 31) * 4;
        float4 v = *(const float4*)(sO + d * 132 + i4);
        *(float4*)(gout + ((size_t)b * INNER + h * DHEAD + d) * NQ + i0 + i4) = v;
    }

    __syncthreads();
    if (tid == 0) { mbar_inval(mbar0); mbar_inval(mbar1); mbar_inval(mbar2); }
    __syncthreads();
    if (w == 0) tmem_dealloc(tmem, 512);
#endif  // __CUDA_ARCH_FEAT_SM103_ALL
}

// ---------------------------------------------------------------------------
extern "C" void kernel_launch(void* const* d_in, const int* in_sizes, int n_in,
                              void* d_out, int out_size)
{
    const float* x      = (const float*)d_in[0];
    const float* wq_dw  = (const float*)d_in[1];
    const float* bn_q_g = (const float*)d_in[2];
    const float* bn_q_b = (const float*)d_in[3];
    const float* bn_q_m = (const float*)d_in[4];
    const float* bn_q_v = (const float*)d_in[5];
    const float* wq_pw  = (const float*)d_in[6];
    const float* wkv_dw = (const float*)d_in[7];
    const float* bn_k_g = (const float*)d_in[8];
    const float* bn_k_b = (const float*)d_in[9];
    const float* bn_k_m = (const float*)d_in[10];
    const float* bn_k_v = (const float*)d_in[11];
    const float* wkv_pw = (const float*)d_in[12];
    const float* w_out  = (const float*)d_in[13];
    const float* b_out  = (const float*)d_in[14];
    float* out = (float*)d_out;

    float *p_qdw, *p_kvdw, *p_q, *p_kv, *p_att;
    cudaGetSymbolAddress((void**)&p_qdw,  g_qdw);
    cudaGetSymbolAddress((void**)&p_kvdw, g_kvdw);
    cudaGetSymbolAddress((void**)&p_q,    g_q);
    cudaGetSymbolAddress((void**)&p_kv,   g_kv);
    cudaGetSymbolAddress((void**)&p_att,  g_att);

    cudaFuncSetAttribute(attn_tc_kernel,
                         cudaFuncAttributeMaxDynamicSharedMemorySize, SM_REQ);
    cudaFuncSetAttribute(gemm_tc_kernel,
                         cudaFuncAttributeMaxDynamicSharedMemorySize, GM_REQ);

    // 1. depthwise convs + BN (fused)
    dw_bn_kernel<<<dim3(CDIM, BATCH), 256>>>(
        x, wq_dw, bn_q_g, bn_q_b, bn_q_m, bn_q_v,
        wkv_dw, bn_k_g, bn_k_b, bn_k_m, bn_k_v);

    // 2. pointwise q: (512 x 128) @ (128 x 4096) per batch  [tcgen05]
    gemm_tc_kernel<<<dim3(NQ / 128, INNER / 128, BATCH), 512, GM_REQ>>>(
        wq_pw, p_qdw, p_q, INNER, NQ, CDIM, nullptr);

    // 3. pointwise kv: (1024 x 128) @ (128 x 512) per batch  [tcgen05]
    gemm_tc_kernel<<<dim3(NK / 128, (2 * INNER) / 128, BATCH), 512, GM_REQ>>>(
        wkv_pw, p_kvdw, p_kv, 2 * INNER, NK, CDIM, nullptr);

    // 4. fused attention (tcgen05, all-fp16, P in TMEM)
    attn_tc_kernel<<<dim3(NQ / 128, NHEADS, BATCH), 512, SM_REQ>>>(
        p_q, p_kv, p_att);

    // 5. out projection + bias: (128 x 512) @ (512 x 4096) per batch  [tcgen05]
    gemm_tc_kernel<<<dim3(NQ / 128, CDIM / 128, BATCH), 512, GM_REQ>>>(
        w_out, p_att, out, CDIM, NQ, INNER, b_out);
}

// round 11
// speedup vs baseline: 5.1405x; 1.0757x over previous
#include <cuda_runtime.h>
#include <cuda_bf16.h>
#include <cuda_fp16.h>
#include <math.h>
#include <stdint.h>

#define BATCH 4
#define CDIM 128
#define INNER 512
#define NQ 4096
#define NK 512
#define NHEADS 8
#define DHEAD 64

// ---------------- scratch (static device globals; allocation-free) ----------
__device__ float g_qdw[BATCH * CDIM * NQ];     // 8 MB   depthwise-q + BN
__device__ float g_kvdw[BATCH * CDIM * NK];    // 1 MB   depthwise-kv + BN
__device__ float g_q[BATCH * INNER * NQ];      // 32 MB  q after pointwise
__device__ float g_kv[BATCH * 2 * INNER * NK]; // 8 MB   kv after pointwise
__device__ float g_att[BATCH * INNER * NQ];    // 32 MB  attention output

// ---------------------------------------------------------------------------
// Kernel 1: both depthwise 3x3x3 convs (stride1 and stride2) + batchnorm.
// ---------------------------------------------------------------------------
__global__ __launch_bounds__(256) void dw_bn_kernel(
    const float* __restrict__ x,
    const float* __restrict__ wq,
    const float* __restrict__ qg, const float* __restrict__ qb,
    const float* __restrict__ qm, const float* __restrict__ qv,
    const float* __restrict__ wkv,
    const float* __restrict__ kg, const float* __restrict__ kb,
    const float* __restrict__ km, const float* __restrict__ kvvar)
{
    __shared__ float s[18 * 18 * 18];
    __shared__ float swq[27], swkv[27];
    const int c = blockIdx.x, b = blockIdx.y;
    const int tid = threadIdx.x;

    const float* xp = x + ((size_t)(b * CDIM + c)) * NQ;
    for (int idx = tid; idx < 5832; idx += 256) {
        int z = idx / 324; int r = idx - z * 324;
        int y = r / 18;    int xx = r - y * 18;
        z -= 1; y -= 1; xx -= 1;
        float v = 0.f;
        if ((unsigned)z < 16u && (unsigned)y < 16u && (unsigned)xx < 16u)
            v = xp[(z * 16 + y) * 16 + xx];
        s[idx] = v;
    }
    if (tid < 27) { swq[tid] = wq[c * 27 + tid]; swkv[tid] = wkv[c * 27 + tid]; }

    const float qscale = qg[c] * rsqrtf(qv[c] + 1e-5f);
    const float qshift = qb[c] - qm[c] * qscale;
    const float kscale = kg[c] * rsqrtf(kvvar[c] + 1e-5f);
    const float kshift = kb[c] - km[c] * kscale;
    __syncthreads();

    float* qo = g_qdw + ((size_t)(b * CDIM + c)) * NQ;
    for (int o = tid; o < 4096; o += 256) {
        const int z = o >> 8, y = (o >> 4) & 15, xx = o & 15;
        float sum = 0.f;
        #pragma unroll
        for (int dz = 0; dz < 3; dz++)
            #pragma unroll
            for (int dy = 0; dy < 3; dy++)
                #pragma unroll
                for (int dx = 0; dx < 3; dx++)
                    sum += swq[dz * 9 + dy * 3 + dx] *
                           s[(z + dz) * 324 + (y + dy) * 18 + (xx + dx)];
        qo[o] = sum * qscale + qshift;
    }

    float* ko = g_kvdw + ((size_t)(b * CDIM + c)) * NK;
    for (int o = tid; o < 512; o += 256) {
        const int z = o >> 6, y = (o >> 3) & 7, xx = o & 7;
        float sum = 0.f;
        #pragma unroll
        for (int dz = 0; dz < 3; dz++)
            #pragma unroll
            for (int dy = 0; dy < 3; dy++)
                #pragma unroll
                for (int dx = 0; dx < 3; dx++)
                    sum += swkv[dz * 9 + dy * 3 + dx] *
                           s[(2 * z + dz) * 324 + (2 * y + dy) * 18 + (2 * xx + dx)];
        ko[o] = sum * kscale + kshift;
    }
}

// ===========================================================================
// tcgen05 helpers
// ===========================================================================
__device__ __forceinline__ uint32_t s2u(const void* p) {
    uint32_t a;
    asm("{ .reg .u64 t; cvta.to.shared.u64 t, %1; cvt.u32.u64 %0, t; }"
        : "=r"(a) : "l"(p));
    return a;
}
__device__ __forceinline__ uint32_t elect1() {
    uint32_t pred;
    asm volatile("{\n\t.reg .pred p;\n\telect.sync _|p, 0xFFFFFFFF;\n\t"
                 "selp.b32 %0, 1, 0, p;\n\t}" : "=r"(pred));
    return pred;
}
__device__ __forceinline__ void mbar_init(uint32_t mbar, uint32_t cnt) {
    asm volatile("mbarrier.init.shared.b64 [%0], %1;" :: "r"(mbar), "r"(cnt) : "memory");
}
__device__ __forceinline__ void mbar_inval(uint32_t mbar) {
    asm volatile("mbarrier.inval.shared.b64 [%0];" :: "r"(mbar) : "memory");
}
__device__ __forceinline__ void mbar_wait(uint32_t mbar, uint32_t parity) {
    asm volatile(
        "{\n\t.reg .pred P1;\n\t"
        "WL%=:\n\t"
        "mbarrier.try_wait.parity.acquire.cta.shared::cta.b64 P1, [%0], %1, 0x989680;\n\t"
        "@P1 bra.uni WD%=;\n\t"
        "bra.uni WL%=;\n\t"
        "WD%=:\n\t}"
        :: "r"(mbar), "r"(parity) : "memory");
}
__device__ __forceinline__ void tmem_alloc(uint32_t smem_dst, uint32_t ncols) {
    asm volatile("tcgen05.alloc.cta_group::1.sync.aligned.shared::cta.b32 [%0], %1;"
                 :: "r"(smem_dst), "r"(ncols) : "memory");
}
__device__ __forceinline__ void tmem_dealloc(uint32_t tmem, uint32_t ncols) {
    asm volatile("tcgen05.relinquish_alloc_permit.cta_group::1.sync.aligned;");
    asm volatile("tcgen05.dealloc.cta_group::1.sync.aligned.b32 %0, %1;"
                 :: "r"(tmem), "r"(ncols));
}
__device__ __forceinline__ void mma_f16_ss(uint32_t d, uint64_t a, uint64_t b,
                                           uint32_t idesc, uint32_t en) {
    asm volatile(
        "{\n\t.reg .pred p;\n\tsetp.ne.u32 p, %5, 0;\n\t"
        "tcgen05.mma.cta_group::1.kind::f16 [%0], %1, %2, %3, {%4, %4, %4, %4}, p;\n\t}"
        :: "r"(d), "l"(a), "l"(b), "r"(idesc), "r"(0u), "r"(en) : "memory");
}
__device__ __forceinline__ void mma_f16_ts(uint32_t d, uint32_t a_tmem, uint64_t b,
                                           uint32_t idesc, uint32_t en) {
    asm volatile(
        "{\n\t.reg .pred p;\n\tsetp.ne.u32 p, %5, 0;\n\t"
        "tcgen05.mma.cta_group::1.kind::f16 [%0], [%1], %2, %3, {%4, %4, %4, %4}, p;\n\t}"
        :: "r"(d), "r"(a_tmem), "l"(b), "r"(idesc), "r"(0u), "r"(en) : "memory");
}
__device__ __forceinline__ void tc_commit(uint32_t mbar) {
    asm volatile(
        "tcgen05.commit.cta_group::1.mbarrier::arrive::one.shared::cluster.b64 [%0];"
        :: "r"(mbar) : "memory");
}
__device__ __forceinline__ float ex2f(float x) {
    float r;
    asm("ex2.approx.f32 %0, %1;" : "=f"(r) : "f"(x));
    return r;
}
#define TC_FENCE_AFTER()  asm volatile("tcgen05.fence::after_thread_sync;" ::: "memory")
#define TC_FENCE_BEFORE() asm volatile("tcgen05.fence::before_thread_sync;" ::: "memory")
#define TC_WAIT_LD()      asm volatile("tcgen05.wait::ld.sync.aligned;" ::: "memory")
#define TC_WAIT_ST()      asm volatile("tcgen05.wait::st.sync.aligned;" ::: "memory")
#define FENCE_ASYNC()     asm volatile("fence.proxy.async.shared::cta;" ::: "memory")

#define TC_LD_X32(r, addr) \
    asm volatile( \
        "tcgen05.ld.sync.aligned.32x32b.x32.b32 " \
        "{%0, %1, %2, %3, %4, %5, %6, %7, " \
        " %8, %9, %10, %11, %12, %13, %14, %15, " \
        " %16, %17, %18, %19, %20, %21, %22, %23, " \
        " %24, %25, %26, %27, %28, %29, %30, %31}, [%32];" \
        : "=r"((r)[0]),  "=r"((r)[1]),  "=r"((r)[2]),  "=r"((r)[3]), \
          "=r"((r)[4]),  "=r"((r)[5]),  "=r"((r)[6]),  "=r"((r)[7]), \
          "=r"((r)[8]),  "=r"((r)[9]),  "=r"((r)[10]), "=r"((r)[11]), \
          "=r"((r)[12]), "=r"((r)[13]), "=r"((r)[14]), "=r"((r)[15]), \
          "=r"((r)[16]), "=r"((r)[17]), "=r"((r)[18]), "=r"((r)[19]), \
          "=r"((r)[20]), "=r"((r)[21]), "=r"((r)[22]), "=r"((r)[23]), \
          "=r"((r)[24]), "=r"((r)[25]), "=r"((r)[26]), "=r"((r)[27]), \
          "=r"((r)[28]), "=r"((r)[29]), "=r"((r)[30]), "=r"((r)[31]) \
        : "r"(addr))

#define TC_ST_X64(addr, r) \
    asm volatile( \
        "tcgen05.st.sync.aligned.32x32b.x64.b32 [%0], " \
        "{%1, %2, %3, %4, %5, %6, %7, %8, " \
        " %9, %10, %11, %12, %13, %14, %15, %16, " \
        " %17, %18, %19, %20, %21, %22, %23, %24, " \
        " %25, %26, %27, %28, %29, %30, %31, %32, " \
        " %33, %34, %35, %36, %37, %38, %39, %40, " \
        " %41, %42, %43, %44, %45, %46, %47, %48, " \
        " %49, %50, %51, %52, %53, %54, %55, %56, " \
        " %57, %58, %59, %60, %61, %62, %63, %64};" \
        :: "r"(addr), \
           "r"((r)[0]),  "r"((r)[1]),  "r"((r)[2]),  "r"((r)[3]), \
           "r"((r)[4]),  "r"((r)[5]),  "r"((r)[6]),  "r"((r)[7]), \
           "r"((r)[8]),  "r"((r)[9]),  "r"((r)[10]), "r"((r)[11]), \
           "r"((r)[12]), "r"((r)[13]), "r"((r)[14]), "r"((r)[15]), \
           "r"((r)[16]), "r"((r)[17]), "r"((r)[18]), "r"((r)[19]), \
           "r"((r)[20]), "r"((r)[21]), "r"((r)[22]), "r"((r)[23]), \
           "r"((r)[24]), "r"((r)[25]), "r"((r)[26]), "r"((r)[27]), \
           "r"((r)[28]), "r"((r)[29]), "r"((r)[30]), "r"((r)[31]), \
           "r"((r)[32]), "r"((r)[33]), "r"((r)[34]), "r"((r)[35]), \
           "r"((r)[36]), "r"((r)[37]), "r"((r)[38]), "r"((r)[39]), \
           "r"((r)[40]), "r"((r)[41]), "r"((r)[42]), "r"((r)[43]), \
           "r"((r)[44]), "r"((r)[45]), "r"((r)[46]), "r"((r)[47]), \
           "r"((r)[48]), "r"((r)[49]), "r"((r)[50]), "r"((r)[51]), \
           "r"((r)[52]), "r"((r)[53]), "r"((r)[54]), "r"((r)[55]), \
           "r"((r)[56]), "r"((r)[57]), "r"((r)[58]), "r"((r)[59]), \
           "r"((r)[60]), "r"((r)[61]), "r"((r)[62]), "r"((r)[63]) \
        : "memory")

// SW128 smem descriptor base (layout=2, version=1, SBO=64, LBO=1)
#define DESC_BASE ((2ULL << 61) | (1ULL << 46) | (64ULL << 32) | (1ULL << 16))
#define MK_DESC(a) (DESC_BASE | ((uint64_t)((a) >> 4) & 0x3FFFULL))

__device__ __forceinline__ uint32_t sw128(uint32_t o) { return o ^ ((o >> 3) & 0x70); }
// rows x 64 elems (128B rows), SW128
__device__ __forceinline__ uint32_t qk_off(int r, int c) {
    return sw128((uint32_t)r * 128u + (uint32_t)c * 2u);
}
// 128 x (64*ac) 2B elems, blocked-atom, 16 atom-rows per atom-col
__device__ __forceinline__ uint32_t p_off(int i, int j) {
    uint32_t o = ((uint32_t)(i >> 3) + (uint32_t)(j >> 6) * 16u) * 1024u +
                 (uint32_t)(i & 7) * 128u + (uint32_t)(j & 63) * 2u;
    return sw128(o);
}
// 64 x 512 fp16 blocked-atom (8 atom-rows per atom-col)
__device__ __forceinline__ uint32_t v_off(int d, int j) {
    uint32_t o = ((uint32_t)(d >> 3) + (uint32_t)(j >> 6) * 8u) * 1024u +
                 (uint32_t)(d & 7) * 128u + (uint32_t)(j & 63) * 2u;
    return sw128(o);
}

// idesc: dtype F32 (1<<4); atype/btype: BF16=1, F16=0; M=128 (8<<24); N bits 17..22
#define IDESC_F16_N(n)  ((1u << 4) | (((n) / 8) << 17) | (8u << 24))

// ===========================================================================
// Kernel 2: tcgen05 GEMM, plain fp16 operands (single term). 66 KB smem ->
// 3 CTAs/SM. grid (N/128, M/128, BATCH), 512 threads.
// ===========================================================================
#define GM_MISC 0
#define GM_A    1024
#define GM_B    (GM_A + 32768)
#define GM_REQ  (GM_B + 32768 + 1024)

__global__ __launch_bounds__(512, 1)
void gemm_tc_kernel(const float* __restrict__ A, const float* __restrict__ Bm,
                    float* __restrict__ Cm, int M, int N, int K,
                    const float* __restrict__ bias)
{
#if defined(__CUDA_ARCH_FEAT_SM103_ALL)
    extern __shared__ char sm_raw[];
    char* base = (char*)(((uintptr_t)sm_raw + 1023) & ~(uintptr_t)1023);
    const uint32_t sb = s2u(base);

    const int tid = threadIdx.x, w = tid >> 5, lane = tid & 31;
    const int sub = w & 3, grp = w >> 2;
    const int row = sub * 32 + lane;
    const int n0 = blockIdx.x * 128, m0 = blockIdx.y * 128, bz = blockIdx.z;

    const uint32_t misc = sb + GM_MISC;
    const uint32_t mbar = misc + 8;
    if (w == 0) tmem_alloc(misc, 128);
    if (tid == 0) mbar_init(mbar, 1);
    __syncthreads();
    uint32_t tmem;
    asm volatile("ld.shared.b32 %0, [%1];" : "=r"(tmem) : "r"(misc));

    const float* Bp = Bm + (size_t)bz * K * N;
    float* Cp = Cm + (size_t)bz * M * N;
    const int nchunks = K >> 7;

    for (int kc = 0; kc < nchunks; kc++) {
        const int k0 = kc << 7;
        // ---- load A tile [128 m][128 k] fp16, blocked-atom ----
        for (int g = tid; g < 2048; g += 512) {
            const int m = g >> 4, kg = (g & 15) * 8;
            const float* as = A + (size_t)(m0 + m) * K + k0 + kg;
            float4 a0 = *(const float4*)(as);
            float4 a1 = *(const float4*)(as + 4);
            uint4 pk;
            ((__half2*)&pk)[0] = __floats2half2_rn(a0.x, a0.y);
            ((__half2*)&pk)[1] = __floats2half2_rn(a0.z, a0.w);
            ((__half2*)&pk)[2] = __floats2half2_rn(a1.x, a1.y);
            ((__half2*)&pk)[3] = __floats2half2_rn(a1.z, a1.w);
            *(uint4*)(base + GM_A + p_off(m, kg)) = pk;
        }
        // ---- load B tile transposed: Bs[n][k] = B[k0+k][n0+n], fp16 ----
        for (int g = tid; g < 2048; g += 512) {
            const int n = g & 127, kg = (g >> 7) * 8;
            const float* bs = Bp + (size_t)(k0 + kg) * N + n0 + n;
            float f[8];
            #pragma unroll
            for (int j = 0; j < 8; j++) f[j] = bs[(size_t)j * N];
            uint4 pk;
            #pragma unroll
            for (int t = 0; t < 4; t++) {
                __half2 h2 = __floats2half2_rn(f[2 * t], f[2 * t + 1]);
                ((uint32_t*)&pk)[t] = *(uint32_t*)&h2;
            }
            *(uint4*)(base + GM_B + p_off(n, kg)) = pk;
        }
        FENCE_ASYNC();
        __syncthreads();

        // ---- single-term fp16 MMA over this K-chunk (8 k-steps) ----
        if (w == 0) {
            TC_FENCE_AFTER();
            const uint64_t ad = MK_DESC(sb + GM_A);
            const uint64_t bd = MK_DESC(sb + GM_B);
            const uint32_t id = IDESC_F16_N(128);
            if (elect1()) {
                #pragma unroll
                for (int s = 0; s < 8; s++) {
                    uint64_t doff = (uint64_t)(s >> 2) * 1024 + (s & 3) * 2;
                    mma_f16_ss(tmem, ad + doff, bd + doff, id, !(kc == 0 && s == 0));
                }
                tc_commit(mbar);
            }
        }
        mbar_wait(mbar, kc & 1);
    }
    TC_FENCE_AFTER();

    // ---- epilogue: LDTM 32 cols per warp-group, (+bias), direct store ----
    {
        uint32_t r[32];
        TC_LD_X32(r, tmem + grp * 32);
        TC_WAIT_LD();
        TC_FENCE_BEFORE();
        const float bb = bias ? bias[m0 + row] : 0.f;
        float* cp = Cp + (size_t)(m0 + row) * N + n0 + grp * 32;
        float4 v;
        #pragma unroll
        for (int t = 0; t < 32; t += 4) {
            v = make_float4(__uint_as_float(r[t]) + bb,
                            __uint_as_float(r[t + 1]) + bb,
                            __uint_as_float(r[t + 2]) + bb,
                            __uint_as_float(r[t + 3]) + bb);
            *(float4*)(cp + t) = v;
        }
    }

    __syncthreads();
    if (tid == 0) mbar_inval(mbar);
    __syncthreads();
    if (w == 0) tmem_dealloc(tmem, 128);
#endif
}

// smem regions for attention (relative to 1024-aligned base)
#define SM_MISC 0
#define SM_Q    4096                 // 16 KB: Q fp16 [128 i][64 d]
#define SM_K    (SM_Q + 16384)       // 64 KB: K fp16 [512 j][64 d]   -> sO stage
#define SM_V    (SM_K + 65536)       // 64 KB: V fp16 [64 d][512 j] blocked-atom
#define SM_REQ  (SM_V + 65536 + 1024)

// ===========================================================================
// Kernel 3: tcgen05 fused attention, all-fp16 operands, P staged in TMEM.
// TMEM map: cols 0-511 dots (fp32) -> cols 0-255 P (fp16x2) ; D at 256-319.
// One CTA = (b, h, 128 q rows). grid (32, 8, 4), 512 threads.
// ===========================================================================
__global__ __launch_bounds__(512, 1)
void attn_tc_kernel(const float* __restrict__ gq,
                    const float* __restrict__ gkv,
                    float* __restrict__ gout)
{
#if defined(__CUDA_ARCH_FEAT_SM103_ALL)
    extern __shared__ char sm_raw[];
    char* base = (char*)(((uintptr_t)sm_raw + 1023) & ~(uintptr_t)1023);
    const uint32_t sb = s2u(base);

    const int tid = threadIdx.x, w = tid >> 5, lane = tid & 31;
    const int sub = w & 3, grp = w >> 2;     // subpartition / 128-col quarter
    const int row = sub * 32 + lane;         // q row owned in TMEM
    const int i0 = blockIdx.x * 128;
    const int h  = blockIdx.y;
    const int b  = blockIdx.z;

    const uint32_t misc  = sb + SM_MISC;
    const uint32_t mbar0 = misc + 8;
    const uint32_t mbar1 = misc + 16;
    const uint32_t mbar2 = misc + 24;
    float* sRow = (float*)(base + SM_MISC + 1024);   // [4][128]
    float* linv = (float*)(base + SM_MISC + 3072);   // [128]

    if (w == 0) tmem_alloc(misc, 512);
    if (tid == 0) { mbar_init(mbar0, 1); mbar_init(mbar1, 1); mbar_init(mbar2, 1); }
    __syncthreads();
    uint32_t tmem;
    asm volatile("ld.shared.b32 %0, [%1];" : "=r"(tmem) : "r"(misc));

    const float* qbase = gq  + ((size_t)b * INNER + h * DHEAD) * NQ + i0;
    const float* kbase = gkv + ((size_t)b * 2 * INNER + h * DHEAD) * NK;
    const float* vbase = kbase + (size_t)INNER * NK;

    // softmax base-2 trick: scale = 1/sqrt(64) * log2(e)
    const float QSCALE = 0.125f * 1.44269504088896341f;

    // ---- load Q fp16 (transpose [d][i]->[i][d], scaled) ----
    for (int g = tid; g < 1024; g += 512) {
        const int i = g & 127, d0 = (g >> 7) * 8;
        float f[8];
        #pragma unroll
        for (int k = 0; k < 8; k++)
            f[k] = qbase[(size_t)(d0 + k) * NQ + i] * QSCALE;
        uint4 pk;
        #pragma unroll
        for (int t = 0; t < 4; t++) {
            __half2 h2 = __floats2half2_rn(f[2 * t], f[2 * t + 1]);
            ((uint32_t*)&pk)[t] = *(uint32_t*)&h2;
        }
        *(uint4*)(base + SM_Q + qk_off(i, d0)) = pk;
    }
    // ---- load K fp16 (transpose [d][j]->[j][d]) ----
    for (int g = tid; g < 4096; g += 512) {
        const int j = g & 511, d0 = (g >> 9) * 8;
        float f[8];
        #pragma unroll
        for (int k = 0; k < 8; k++)
            f[k] = kbase[(size_t)(d0 + k) * NK + j];
        uint4 pk;
        #pragma unroll
        for (int t = 0; t < 4; t++) {
            __half2 h2 = __floats2half2_rn(f[2 * t], f[2 * t + 1]);
            ((uint32_t*)&pk)[t] = *(uint32_t*)&h2;
        }
        *(uint4*)(base + SM_K + qk_off(j, d0)) = pk;
    }
    FENCE_ASYNC();
    __syncthreads();

    // ---- MMA1: dots = Q K^T, fp16, two N=256 chunks (4 K-steps each) ----
    if (w == 0) {
        const uint64_t qd = MK_DESC(sb + SM_Q);
        const uint32_t id1 = IDESC_F16_N(256);
        if (elect1()) {
            #pragma unroll
            for (int c = 0; c < 2; c++) {
                const uint32_t dst = tmem + c * 256;
                const uint64_t kd = MK_DESC(sb + SM_K + c * 32768);
                #pragma unroll
                for (int s = 0; s < 4; s++)
                    mma_f16_ss(dst, qd + s * 2, kd + s * 2, id1, s > 0);
                tc_commit(c ? mbar1 : mbar0);
            }
        }
    }

    // ---- load V fp16 [d][j] blocked-atom (overlaps MMA1) ----
    for (int g = tid; g < 4096; g += 512) {
        const int d = g >> 6, j8 = (g & 63) * 8;
        const float* vs = vbase + (size_t)d * NK + j8;
        float4 v0 = *(const float4*)(vs);
        float4 v1 = *(const float4*)(vs + 4);
        uint4 pk;
        ((__half2*)&pk)[0] = __floats2half2_rn(v0.x, v0.y);
        ((__half2*)&pk)[1] = __floats2half2_rn(v0.z, v0.w);
        ((__half2*)&pk)[2] = __floats2half2_rn(v1.x, v1.y);
        ((__half2*)&pk)[3] = __floats2half2_rn(v1.z, v1.w);
        *(uint4*)(base + SM_V + v_off(d, j8)) = pk;
    }
    FENCE_ASYNC();

    // ---- LDTM dots + exp2 + row-sum -> 64 packed fp16x2 regs ----
    mbar_wait(grp < 2 ? mbar0 : mbar1, 0);
    TC_FENCE_AFTER();
    uint32_t pk[64];
    {
        float rsum = 0.f;
        #pragma unroll
        for (int c8 = 0; c8 < 4; c8++) {
            uint32_t r[32];
            TC_LD_X32(r, tmem + grp * 128 + c8 * 32);
            TC_WAIT_LD();
            #pragma unroll
            for (int t = 0; t < 16; t++) {
                float e0 = ex2f(__uint_as_float(r[2 * t]));
                float e1 = ex2f(__uint_as_float(r[2 * t + 1]));
                rsum += e0 + e1;
                __half2 h2 = __floats2half2_rn(e0, e1);
                pk[c8 * 16 + t] = *(uint32_t*)&h2;
            }
        }
        sRow[grp * 128 + row] = rsum;
    }
    __syncthreads();   // ALL dots consumed before any P overwrites them

    // ---- STTM P (fp16x2) into TMEM cols [64*grp, 64*grp+64) ----
    TC_ST_X64(tmem + grp * 64, pk);
    TC_WAIT_ST();
    if (tid < 128)
        linv[tid] = 1.f / (sRow[tid] + sRow[128 + tid] +
                           sRow[256 + tid] + sRow[384 + tid]);
    TC_FENCE_BEFORE();
    __syncthreads();

    // ---- MMA2 (TS): D = P(tmem) @ V^T, K=512 (32 steps), D at cols 256 ----
    if (w == 0) {
        TC_FENCE_AFTER();
        const uint64_t vd = MK_DESC(sb + SM_V);
        const uint32_t id2 = IDESC_F16_N(64);
        if (elect1()) {
            #pragma unroll
            for (int s = 0; s < 32; s++) {
                uint64_t bd = vd + (uint64_t)(s >> 2) * 512 + (s & 3) * 2;
                mma_f16_ts(tmem + 256, tmem + s * 8, bd, id2, s > 0);
            }
            tc_commit(mbar2);
        }
    }
    mbar_wait(mbar2, 0);
    TC_FENCE_AFTER();

    // ---- epilogue: scale by 1/l, stage sO[d][i] in SM_K, coalesced store ----
    float* sO = (float*)(base + SM_K);       // [64][132] floats
    if (grp < 2) {
        const int colb = grp * 32;
        uint32_t r[32];
        TC_LD_X32(r, tmem + 256 + colb);
        TC_WAIT_LD();
        TC_FENCE_BEFORE();
        const float li = linv[row];
        #pragma unroll
        for (int t = 0; t < 32; t++)
            sO[(colb + t) * 132 + row] = __uint_as_float(r[t]) * li;
    }
    __syncthreads();
    for (int e = tid; e < 2048; e += 512) {
        const int d = e >> 5, i4 = (e & 31) * 4;
        float4 v = *(const float4*)(sO + d * 132 + i4);
        *(float4*)(gout + ((size_t)b * INNER + h * DHEAD + d) * NQ + i0 + i4) = v;
    }

    __syncthreads();
    if (tid == 0) { mbar_inval(mbar0); mbar_inval(mbar1); mbar_inval(mbar2); }
    __syncthreads();
    if (w == 0) tmem_dealloc(tmem, 512);
#endif  // __CUDA_ARCH_FEAT_SM103_ALL
}

// ---------------------------------------------------------------------------
extern "C" void kernel_launch(void* const* d_in, const int* in_sizes, int n_in,
                              void* d_out, int out_size)
{
    const float* x      = (const float*)d_in[0];
    const float* wq_dw  = (const float*)d_in[1];
    const float* bn_q_g = (const float*)d_in[2];
    const float* bn_q_b = (const float*)d_in[3];
    const float* bn_q_m = (const float*)d_in[4];
    const float* bn_q_v = (const float*)d_in[5];
    const float* wq_pw  = (const float*)d_in[6];
    const float* wkv_dw = (const float*)d_in[7];
    const float* bn_k_g = (const float*)d_in[8];
    const float* bn_k_b = (const float*)d_in[9];
    const float* bn_k_m = (const float*)d_in[10];
    const float* bn_k_v = (const float*)d_in[11];
    const float* wkv_pw = (const float*)d_in[12];
    const float* w_out  = (const float*)d_in[13];
    const float* b_out  = (const float*)d_in[14];
    float* out = (float*)d_out;

    float *p_qdw, *p_kvdw, *p_q, *p_kv, *p_att;
    cudaGetSymbolAddress((void**)&p_qdw,  g_qdw);
    cudaGetSymbolAddress((void**)&p_kvdw, g_kvdw);
    cudaGetSymbolAddress((void**)&p_q,    g_q);
    cudaGetSymbolAddress((void**)&p_kv,   g_kv);
    cudaGetSymbolAddress((void**)&p_att,  g_att);

    cudaFuncSetAttribute(attn_tc_kernel,
                         cudaFuncAttributeMaxDynamicSharedMemorySize, SM_REQ);
    cudaFuncSetAttribute(gemm_tc_kernel,
                         cudaFuncAttributeMaxDynamicSharedMemorySize, GM_REQ);

    // 1. depthwise convs + BN (fused)
    dw_bn_kernel<<<dim3(CDIM, BATCH), 256>>>(
        x, wq_dw, bn_q_g, bn_q_b, bn_q_m, bn_q_v,
        wkv_dw, bn_k_g, bn_k_b, bn_k_m, bn_k_v);

    // 2. pointwise q: (512 x 128) @ (128 x 4096) per batch  [tcgen05 fp16]
    gemm_tc_kernel<<<dim3(NQ / 128, INNER / 128, BATCH), 512, GM_REQ>>>(
        wq_pw, p_qdw, p_q, INNER, NQ, CDIM, nullptr);

    // 3. pointwise kv: (1024 x 128) @ (128 x 512) per batch  [tcgen05 fp16]
    gemm_tc_kernel<<<dim3(NK / 128, (2 * INNER) / 128, BATCH), 512, GM_REQ>>>(
        wkv_pw, p_kvdw, p_kv, 2 * INNER, NK, CDIM, nullptr);

    // 4. fused attention (tcgen05, all-fp16, P in TMEM)
    attn_tc_kernel<<<dim3(NQ / 128, NHEADS, BATCH), 512, SM_REQ>>>(
        p_q, p_kv, p_att);

    // 5. out projection + bias: (128 x 512) @ (512 x 4096) per batch  [tcgen05 fp16]
    gemm_tc_kernel<<<dim3(NQ / 128, CDIM / 128, BATCH), 512, GM_REQ>>>(
        w_out, p_att, out, CDIM, NQ, INNER, b_out);
}

// round 15
// speedup vs baseline: 5.1519x; 1.0022x over previous
#include <cuda_runtime.h>
#include <cuda_bf16.h>
#include <cuda_fp16.h>
#include <math.h>
#include <stdint.h>

#define BATCH 4
#define CDIM 128
#define INNER 512
#define NQ 4096
#define NK 512
#define NHEADS 8
#define DHEAD 64

// ---------------- scratch (static device globals; allocation-free) ----------
__device__ float g_qdw[BATCH * CDIM * NQ];     // 8 MB   depthwise-q + BN
__device__ float g_kvdw[BATCH * CDIM * NK];    // 1 MB   depthwise-kv + BN
__device__ float g_q[BATCH * INNER * NQ];      // 32 MB  q after pointwise
__device__ float g_kv[BATCH * 2 * INNER * NK]; // 8 MB   kv after pointwise
__device__ float g_att[BATCH * INNER * NQ];    // 32 MB  attention output

// ---------------------------------------------------------------------------
// Kernel 1: both depthwise 3x3x3 convs (stride1 and stride2) + batchnorm.
// ---------------------------------------------------------------------------
__global__ __launch_bounds__(256) void dw_bn_kernel(
    const float* __restrict__ x,
    const float* __restrict__ wq,
    const float* __restrict__ qg, const float* __restrict__ qb,
    const float* __restrict__ qm, const float* __restrict__ qv,
    const float* __restrict__ wkv,
    const float* __restrict__ kg, const float* __restrict__ kb,
    const float* __restrict__ km, const float* __restrict__ kvvar)
{
    __shared__ float s[18 * 18 * 18];
    __shared__ float swq[27], swkv[27];
    const int c = blockIdx.x, b = blockIdx.y;
    const int tid = threadIdx.x;

    const float* xp = x + ((size_t)(b * CDIM + c)) * NQ;
    for (int idx = tid; idx < 5832; idx += 256) {
        int z = idx / 324; int r = idx - z * 324;
        int y = r / 18;    int xx = r - y * 18;
        z -= 1; y -= 1; xx -= 1;
        float v = 0.f;
        if ((unsigned)z < 16u && (unsigned)y < 16u && (unsigned)xx < 16u)
            v = xp[(z * 16 + y) * 16 + xx];
        s[idx] = v;
    }
    if (tid < 27) { swq[tid] = wq[c * 27 + tid]; swkv[tid] = wkv[c * 27 + tid]; }

    const float qscale = qg[c] * rsqrtf(qv[c] + 1e-5f);
    const float qshift = qb[c] - qm[c] * qscale;
    const float kscale = kg[c] * rsqrtf(kvvar[c] + 1e-5f);
    const float kshift = kb[c] - km[c] * kscale;
    __syncthreads();

    float* qo = g_qdw + ((size_t)(b * CDIM + c)) * NQ;
    for (int o = tid; o < 4096; o += 256) {
        const int z = o >> 8, y = (o >> 4) & 15, xx = o & 15;
        float sum = 0.f;
        #pragma unroll
        for (int dz = 0; dz < 3; dz++)
            #pragma unroll
            for (int dy = 0; dy < 3; dy++)
                #pragma unroll
                for (int dx = 0; dx < 3; dx++)
                    sum += swq[dz * 9 + dy * 3 + dx] *
                           s[(z + dz) * 324 + (y + dy) * 18 + (xx + dx)];
        qo[o] = sum * qscale + qshift;
    }

    float* ko = g_kvdw + ((size_t)(b * CDIM + c)) * NK;
    for (int o = tid; o < 512; o += 256) {
        const int z = o >> 6, y = (o >> 3) & 7, xx = o & 7;
        float sum = 0.f;
        #pragma unroll
        for (int dz = 0; dz < 3; dz++)
            #pragma unroll
            for (int dy = 0; dy < 3; dy++)
                #pragma unroll
                for (int dx = 0; dx < 3; dx++)
                    sum += swkv[dz * 9 + dy * 3 + dx] *
                           s[(2 * z + dz) * 324 + (2 * y + dy) * 18 + (2 * xx + dx)];
        ko[o] = sum * kscale + kshift;
    }
}

// ===========================================================================
// tcgen05 helpers
// ===========================================================================
__device__ __forceinline__ uint32_t s2u(const void* p) {
    uint32_t a;
    asm("{ .reg .u64 t; cvta.to.shared.u64 t, %1; cvt.u32.u64 %0, t; }"
        : "=r"(a) : "l"(p));
    return a;
}
__device__ __forceinline__ uint32_t elect1() {
    uint32_t pred;
    asm volatile("{\n\t.reg .pred p;\n\telect.sync _|p, 0xFFFFFFFF;\n\t"
                 "selp.b32 %0, 1, 0, p;\n\t}" : "=r"(pred));
    return pred;
}
__device__ __forceinline__ void mbar_init(uint32_t mbar, uint32_t cnt) {
    asm volatile("mbarrier.init.shared.b64 [%0], %1;" :: "r"(mbar), "r"(cnt) : "memory");
}
__device__ __forceinline__ void mbar_inval(uint32_t mbar) {
    asm volatile("mbarrier.inval.shared.b64 [%0];" :: "r"(mbar) : "memory");
}
__device__ __forceinline__ void mbar_wait(uint32_t mbar, uint32_t parity) {
    asm volatile(
        "{\n\t.reg .pred P1;\n\t"
        "WL%=:\n\t"
        "mbarrier.try_wait.parity.acquire.cta.shared::cta.b64 P1, [%0], %1, 0x989680;\n\t"
        "@P1 bra.uni WD%=;\n\t"
        "bra.uni WL%=;\n\t"
        "WD%=:\n\t}"
        :: "r"(mbar), "r"(parity) : "memory");
}
__device__ __forceinline__ void tmem_alloc(uint32_t smem_dst, uint32_t ncols) {
    asm volatile("tcgen05.alloc.cta_group::1.sync.aligned.shared::cta.b32 [%0], %1;"
                 :: "r"(smem_dst), "r"(ncols) : "memory");
}
__device__ __forceinline__ void tmem_dealloc(uint32_t tmem, uint32_t ncols) {
    asm volatile("tcgen05.relinquish_alloc_permit.cta_group::1.sync.aligned;");
    asm volatile("tcgen05.dealloc.cta_group::1.sync.aligned.b32 %0, %1;"
                 :: "r"(tmem), "r"(ncols));
}
__device__ __forceinline__ void mma_f16_ss(uint32_t d, uint64_t a, uint64_t b,
                                           uint32_t idesc, uint32_t en) {
    asm volatile(
        "{\n\t.reg .pred p;\n\tsetp.ne.u32 p, %5, 0;\n\t"
        "tcgen05.mma.cta_group::1.kind::f16 [%0], %1, %2, %3, {%4, %4, %4, %4}, p;\n\t}"
        :: "r"(d), "l"(a), "l"(b), "r"(idesc), "r"(0u), "r"(en) : "memory");
}
__device__ __forceinline__ void mma_f16_ts(uint32_t d, uint32_t a_tmem, uint64_t b,
                                           uint32_t idesc, uint32_t en) {
    asm volatile(
        "{\n\t.reg .pred p;\n\tsetp.ne.u32 p, %5, 0;\n\t"
        "tcgen05.mma.cta_group::1.kind::f16 [%0], [%1], %2, %3, {%4, %4, %4, %4}, p;\n\t}"
        :: "r"(d), "r"(a_tmem), "l"(b), "r"(idesc), "r"(0u), "r"(en) : "memory");
}
__device__ __forceinline__ void tc_commit(uint32_t mbar) {
    asm volatile(
        "tcgen05.commit.cta_group::1.mbarrier::arrive::one.shared::cluster.b64 [%0];"
        :: "r"(mbar) : "memory");
}
__device__ __forceinline__ float ex2f(float x) {
    float r;
    asm("ex2.approx.f32 %0, %1;" : "=f"(r) : "f"(x));
    return r;
}
#define TC_FENCE_AFTER()  asm volatile("tcgen05.fence::after_thread_sync;" ::: "memory")
#define TC_FENCE_BEFORE() asm volatile("tcgen05.fence::before_thread_sync;" ::: "memory")
#define TC_WAIT_LD()      asm volatile("tcgen05.wait::ld.sync.aligned;" ::: "memory")
#define TC_WAIT_ST()      asm volatile("tcgen05.wait::st.sync.aligned;" ::: "memory")
#define FENCE_ASYNC()     asm volatile("fence.proxy.async.shared::cta;" ::: "memory")

#define TC_LD_X32(r, addr) \
    asm volatile( \
        "tcgen05.ld.sync.aligned.32x32b.x32.b32 " \
        "{%0, %1, %2, %3, %4, %5, %6, %7, " \
        " %8, %9, %10, %11, %12, %13, %14, %15, " \
        " %16, %17, %18, %19, %20, %21, %22, %23, " \
        " %24, %25, %26, %27, %28, %29, %30, %31}, [%32];" \
        : "=r"((r)[0]),  "=r"((r)[1]),  "=r"((r)[2]),  "=r"((r)[3]), \
          "=r"((r)[4]),  "=r"((r)[5]),  "=r"((r)[6]),  "=r"((r)[7]), \
          "=r"((r)[8]),  "=r"((r)[9]),  "=r"((r)[10]), "=r"((r)[11]), \
          "=r"((r)[12]), "=r"((r)[13]), "=r"((r)[14]), "=r"((r)[15]), \
          "=r"((r)[16]), "=r"((r)[17]), "=r"((r)[18]), "=r"((r)[19]), \
          "=r"((r)[20]), "=r"((r)[21]), "=r"((r)[22]), "=r"((r)[23]), \
          "=r"((r)[24]), "=r"((r)[25]), "=r"((r)[26]), "=r"((r)[27]), \
          "=r"((r)[28]), "=r"((r)[29]), "=r"((r)[30]), "=r"((r)[31]) \
        : "r"(addr))

#define TC_ST_X16(addr, r) \
    asm volatile( \
        "tcgen05.st.sync.aligned.32x32b.x16.b32 [%0], " \
        "{%1, %2, %3, %4, %5, %6, %7, %8, " \
        " %9, %10, %11, %12, %13, %14, %15, %16};" \
        :: "r"(addr), \
           "r"((r)[0]),  "r"((r)[1]),  "r"((r)[2]),  "r"((r)[3]), \
           "r"((r)[4]),  "r"((r)[5]),  "r"((r)[6]),  "r"((r)[7]), \
           "r"((r)[8]),  "r"((r)[9]),  "r"((r)[10]), "r"((r)[11]), \
           "r"((r)[12]), "r"((r)[13]), "r"((r)[14]), "r"((r)[15]) \
        : "memory")

// SW128 smem descriptor base (layout=2, version=1, SBO=64, LBO=1)
#define DESC_BASE ((2ULL << 61) | (1ULL << 46) | (64ULL << 32) | (1ULL << 16))
#define MK_DESC(a) (DESC_BASE | ((uint64_t)((a) >> 4) & 0x3FFFULL))

__device__ __forceinline__ uint32_t sw128(uint32_t o) { return o ^ ((o >> 3) & 0x70); }
// rows x 64 elems (128B rows), SW128
__device__ __forceinline__ uint32_t qk_off(int r, int c) {
    return sw128((uint32_t)r * 128u + (uint32_t)c * 2u);
}
// 128 x (64*ac) 2B elems, blocked-atom, 16 atom-rows per atom-col
__device__ __forceinline__ uint32_t p_off(int i, int j) {
    uint32_t o = ((uint32_t)(i >> 3) + (uint32_t)(j >> 6) * 16u) * 1024u +
                 (uint32_t)(i & 7) * 128u + (uint32_t)(j & 63) * 2u;
    return sw128(o);
}
// 64 x 512 fp16 blocked-atom (8 atom-rows per atom-col)
__device__ __forceinline__ uint32_t v_off(int d, int j) {
    uint32_t o = ((uint32_t)(d >> 3) + (uint32_t)(j >> 6) * 8u) * 1024u +
                 (uint32_t)(d & 7) * 128u + (uint32_t)(j & 63) * 2u;
    return sw128(o);
}

// idesc: dtype F32 (1<<4); atype/btype F16=0; M=128 (8<<24); N bits 17..22
#define IDESC_F16_N(n)  ((1u << 4) | (((n) / 8) << 17) | (8u << 24))

// ===========================================================================
// Kernel 2: tcgen05 GEMM, plain fp16 operands (single term). 66 KB smem ->
// 3 CTAs/SM. grid (N/128, M/128, BATCH), 512 threads.
// ===========================================================================
#define GM_MISC 0
#define GM_A    1024
#define GM_B    (GM_A + 32768)
#define GM_REQ  (GM_B + 32768 + 1024)

__global__ __launch_bounds__(512, 1)
void gemm_tc_kernel(const float* __restrict__ A, const float* __restrict__ Bm,
                    float* __restrict__ Cm, int M, int N, int K,
                    const float* __restrict__ bias)
{
#if defined(__CUDA_ARCH_FEAT_SM103_ALL)
    extern __shared__ char sm_raw[];
    char* base = (char*)(((uintptr_t)sm_raw + 1023) & ~(uintptr_t)1023);
    const uint32_t sb = s2u(base);

    const int tid = threadIdx.x, w = tid >> 5, lane = tid & 31;
    const int sub = w & 3, grp = w >> 2;
    const int row = sub * 32 + lane;
    const int n0 = blockIdx.x * 128, m0 = blockIdx.y * 128, bz = blockIdx.z;

    const uint32_t misc = sb + GM_MISC;
    const uint32_t mbar = misc + 8;
    if (w == 0) tmem_alloc(misc, 128);
    if (tid == 0) mbar_init(mbar, 1);
    __syncthreads();
    uint32_t tmem;
    asm volatile("ld.shared.b32 %0, [%1];" : "=r"(tmem) : "r"(misc));

    const float* Bp = Bm + (size_t)bz * K * N;
    float* Cp = Cm + (size_t)bz * M * N;
    const int nchunks = K >> 7;

    for (int kc = 0; kc < nchunks; kc++) {
        const int k0 = kc << 7;
        // ---- load A tile [128 m][128 k] fp16, blocked-atom ----
        for (int g = tid; g < 2048; g += 512) {
            const int m = g >> 4, kg = (g & 15) * 8;
            const float* as = A + (size_t)(m0 + m) * K + k0 + kg;
            float4 a0 = *(const float4*)(as);
            float4 a1 = *(const float4*)(as + 4);
            uint4 pk;
            ((__half2*)&pk)[0] = __floats2half2_rn(a0.x, a0.y);
            ((__half2*)&pk)[1] = __floats2half2_rn(a0.z, a0.w);
            ((__half2*)&pk)[2] = __floats2half2_rn(a1.x, a1.y);
            ((__half2*)&pk)[3] = __floats2half2_rn(a1.z, a1.w);
            *(uint4*)(base + GM_A + p_off(m, kg)) = pk;
        }
        // ---- load B tile transposed: Bs[n][k] = B[k0+k][n0+n], fp16 ----
        for (int g = tid; g < 2048; g += 512) {
            const int n = g & 127, kg = (g >> 7) * 8;
            const float* bs = Bp + (size_t)(k0 + kg) * N + n0 + n;
            float f[8];
            #pragma unroll
            for (int j = 0; j < 8; j++) f[j] = bs[(size_t)j * N];
            uint4 pk;
            #pragma unroll
            for (int t = 0; t < 4; t++) {
                __half2 h2 = __floats2half2_rn(f[2 * t], f[2 * t + 1]);
                ((uint32_t*)&pk)[t] = *(uint32_t*)&h2;
            }
            *(uint4*)(base + GM_B + p_off(n, kg)) = pk;
        }
        FENCE_ASYNC();
        __syncthreads();

        // ---- single-term fp16 MMA over this K-chunk (8 k-steps) ----
        if (w == 0) {
            TC_FENCE_AFTER();
            const uint64_t ad = MK_DESC(sb + GM_A);
            const uint64_t bd = MK_DESC(sb + GM_B);
            const uint32_t id = IDESC_F16_N(128);
            if (elect1()) {
                #pragma unroll
                for (int s = 0; s < 8; s++) {
                    uint64_t doff = (uint64_t)(s >> 2) * 1024 + (s & 3) * 2;
                    mma_f16_ss(tmem, ad + doff, bd + doff, id, !(kc == 0 && s == 0));
                }
                tc_commit(mbar);
            }
        }
        mbar_wait(mbar, kc & 1);
    }
    TC_FENCE_AFTER();

    // ---- epilogue: LDTM 32 cols per warp-group, (+bias), direct store ----
    {
        uint32_t r[32];
        TC_LD_X32(r, tmem + grp * 32);
        TC_WAIT_LD();
        TC_FENCE_BEFORE();
        const float bb = bias ? bias[m0 + row] : 0.f;
        float* cp = Cp + (size_t)(m0 + row) * N + n0 + grp * 32;
        float4 v;
        #pragma unroll
        for (int t = 0; t < 32; t += 4) {
            v = make_float4(__uint_as_float(r[t]) + bb,
                            __uint_as_float(r[t + 1]) + bb,
                            __uint_as_float(r[t + 2]) + bb,
                            __uint_as_float(r[t + 3]) + bb);
            *(float4*)(cp + t) = v;
        }
    }

    __syncthreads();
    if (tid == 0) mbar_inval(mbar);
    __syncthreads();
    if (w == 0) tmem_dealloc(tmem, 128);
#endif
}

// smem regions for attention (relative to 1024-aligned base)
#define SM_MISC 0
#define SM_Q    4096                 // 16 KB: Q fp16 [128 i][64 d]
#define SM_K    (SM_Q + 16384)       // 64 KB: K fp16 [512 j][64 d]   -> sO stage
#define SM_V    (SM_K + 65536)       // 64 KB: V fp16 [64 d][512 j] blocked-atom
#define SM_REQ  (SM_V + 65536 + 1024)

// ===========================================================================
// Kernel 3: tcgen05 fused attention, fp16 operands, fp32 dots, P in TMEM.
// TMEM map (word-cols): dots fp32 at 0-511; warp-group g owns j-quarter g
// = dots cols [128g, 128g+128). P (fp16x2) written IN-PLACE into
// [128g, 128g+64) — inside g's own already-read dots, no cross-warp hazard.
// D (fp32) at cols 448-511: the ONLY 64-col window free of P (P quarters
// end at 448) whose dots (quarter 3 upper chunks) are dead pre-MMA2.
// (R14 bug: D at 256 collided with P quarter 2 -> NaN.)
// MMA2 A addressing: step s reads P word-cols (s>>3)*128 + (s&7)*8.
// One CTA = (b, h, 128 q rows). grid (32, 8, 4), 512 threads.
// ===========================================================================
__global__ __launch_bounds__(512, 1)
void attn_tc_kernel(const float* __restrict__ gq,
                    const float* __restrict__ gkv,
                    float* __restrict__ gout)
{
#if defined(__CUDA_ARCH_FEAT_SM103_ALL)
    extern __shared__ char sm_raw[];
    char* base = (char*)(((uintptr_t)sm_raw + 1023) & ~(uintptr_t)1023);
    const uint32_t sb = s2u(base);

    const int tid = threadIdx.x, w = tid >> 5, lane = tid & 31;
    const int sub = w & 3, grp = w >> 2;     // subpartition / 128-j quarter
    const int row = sub * 32 + lane;         // q row owned in TMEM
    const int i0 = blockIdx.x * 128;
    const int h  = blockIdx.y;
    const int b  = blockIdx.z;

    const uint32_t misc  = sb + SM_MISC;
    const uint32_t mbar0 = misc + 8;
    const uint32_t mbar1 = misc + 16;
    const uint32_t mbar2 = misc + 24;
    float* sRow = (float*)(base + SM_MISC + 1024);   // [4][128]
    float* linv = (float*)(base + SM_MISC + 3072);   // [128]

    if (w == 0) tmem_alloc(misc, 512);
    if (tid == 0) { mbar_init(mbar0, 1); mbar_init(mbar1, 1); mbar_init(mbar2, 1); }
    __syncthreads();
    uint32_t tmem;
    asm volatile("ld.shared.b32 %0, [%1];" : "=r"(tmem) : "r"(misc));

    const float* qbase = gq  + ((size_t)b * INNER + h * DHEAD) * NQ + i0;
    const float* kbase = gkv + ((size_t)b * 2 * INNER + h * DHEAD) * NK;
    const float* vbase = kbase + (size_t)INNER * NK;

    // softmax base-2 trick: scale = 1/sqrt(64) * log2(e)
    const float QSCALE = 0.125f * 1.44269504088896341f;

    // ---- load Q fp16 (transpose [d][i]->[i][d], scaled) ----
    for (int g = tid; g < 1024; g += 512) {
        const int i = g & 127, d0 = (g >> 7) * 8;
        float f[8];
        #pragma unroll
        for (int k = 0; k < 8; k++)
            f[k] = qbase[(size_t)(d0 + k) * NQ + i] * QSCALE;
        uint4 pk;
        #pragma unroll
        for (int t = 0; t < 4; t++) {
            __half2 h2 = __floats2half2_rn(f[2 * t], f[2 * t + 1]);
            ((uint32_t*)&pk)[t] = *(uint32_t*)&h2;
        }
        *(uint4*)(base + SM_Q + qk_off(i, d0)) = pk;
    }
    // ---- load K fp16 (transpose [d][j]->[j][d]) ----
    for (int g = tid; g < 4096; g += 512) {
        const int j = g & 511, d0 = (g >> 9) * 8;
        float f[8];
        #pragma unroll
        for (int k = 0; k < 8; k++)
            f[k] = kbase[(size_t)(d0 + k) * NK + j];
        uint4 pk;
        #pragma unroll
        for (int t = 0; t < 4; t++) {
            __half2 h2 = __floats2half2_rn(f[2 * t], f[2 * t + 1]);
            ((uint32_t*)&pk)[t] = *(uint32_t*)&h2;
        }
        *(uint4*)(base + SM_K + qk_off(j, d0)) = pk;
    }
    FENCE_ASYNC();
    __syncthreads();

    // ---- MMA1: dots = Q K^T, fp32 accum, two N=256 chunks (4 K-steps) ----
    if (w == 0) {
        const uint64_t qd = MK_DESC(sb + SM_Q);
        const uint32_t id1 = IDESC_F16_N(256);
        if (elect1()) {
            #pragma unroll
            for (int c = 0; c < 2; c++) {
                const uint32_t dst = tmem + c * 256;
                const uint64_t kd = MK_DESC(sb + SM_K + c * 32768);
                #pragma unroll
                for (int s = 0; s < 4; s++)
                    mma_f16_ss(dst, qd + s * 2, kd + s * 2, id1, s > 0);
                tc_commit(c ? mbar1 : mbar0);
            }
        }
    }

    // ---- load V fp16 [d][j] blocked-atom (overlaps MMA1) ----
    for (int g = tid; g < 4096; g += 512) {
        const int d = g >> 6, j8 = (g & 63) * 8;
        const float* vs = vbase + (size_t)d * NK + j8;
        float4 v0 = *(const float4*)(vs);
        float4 v1 = *(const float4*)(vs + 4);
        uint4 pk;
        ((__half2*)&pk)[0] = __floats2half2_rn(v0.x, v0.y);
        ((__half2*)&pk)[1] = __floats2half2_rn(v0.z, v0.w);
        ((__half2*)&pk)[2] = __floats2half2_rn(v1.x, v1.y);
        ((__half2*)&pk)[3] = __floats2half2_rn(v1.z, v1.w);
        *(uint4*)(base + SM_V + v_off(d, j8)) = pk;
    }
    FENCE_ASYNC();

    // ---- per-chunk: LDTM 32 fp32 dots + exp + row-sum + STTM 16 P words.
    //      P chunk c8 -> word-cols [128*grp + 16*c8): inside own read region.
    mbar_wait(grp < 2 ? mbar0 : mbar1, 0);
    TC_FENCE_AFTER();
    {
        float rsum = 0.f;
        for (int c8 = 0; c8 < 4; c8++) {
            uint32_t r[32], pk[16];
            TC_LD_X32(r, tmem + grp * 128 + c8 * 32);
            TC_WAIT_LD();
            #pragma unroll
            for (int t = 0; t < 16; t++) {
                float e0 = ex2f(__uint_as_float(r[2 * t]));
                float e1 = ex2f(__uint_as_float(r[2 * t + 1]));
                rsum += e0 + e1;
                __half2 h2 = __floats2half2_rn(e0, e1);
                pk[t] = *(uint32_t*)&h2;
            }
            TC_ST_X16(tmem + grp * 128 + c8 * 16, pk);
            TC_WAIT_ST();
        }
        sRow[grp * 128 + row] = rsum;
        TC_FENCE_BEFORE();
    }
    __syncthreads();
    if (tid < 128)
        linv[tid] = 1.f / (sRow[tid] + sRow[128 + tid] +
                           sRow[256 + tid] + sRow[384 + tid]);
    __syncthreads();

    // ---- MMA2 (TS): D = P(tmem) @ V^T, K=512 (32 steps), D at cols 448 ----
    if (w == 0) {
        TC_FENCE_AFTER();
        const uint64_t vd = MK_DESC(sb + SM_V);
        const uint32_t id2 = IDESC_F16_N(64);
        if (elect1()) {
            #pragma unroll
            for (int s = 0; s < 32; s++) {
                uint32_t a_tmem = tmem + (s >> 3) * 128 + (s & 7) * 8;
                uint64_t bd = vd + (uint64_t)(s >> 2) * 512 + (s & 3) * 2;
                mma_f16_ts(tmem + 448, a_tmem, bd, id2, s > 0);
            }
            tc_commit(mbar2);
        }
    }
    mbar_wait(mbar2, 0);
    TC_FENCE_AFTER();

    // ---- epilogue: scale by 1/l, stage sO[d][i] in SM_K, coalesced store ----
    float* sO = (float*)(base + SM_K);       // [64][132] floats
    if (grp < 2) {
        const int colb = grp * 32;
        uint32_t r[32];
        TC_LD_X32(r, tmem + 448 + colb);
        TC_WAIT_LD();
        TC_FENCE_BEFORE();
        const float li = linv[row];
        #pragma unroll
        for (int t = 0; t < 32; t++)
            sO[(colb + t) * 132 + row] = __uint_as_float(r[t]) * li;
    }
    __syncthreads();
    for (int e = tid; e < 2048; e += 512) {
        const int d = e >> 5, i4 = (e & 31) * 4;
        float4 v = *(const float4*)(sO + d * 132 + i4);
        *(float4*)(gout + ((size_t)b * INNER + h * DHEAD + d) * NQ + i0 + i4) = v;
    }

    __syncthreads();
    if (tid == 0) { mbar_inval(mbar0); mbar_inval(mbar1); mbar_inval(mbar2); }
    __syncthreads();
    if (w == 0) tmem_dealloc(tmem, 512);
#endif  // __CUDA_ARCH_FEAT_SM103_ALL
}

// ---------------------------------------------------------------------------
extern "C" void kernel_launch(void* const* d_in, const int* in_sizes, int n_in,
                              void* d_out, int out_size)
{
    const float* x      = (const float*)d_in[0];
    const float* wq_dw  = (const float*)d_in[1];
    const float* bn_q_g = (const float*)d_in[2];
    const float* bn_q_b = (const float*)d_in[3];
    const float* bn_q_m = (const float*)d_in[4];
    const float* bn_q_v = (const float*)d_in[5];
    const float* wq_pw  = (const float*)d_in[6];
    const float* wkv_dw = (const float*)d_in[7];
    const float* bn_k_g = (const float*)d_in[8];
    const float* bn_k_b = (const float*)d_in[9];
    const float* bn_k_m = (const float*)d_in[10];
    const float* bn_k_v = (const float*)d_in[11];
    const float* wkv_pw = (const float*)d_in[12];
    const float* w_out  = (const float*)d_in[13];
    const float* b_out  = (const float*)d_in[14];
    float* out = (float*)d_out;

    float *p_qdw, *p_kvdw, *p_q, *p_kv, *p_att;
    cudaGetSymbolAddress((void**)&p_qdw,  g_qdw);
    cudaGetSymbolAddress((void**)&p_kvdw, g_kvdw);
    cudaGetSymbolAddress((void**)&p_q,    g_q);
    cudaGetSymbolAddress((void**)&p_kv,   g_kv);
    cudaGetSymbolAddress((void**)&p_att,  g_att);

    cudaFuncSetAttribute(attn_tc_kernel,
                         cudaFuncAttributeMaxDynamicSharedMemorySize, SM_REQ);
    cudaFuncSetAttribute(gemm_tc_kernel,
                         cudaFuncAttributeMaxDynamicSharedMemorySize, GM_REQ);

    // 1. depthwise convs + BN (fused)
    dw_bn_kernel<<<dim3(CDIM, BATCH), 256>>>(
        x, wq_dw, bn_q_g, bn_q_b, bn_q_m, bn_q_v,
        wkv_dw, bn_k_g, bn_k_b, bn_k_m, bn_k_v);

    // 2. pointwise q: (512 x 128) @ (128 x 4096) per batch  [tcgen05 fp16]
    gemm_tc_kernel<<<dim3(NQ / 128, INNER / 128, BATCH), 512, GM_REQ>>>(
        wq_pw, p_qdw, p_q, INNER, NQ, CDIM, nullptr);

    // 3. pointwise kv: (1024 x 128) @ (128 x 512) per batch  [tcgen05 fp16]
    gemm_tc_kernel<<<dim3(NK / 128, (2 * INNER) / 128, BATCH), 512, GM_REQ>>>(
        wkv_pw, p_kvdw, p_kv, 2 * INNER, NK, CDIM, nullptr);

    // 4. fused attention (tcgen05, fp32 dots, P in TMEM in place, D at 448)
    attn_tc_kernel<<<dim3(NQ / 128, NHEADS, BATCH), 512, SM_REQ>>>(
        p_q, p_kv, p_att);

    // 5. out projection + bias: (128 x 512) @ (512 x 4096) per batch  [tcgen05 fp16]
    gemm_tc_kernel<<<dim3(NQ / 128, CDIM / 128, BATCH), 512, GM_REQ>>>(
        w_out, p_att, out, CDIM, NQ, INNER, b_out);
}